// round 4
// baseline (speedup 1.0000x reference)
#include <cuda_runtime.h>
#include <cuda_fp16.h>
#include <cstdint>

// ---------------- problem constants ----------------
#define B_TOK 8192
#define DIN   1024
#define HID   2048
#define DOUT  1024
#define NE    8
#define GHID  1024
#define CAP   8192

#define FLAG_RELU  1
#define FLAG_ADD   2
#define FLAG_SPLIT 4
#define FLAG_DEST  8
#define FLAG_OCAP  16

// ---------------- scratch (static device globals) ----------------
__device__ unsigned short g_xh  [(size_t)B_TOK*2*DIN];      // x split fp16 [hi|lo]
__device__ unsigned short g_w1h [(size_t)NE*HID*DIN];       // w1^T fp16 (single)
__device__ unsigned short g_wph [(size_t)NE*HID*DIN];
__device__ unsigned short g_w2h [(size_t)NE*HID*HID];
__device__ unsigned short g_w3h [(size_t)NE*DOUT*HID];
__device__ unsigned short g_gwh [(size_t)GHID*2*DIN];       // gw1^T split [hi|lo]
__device__ unsigned short g_hs  [(size_t)NE*CAP*2*HID];     // h split (L1 out)
__device__ unsigned short g_os  [(size_t)NE*CAP*2*HID];     // o split (L3 out)
__device__ float g_p     [(size_t)NE*CAP*HID];              // projection (L2 out)
__device__ float g_hidden[(size_t)B_TOK*GHID];
__device__ float g_logits[(size_t)B_TOK*NE];
__device__ int   g_counts[NE];
__device__ int   g_tokens[(size_t)NE*CAP];
__device__ float g_wts   [(size_t)NE*CAP];
__device__ int   g_dests [(size_t)NE*CAP];
__device__ float g_eout  [(size_t)B_TOK*2*DOUT];

// ---------------- PTX helpers (baseline ISA only) ----------------
__device__ __forceinline__ uint32_t smem_u32(const void* p) {
    uint32_t a;
    asm("{ .reg .u64 t; cvta.to.shared.u64 t, %1; cvt.u32.u64 %0, t; }" : "=r"(a) : "l"(p));
    return a;
}
#define CPA16(dst, src) \
    asm volatile("cp.async.cg.shared.global [%0], [%1], 16;" :: "r"(dst), "l"(src) : "memory")
#define CP_COMMIT() asm volatile("cp.async.commit_group;" ::: "memory")
#define CP_WAIT1()  asm volatile("cp.async.wait_group 1;" ::: "memory")
#define LDSM4(r, addr) \
    asm volatile("ldmatrix.sync.aligned.m8n8.x4.shared.b16 {%0,%1,%2,%3}, [%4];" \
        : "=r"((r)[0]), "=r"((r)[1]), "=r"((r)[2]), "=r"((r)[3]) : "r"(addr))
#define MMA16816(d, a, b0, b1) \
    asm volatile("mma.sync.aligned.m16n8k16.row.col.f32.f16.f16.f32 " \
        "{%0,%1,%2,%3},{%4,%5,%6,%7},{%8,%9},{%0,%1,%2,%3};" \
        : "+f"((d)[0]), "+f"((d)[1]), "+f"((d)[2]), "+f"((d)[3]) \
        : "r"((a)[0]), "r"((a)[1]), "r"((a)[2]), "r"((a)[3]), "r"(b0), "r"(b1))

// ---------------- HMMA GEMM: tile 128x128x32, 8 warps, 3-stage cp.async ----------------
// K-space is a sequence of nTerms blocks; aMap/bMap (2 bits per term) select which
// stored K-block of A / B each term reads. 2-term: A=[hi|lo] map (0,1); B single, map (0,0).
#define BM 128
#define BN 128
#define BK 32
#define ROWE 40                 // padded row stride (elements): conflict-free ldmatrix
#define ATILE_B (BM * ROWE * 2) // 10240
#define STAGE_B (2 * ATILE_B)   // 20480 (A then B)
#define STAGES 3
#define DYN_SMEM (STAGES * STAGE_B)

__global__ __launch_bounds__(256) void mma_gemm(
    const unsigned short* __restrict__ A, int aRL, int aCap,
    const int* __restrict__ gather,
    const unsigned short* __restrict__ W, size_t wStrideE, int bRL,
    const float* __restrict__ bias, int bStrideE,
    const float* __restrict__ addt,
    float* __restrict__ outF, unsigned short* __restrict__ outS,
    const float* __restrict__ scales, const int* __restrict__ dests,
    const int* __restrict__ counts, int Mfixed,
    int K, int nTerms, int aMap, int bMap,
    int N, int flags)
{
    const int e  = blockIdx.z;
    const int M  = counts ? counts[e] : Mfixed;
    const int m0 = blockIdx.y * BM;
    if (m0 >= M) return;
    const int n0 = blockIdx.x * BN;

    extern __shared__ char smem[];
    const uint32_t sbase = smem_u32(smem);

    const int tid  = threadIdx.x;
    const int wid  = tid >> 5;
    const int lane = tid & 31;

    // ---- load mapping: thread -> one row (A and B), two 16B chunks ----
    const int lrow   = tid >> 1;           // 0..127
    const int lchunk = (tid & 1) * 2;      // {0,1} or {2,3}
    const unsigned short* Asrc;
    {
        int r = m0 + lrow;
        int row = gather ? gather[(size_t)e * CAP + r] : (aCap ? e * CAP + r : r);
        Asrc = A + (size_t)row * aRL + lchunk * 8;
    }
    const unsigned short* Bsrc = W + (size_t)e * wStrideE + (size_t)(n0 + lrow) * bRL + lchunk * 8;
    const uint32_t a_dst = sbase + lrow * 80 + lchunk * 16;
    const uint32_t b_dst = a_dst + ATILE_B;

    // ---- fragment smem addresses ----
    const int wm = wid & 1;    // M half (64)
    const int wn = wid >> 1;   // N quarter (32)
    uint32_t aAddr[4][2], bAddr[2][2];
    {
        int arow = wm * 64 + (lane & 15);
        int acol = (lane >> 4) * 8;
        int brow = wn * 32 + ((lane >> 4) * 8) + (lane & 7);
        int bcol = ((lane >> 3) & 1) * 8;
        #pragma unroll
        for (int ks = 0; ks < 2; ks++) {
            #pragma unroll
            for (int mt = 0; mt < 4; mt++)
                aAddr[mt][ks] = sbase + ((arow + mt * 16) * ROWE + ks * 16 + acol) * 2;
            #pragma unroll
            for (int nt2 = 0; nt2 < 2; nt2++)
                bAddr[nt2][ks] = sbase + ATILE_B + ((brow + nt2 * 16) * ROWE + ks * 16 + bcol) * 2;
        }
    }

    float acc[4][4][4];
    #pragma unroll
    for (int mt = 0; mt < 4; mt++)
        #pragma unroll
        for (int nt = 0; nt < 4; nt++)
            #pragma unroll
            for (int k = 0; k < 4; k++) acc[mt][nt][k] = 0.0f;

    const int KPB = K >> 5;            // iterations per term
    const int NIT = nTerms * KPB;

    // stateful loader: advances (term, kk) each call, in issue order
    int ld_t = 0, ld_kk = 0;
    auto load_stage = [&](int s) {
        uint32_t off = s * STAGE_B;
        int aO = ((aMap >> (2 * ld_t)) & 3) * K + ld_kk * BK;
        int bO = ((bMap >> (2 * ld_t)) & 3) * K + ld_kk * BK;
        const unsigned short* as = Asrc + aO;
        const unsigned short* bs = Bsrc + bO;
        CPA16(a_dst + off,      as);
        CPA16(a_dst + off + 16, as + 8);
        CPA16(b_dst + off,      bs);
        CPA16(b_dst + off + 16, bs + 8);
        if (++ld_kk == KPB) { ld_kk = 0; ld_t++; }
    };

    load_stage(0); CP_COMMIT();
    load_stage(1); CP_COMMIT();

    for (int it = 0; it < NIT; it++) {
        CP_WAIT1();
        __syncthreads();
        if (it + STAGES - 1 < NIT) load_stage((it + STAGES - 1) % STAGES);
        CP_COMMIT();

        const uint32_t soff = (it % STAGES) * STAGE_B;
        #pragma unroll
        for (int ks = 0; ks < 2; ks++) {
            uint32_t af[4][4], bf[2][4];
            #pragma unroll
            for (int mt = 0; mt < 4; mt++) LDSM4(af[mt], aAddr[mt][ks] + soff);
            #pragma unroll
            for (int nt2 = 0; nt2 < 2; nt2++) LDSM4(bf[nt2], bAddr[nt2][ks] + soff);
            #pragma unroll
            for (int mt = 0; mt < 4; mt++)
                #pragma unroll
                for (int nt = 0; nt < 4; nt++)
                    MMA16816(acc[mt][nt], af[mt], bf[nt >> 1][(nt & 1) * 2], bf[nt >> 1][(nt & 1) * 2 + 1]);
        }
    }

    // ---- epilogue: direct from c-fragments ----
    const float* biasE = bias + (size_t)e * bStrideE;
    const int cq = (lane & 3) * 2;
    const int r0 = lane >> 2;
    float b2v[4][2];
    #pragma unroll
    for (int nt = 0; nt < 4; nt++) {
        int n = n0 + wn * 32 + nt * 8 + cq;
        b2v[nt][0] = biasE[n];
        b2v[nt][1] = biasE[n + 1];
    }

    #pragma unroll
    for (int mt = 0; mt < 4; mt++) {
        #pragma unroll
        for (int h = 0; h < 2; h++) {
            int row = m0 + wm * 64 + mt * 16 + r0 + h * 8;
            if (row >= M) continue;
            size_t erow = (size_t)e * CAP + row;
            float  sc = 1.0f;
            size_t orow = 0;
            if (flags & FLAG_DEST) {
                sc   = scales[erow];
                orow = (size_t)dests[erow];
            } else if (flags & FLAG_OCAP) {
                orow = erow;
            } else {
                orow = (size_t)row;
            }
            #pragma unroll
            for (int nt = 0; nt < 4; nt++) {
                int n = n0 + wn * 32 + nt * 8 + cq;
                float v0 = acc[mt][nt][h * 2]     + b2v[nt][0];
                float v1 = acc[mt][nt][h * 2 + 1] + b2v[nt][1];
                if (flags & FLAG_ADD) {
                    float2 ad = *(const float2*)(addt + erow * N + n);
                    v0 += ad.x; v1 += ad.y;
                }
                if (flags & FLAG_RELU) { v0 = fmaxf(v0, 0.0f); v1 = fmaxf(v1, 0.0f); }
                if (flags & FLAG_SPLIT) {
                    __half h0 = __float2half_rn(v0);
                    __half h1 = __float2half_rn(v1);
                    __half l0 = __float2half_rn(v0 - __half2float(h0));
                    __half l1 = __float2half_rn(v1 - __half2float(h1));
                    size_t ob = erow * (size_t)(2 * N);   // [hi | lo] layout
                    *(__half2*)((__half*)outS + ob + n)     = __halves2half2(h0, h1);
                    *(__half2*)((__half*)outS + ob + N + n) = __halves2half2(l0, l1);
                } else {
                    float2 o2; o2.x = v0 * sc; o2.y = v1 * sc;
                    *(float2*)(outF + orow * N + n) = o2;
                }
            }
        }
    }
}

// ---------------- conversion kernels ----------------
// x [B,K] fp32 -> xh [B,2K] fp16: [hi | lo]
__global__ __launch_bounds__(256) void convert_x(const float* __restrict__ x,
                                                 unsigned short* __restrict__ xh,
                                                 int K, size_t total)
{
    size_t idx = (size_t)blockIdx.x * blockDim.x + threadIdx.x;
    if (idx >= total) return;
    size_t m = idx / K;
    int    k = (int)(idx % K);
    float v = x[idx];
    __half hi = __float2half_rn(v);
    __half lo = __float2half_rn(v - __half2float(hi));
    __half* o = (__half*)(xh + m * (size_t)(2 * K));
    o[k]     = hi;
    o[K + k] = lo;
}

// W [E,K,N] fp32 -> Wt [E,N,K] fp16 (single) or [E,N,2K] split, transposed
__global__ __launch_bounds__(256) void convert_w(const float* __restrict__ W,
                                                 unsigned short* __restrict__ Wt,
                                                 int K, int N, int split)
{
    const int e = blockIdx.z;
    __shared__ float t[32][33];
    const int n0 = blockIdx.x * 32;
    const int k0 = blockIdx.y * 32;
    const float* We = W + (size_t)e * K * N;
    #pragma unroll
    for (int j = 0; j < 4; j++) {
        int k = k0 + threadIdx.y + j * 8;
        t[threadIdx.y + j * 8][threadIdx.x] = We[(size_t)k * N + n0 + threadIdx.x];
    }
    __syncthreads();
    const int rowlen = split ? 2 * K : K;
    unsigned short* Wte = Wt + (size_t)e * N * (size_t)rowlen;
    #pragma unroll
    for (int j = 0; j < 4; j++) {
        int n = n0 + threadIdx.y + j * 8;
        int k = k0 + threadIdx.x;
        float v = t[threadIdx.x][threadIdx.y + j * 8];
        __half hi = __float2half_rn(v);
        __half* o = (__half*)(Wte + (size_t)n * (size_t)rowlen);
        o[k] = hi;
        if (split) o[K + k] = __float2half_rn(v - __half2float(hi));
    }
}

// ---------------- gating logits: one warp per token, N=8 ----------------
__global__ __launch_bounds__(256) void logits_kernel(
    const float* __restrict__ h, const float* __restrict__ gw2,
    const float* __restrict__ gb2, float* __restrict__ logits)
{
    int warp = (blockIdx.x * blockDim.x + threadIdx.x) >> 5;
    int lane = threadIdx.x & 31;
    if (warp >= B_TOK) return;
    const float4* hrow = (const float4*)(h + (size_t)warp * GHID);
    float acc[NE];
    #pragma unroll
    for (int e = 0; e < NE; e++) acc[e] = 0.0f;
    for (int i = lane; i < GHID / 4; i += 32) {
        float4 hv = hrow[i];
        const float* g = gw2 + (size_t)(i * 4) * NE;
        #pragma unroll
        for (int e = 0; e < NE; e++)
            acc[e] += hv.x * g[e] + hv.y * g[NE + e] + hv.z * g[2 * NE + e] + hv.w * g[3 * NE + e];
    }
    #pragma unroll
    for (int e = 0; e < NE; e++)
        #pragma unroll
        for (int off = 16; off > 0; off >>= 1)
            acc[e] += __shfl_xor_sync(0xFFFFFFFFu, acc[e], off);
    if (lane == 0) {
        #pragma unroll
        for (int e = 0; e < NE; e++)
            logits[(size_t)warp * NE + e] = acc[e] + gb2[e];
    }
}

// ---------------- routing ----------------
__global__ void init_kernel() {
    if (threadIdx.x < NE) g_counts[threadIdx.x] = 0;
}

__global__ __launch_bounds__(256) void route_kernel() {
    int t = blockIdx.x * blockDim.x + threadIdx.x;
    if (t >= B_TOK) return;
    float v[NE];
    #pragma unroll
    for (int e = 0; e < NE; e++) v[e] = g_logits[(size_t)t * NE + e];
    int i0 = 0;
    #pragma unroll
    for (int e = 1; e < NE; e++) if (v[e] > v[i0]) i0 = e;
    int i1 = (i0 == 0) ? 1 : 0;
    #pragma unroll
    for (int e = 0; e < NE; e++) if (e != i0 && v[e] > v[i1]) i1 = e;
    float b = __expf(v[i1] - v[i0]);
    float s = 1.0f + b;
    float w0 = 1.0f / s;
    float w1 = b / s;

    int p0 = atomicAdd(&g_counts[i0], 1);
    g_tokens[i0 * CAP + p0] = t;
    g_wts[i0 * CAP + p0]    = w0;
    g_dests[i0 * CAP + p0]  = 2 * t;

    int p1 = atomicAdd(&g_counts[i1], 1);
    g_tokens[i1 * CAP + p1] = t;
    g_wts[i1 * CAP + p1]    = w1;
    g_dests[i1 * CAP + p1]  = 2 * t + 1;
}

// ---------------- final reduce ----------------
__global__ __launch_bounds__(256) void reduce_kernel(float* __restrict__ out) {
    size_t idx = (size_t)blockIdx.x * blockDim.x + threadIdx.x;
    const size_t total = (size_t)B_TOK * DOUT / 4;
    if (idx >= total) return;
    size_t t  = idx / (DOUT / 4);
    size_t c4 = idx % (DOUT / 4);
    const float4* e4 = (const float4*)g_eout;
    float4 a = e4[(2 * t) * (DOUT / 4) + c4];
    float4 b = e4[(2 * t + 1) * (DOUT / 4) + c4];
    float4 r;
    r.x = a.x + b.x; r.y = a.y + b.y; r.z = a.z + b.z; r.w = a.w + b.w;
    ((float4*)out)[idx] = r;
}

// ---------------- host ----------------
extern "C" void kernel_launch(void* const* d_in, const int* in_sizes, int n_in,
                              void* d_out, int out_size) {
    const float* x   = (const float*)d_in[0];
    const float* w1  = (const float*)d_in[1];
    const float* b1  = (const float*)d_in[2];
    const float* w2  = (const float*)d_in[3];
    const float* b2  = (const float*)d_in[4];
    const float* w3  = (const float*)d_in[5];
    const float* b3  = (const float*)d_in[6];
    const float* wp  = (const float*)d_in[7];
    const float* bp  = (const float*)d_in[8];
    const float* gw1 = (const float*)d_in[9];
    const float* gb1 = (const float*)d_in[10];
    const float* gw2 = (const float*)d_in[11];
    const float* gb2 = (const float*)d_in[12];
    float* out = (float*)d_out;

    unsigned short *p_xh, *p_w1h, *p_wph, *p_w2h, *p_w3h, *p_gwh, *p_hs, *p_os;
    float *p_p, *p_hidden, *p_logits, *p_wts, *p_eout;
    int *p_counts, *p_tokens, *p_dests;
    cudaGetSymbolAddress((void**)&p_xh,     g_xh);
    cudaGetSymbolAddress((void**)&p_w1h,    g_w1h);
    cudaGetSymbolAddress((void**)&p_wph,    g_wph);
    cudaGetSymbolAddress((void**)&p_w2h,    g_w2h);
    cudaGetSymbolAddress((void**)&p_w3h,    g_w3h);
    cudaGetSymbolAddress((void**)&p_gwh,    g_gwh);
    cudaGetSymbolAddress((void**)&p_hs,     g_hs);
    cudaGetSymbolAddress((void**)&p_os,     g_os);
    cudaGetSymbolAddress((void**)&p_p,      g_p);
    cudaGetSymbolAddress((void**)&p_hidden, g_hidden);
    cudaGetSymbolAddress((void**)&p_logits, g_logits);
    cudaGetSymbolAddress((void**)&p_wts,    g_wts);
    cudaGetSymbolAddress((void**)&p_eout,   g_eout);
    cudaGetSymbolAddress((void**)&p_counts, g_counts);
    cudaGetSymbolAddress((void**)&p_tokens, g_tokens);
    cudaGetSymbolAddress((void**)&p_dests,  g_dests);

    cudaFuncSetAttribute(mma_gemm, cudaFuncAttributeMaxDynamicSharedMemorySize, DYN_SMEM);

    // conversions
    {
        size_t total = (size_t)B_TOK * DIN;
        convert_x<<<(unsigned)((total + 255) / 256), 256>>>(x, p_xh, DIN, total);
    }
    convert_w<<<dim3(HID / 32, DIN / 32, NE),  dim3(32, 8)>>>(w1,  p_w1h, DIN, HID,  0);
    convert_w<<<dim3(HID / 32, DIN / 32, NE),  dim3(32, 8)>>>(wp,  p_wph, DIN, HID,  0);
    convert_w<<<dim3(HID / 32, HID / 32, NE),  dim3(32, 8)>>>(w2,  p_w2h, HID, HID,  0);
    convert_w<<<dim3(DOUT / 32, HID / 32, NE), dim3(32, 8)>>>(w3,  p_w3h, HID, DOUT, 0);
    convert_w<<<dim3(GHID / 32, DIN / 32, 1),  dim3(32, 8)>>>(gw1, p_gwh, DIN, GHID, 1);

    // maps: 2 bits per term selecting stored K-block
    const int AMAP2 = 0 | (1 << 2);              // (hi, lo)
    const int BMAP2 = 0;                         // (b, b)
    const int AMAP3 = 0 | (1 << 2) | (0 << 4);   // (hi, lo, hi)
    const int BMAP3 = 0 | (0 << 2) | (1 << 4);   // (hi, hi, lo)

    // G1: gating hidden = relu(x @ gw1 + gb1), 3-term fp16 (accurate routing)
    mma_gemm<<<dim3(GHID / BN, B_TOK / BM, 1), 256, DYN_SMEM>>>(
        p_xh, 2 * DIN, 0, nullptr, p_gwh, 0, 2 * DIN, gb1, 0, nullptr,
        p_hidden, nullptr, nullptr, nullptr, nullptr, B_TOK,
        DIN, 3, AMAP3, BMAP3, GHID, FLAG_RELU);

    // G2 + routing
    logits_kernel<<<B_TOK / 8, 256>>>(p_hidden, gw2, gb2, p_logits);
    init_kernel<<<1, 32>>>();
    route_kernel<<<B_TOK / 256, 256>>>();

    // L1: h = relu(x_g @ w1 + b1) -> split fp16
    mma_gemm<<<dim3(HID / BN, CAP / BM, NE), 256, DYN_SMEM>>>(
        p_xh, 2 * DIN, 0, p_tokens, p_w1h, (size_t)HID * DIN, DIN, b1, HID, nullptr,
        nullptr, p_hs, nullptr, nullptr, p_counts, 0,
        DIN, 2, AMAP2, BMAP2, HID, FLAG_RELU | FLAG_SPLIT);

    // L2: p = x_g @ wp + bp  (fp32, capacity layout)
    mma_gemm<<<dim3(HID / BN, CAP / BM, NE), 256, DYN_SMEM>>>(
        p_xh, 2 * DIN, 0, p_tokens, p_wph, (size_t)HID * DIN, DIN, bp, HID, nullptr,
        p_p, nullptr, nullptr, nullptr, p_counts, 0,
        DIN, 2, AMAP2, BMAP2, HID, FLAG_OCAP);

    // L3: o = relu(h @ w2 + b2 + p) -> split fp16
    mma_gemm<<<dim3(HID / BN, CAP / BM, NE), 256, DYN_SMEM>>>(
        p_hs, 2 * HID, 1, nullptr, p_w2h, (size_t)HID * HID, HID, b2, HID, p_p,
        nullptr, p_os, nullptr, nullptr, p_counts, 0,
        HID, 2, AMAP2, BMAP2, HID, FLAG_RELU | FLAG_ADD | FLAG_SPLIT);

    // L4: eout[dest] = (o @ w3 + b3) * gate_w
    mma_gemm<<<dim3(DOUT / BN, CAP / BM, NE), 256, DYN_SMEM>>>(
        p_os, 2 * HID, 1, nullptr, p_w3h, (size_t)DOUT * HID, HID, b3, DOUT, nullptr,
        p_eout, nullptr, p_wts, p_dests, p_counts, 0,
        HID, 2, AMAP2, BMAP2, DOUT, FLAG_DEST);

    // reduce
    size_t total4 = (size_t)B_TOK * DOUT / 4;
    reduce_kernel<<<(unsigned)((total4 + 255) / 256), 256>>>(out);
}

// round 6
// speedup vs baseline: 1.0893x; 1.0893x over previous
#include <cuda_runtime.h>
#include <cuda_fp16.h>
#include <cstdint>

// ---------------- problem constants ----------------
#define B_TOK 8192
#define DIN   1024
#define HID   2048
#define DOUT  1024
#define NE    8
#define GHID  1024
#define CAP   8192

#define FLAG_RELU  1
#define FLAG_ADD   2
#define FLAG_SPLIT 4
#define FLAG_DEST  8
#define FLAG_OCAP  16

// ---------------- scratch (static device globals) ----------------
__device__ unsigned short g_xh  [(size_t)B_TOK*2*DIN];      // x split fp16 [hi|lo]
__device__ unsigned short g_w1h [(size_t)NE*HID*DIN];       // w1^T fp16
__device__ unsigned short g_wph [(size_t)NE*HID*DIN];
__device__ unsigned short g_w2h [(size_t)NE*HID*HID];
__device__ unsigned short g_w3h [(size_t)NE*DOUT*HID];
__device__ unsigned short g_gwh [(size_t)GHID*2*DIN];       // gw1^T split [hi|lo]
__device__ unsigned short g_hs  [(size_t)NE*CAP*2*HID];     // h split [hi|lo] (L1 out)
__device__ unsigned short g_os  [(size_t)NE*CAP*2*HID];     // o split [hi|lo] (L3 out)
__device__ float g_p     [(size_t)NE*CAP*HID];              // projection (L2 out)
__device__ float g_hidden[(size_t)B_TOK*GHID];
__device__ float g_logits[(size_t)B_TOK*NE];
__device__ int   g_counts[NE];
__device__ int   g_tokens[(size_t)NE*CAP];
__device__ float g_wts   [(size_t)NE*CAP];
__device__ int   g_dests [(size_t)NE*CAP];
__device__ float g_eout  [(size_t)B_TOK*2*DOUT];

// ---------------- PTX helpers (baseline ISA only) ----------------
__device__ __forceinline__ uint32_t smem_u32(const void* p) {
    uint32_t a;
    asm("{ .reg .u64 t; cvta.to.shared.u64 t, %1; cvt.u32.u64 %0, t; }" : "=r"(a) : "l"(p));
    return a;
}
#define CPA16(dst, src) \
    asm volatile("cp.async.cg.shared.global [%0], [%1], 16;" :: "r"(dst), "l"(src) : "memory")
#define CP_COMMIT() asm volatile("cp.async.commit_group;" ::: "memory")
#define LDSM4(r, addr) \
    asm volatile("ldmatrix.sync.aligned.m8n8.x4.shared.b16 {%0,%1,%2,%3}, [%4];" \
        : "=r"((r)[0]), "=r"((r)[1]), "=r"((r)[2]), "=r"((r)[3]) : "r"(addr))
#define MMA16816(d, a, b0, b1) \
    asm volatile("mma.sync.aligned.m16n8k16.row.col.f32.f16.f16.f32 " \
        "{%0,%1,%2,%3},{%4,%5,%6,%7},{%8,%9},{%0,%1,%2,%3};" \
        : "+f"((d)[0]), "+f"((d)[1]), "+f"((d)[2]), "+f"((d)[3]) \
        : "r"((a)[0]), "r"((a)[1]), "r"((a)[2]), "r"((a)[3]), "r"(b0), "r"(b1))

// ---------------- HMMA GEMM: tile 128x256x32, dual-A-term, 8 warps ----------------
// Stage = [A_hi | A_lo | B_hi | (B_lo if BSPLIT)].
// Per k-block: acc += A_hi*B_hi + A_lo*B_hi (+ A_hi*B_lo if BSPLIT).
// BSPLIT=0: exact A, fp16-rounded B -> rel err ~2^-11 (expert layers).
// BSPLIT=1: rel err ~2^-22 (gating — routing needs near-exact logits).
#define BM 128
#define BN 256
#define BK 32
#define ROWE 40                   // padded row stride (elems): 80B, conflict-free ldmatrix
#define A_B   (BM * ROWE * 2)     // 10240 per A term
#define B_B   (BN * ROWE * 2)     // 20480 per B term
#define DYN_SMEM_E (5 * (2 * A_B + B_B))       // 204800 (experts, 5 stages)
#define DYN_SMEM_G (3 * (2 * A_B + 2 * B_B))   // 184320 (gating, 3 stages)

template<int BSPLIT, int NSTAGES>
__global__ __launch_bounds__(256) void mma_gemm(
    const unsigned short* __restrict__ A, int aRL, int aCap,
    const int* __restrict__ gather,
    const unsigned short* __restrict__ W, size_t wStrideE, int bRL,
    const float* __restrict__ bias, int bStrideE,
    const float* __restrict__ addt,
    float* __restrict__ outF, unsigned short* __restrict__ outS,
    const float* __restrict__ scales, const int* __restrict__ dests,
    const int* __restrict__ counts, int Mfixed,
    int K, int N, int flags)
{
    constexpr uint32_t STAGE_B = 2 * A_B + (1 + BSPLIT) * B_B;

    const int e  = blockIdx.z;
    const int M  = counts ? counts[e] : Mfixed;
    const int m0 = blockIdx.y * BM;
    if (m0 >= M) return;
    const int n0 = blockIdx.x * BN;

    extern __shared__ char smem[];
    const uint32_t sbase = smem_u32(smem);

    const int tid  = threadIdx.x;
    const int wid  = tid >> 5;
    const int lane = tid & 31;

    // ---- load mapping: 2 threads per row ----
    const int lrow   = tid >> 1;           // 0..127
    const int lchunk = (tid & 1) * 2;      // chunk pair
    const unsigned short* Asrc;            // hi term; lo term at +K
    {
        int r = m0 + lrow;
        int row = gather ? gather[(size_t)e * CAP + r] : (aCap ? e * CAP + r : r);
        Asrc = A + (size_t)row * aRL + lchunk * 8;
    }
    const unsigned short* Bsrc0 = W + (size_t)e * wStrideE + (size_t)(n0 + lrow) * bRL + lchunk * 8;
    const unsigned short* Bsrc1 = Bsrc0 + (size_t)128 * bRL;
    const uint32_t a0_dst = sbase + lrow * 80 + lchunk * 16;
    const uint32_t a1_dst = a0_dst + A_B;
    const uint32_t b0_dst = sbase + 2 * A_B + lrow * 80 + lchunk * 16;
    const uint32_t b1_dst = b0_dst + 128 * 80;

    // ---- fragment smem addresses: warp tile 64x64 ----
    const int wm = wid & 1;    // M half (64)
    const int wn = wid >> 1;   // N quarter (64)
    uint32_t aAddr[4][2], bAddr[4][2];
    {
        int arow = wm * 64 + (lane & 15);
        int acol = (lane >> 4) * 8;
        int brbase = wn * 64 + ((lane >> 4) * 8) + (lane & 7);
        int bcol = ((lane >> 3) & 1) * 8;
        #pragma unroll
        for (int ks = 0; ks < 2; ks++) {
            #pragma unroll
            for (int mt = 0; mt < 4; mt++)
                aAddr[mt][ks] = sbase + ((arow + mt * 16) * ROWE + ks * 16 + acol) * 2;
            #pragma unroll
            for (int nt2 = 0; nt2 < 4; nt2++)
                bAddr[nt2][ks] = sbase + 2 * A_B + ((brbase + nt2 * 16) * ROWE + ks * 16 + bcol) * 2;
        }
    }

    float acc[4][8][4];
    #pragma unroll
    for (int mt = 0; mt < 4; mt++)
        #pragma unroll
        for (int nt = 0; nt < 8; nt++)
            #pragma unroll
            for (int k = 0; k < 4; k++) acc[mt][nt][k] = 0.0f;

    const int NIT = K >> 5;

    auto load_stage = [&](int s, int it) {
        uint32_t off = s * STAGE_B;
        const unsigned short* ah = Asrc + it * BK;
        const unsigned short* al = ah + K;
        const unsigned short* b0 = Bsrc0 + it * BK;
        const unsigned short* b1 = Bsrc1 + it * BK;
        CPA16(a0_dst + off,      ah);
        CPA16(a0_dst + off + 16, ah + 8);
        CPA16(a1_dst + off,      al);
        CPA16(a1_dst + off + 16, al + 8);
        CPA16(b0_dst + off,      b0);
        CPA16(b0_dst + off + 16, b0 + 8);
        CPA16(b1_dst + off,      b1);
        CPA16(b1_dst + off + 16, b1 + 8);
        if (BSPLIT) {
            const unsigned short* b0l = b0 + K;
            const unsigned short* b1l = b1 + K;
            CPA16(b0_dst + off + B_B,      b0l);
            CPA16(b0_dst + off + B_B + 16, b0l + 8);
            CPA16(b1_dst + off + B_B,      b1l);
            CPA16(b1_dst + off + B_B + 16, b1l + 8);
        }
    };

    #pragma unroll
    for (int s = 0; s < NSTAGES - 1; s++) {
        if (s < NIT) load_stage(s, s);
        CP_COMMIT();
    }

    for (int it = 0; it < NIT; it++) {
        asm volatile("cp.async.wait_group %0;" :: "n"(NSTAGES - 2) : "memory");
        __syncthreads();
        if (it + NSTAGES - 1 < NIT) load_stage((it + NSTAGES - 1) % NSTAGES, it + NSTAGES - 1);
        CP_COMMIT();

        const uint32_t soff = (it % NSTAGES) * STAGE_B;
        #pragma unroll
        for (int ks = 0; ks < 2; ks++) {
            uint32_t af0[4][4], af1[4][4], bf[4][4];
            #pragma unroll
            for (int mt = 0; mt < 4; mt++) {
                LDSM4(af0[mt], aAddr[mt][ks] + soff);
                LDSM4(af1[mt], aAddr[mt][ks] + soff + A_B);
            }
            #pragma unroll
            for (int nt2 = 0; nt2 < 4; nt2++) LDSM4(bf[nt2], bAddr[nt2][ks] + soff);
            #pragma unroll
            for (int mt = 0; mt < 4; mt++)
                #pragma unroll
                for (int nt = 0; nt < 8; nt++)
                    MMA16816(acc[mt][nt], af0[mt], bf[nt >> 1][(nt & 1) * 2], bf[nt >> 1][(nt & 1) * 2 + 1]);
            #pragma unroll
            for (int mt = 0; mt < 4; mt++)
                #pragma unroll
                for (int nt = 0; nt < 8; nt++)
                    MMA16816(acc[mt][nt], af1[mt], bf[nt >> 1][(nt & 1) * 2], bf[nt >> 1][(nt & 1) * 2 + 1]);
            if (BSPLIT) {
                uint32_t bfl[4][4];
                #pragma unroll
                for (int nt2 = 0; nt2 < 4; nt2++) LDSM4(bfl[nt2], bAddr[nt2][ks] + soff + B_B);
                #pragma unroll
                for (int mt = 0; mt < 4; mt++)
                    #pragma unroll
                    for (int nt = 0; nt < 8; nt++)
                        MMA16816(acc[mt][nt], af0[mt], bfl[nt >> 1][(nt & 1) * 2], bfl[nt >> 1][(nt & 1) * 2 + 1]);
            }
        }
    }

    // ---- epilogue: direct from c-fragments ----
    const float* biasE = bias + (size_t)e * bStrideE;
    const int cq = (lane & 3) * 2;
    const int r0 = lane >> 2;
    float b2v[8][2];
    #pragma unroll
    for (int nt = 0; nt < 8; nt++) {
        int n = n0 + wn * 64 + nt * 8 + cq;
        b2v[nt][0] = biasE[n];
        b2v[nt][1] = biasE[n + 1];
    }

    #pragma unroll
    for (int mt = 0; mt < 4; mt++) {
        #pragma unroll
        for (int h = 0; h < 2; h++) {
            int row = m0 + wm * 64 + mt * 16 + r0 + h * 8;
            if (row >= M) continue;
            size_t erow = (size_t)e * CAP + row;
            float  sc = 1.0f;
            size_t orow = 0;
            if (flags & FLAG_DEST) {
                sc   = scales[erow];
                orow = (size_t)dests[erow];
            } else if (flags & FLAG_OCAP) {
                orow = erow;
            } else {
                orow = (size_t)row;
            }
            #pragma unroll
            for (int nt = 0; nt < 8; nt++) {
                int n = n0 + wn * 64 + nt * 8 + cq;
                float v0 = acc[mt][nt][h * 2]     + b2v[nt][0];
                float v1 = acc[mt][nt][h * 2 + 1] + b2v[nt][1];
                if (flags & FLAG_ADD) {
                    float2 ad = *(const float2*)(addt + erow * N + n);
                    v0 += ad.x; v1 += ad.y;
                }
                if (flags & FLAG_RELU) { v0 = fmaxf(v0, 0.0f); v1 = fmaxf(v1, 0.0f); }
                if (flags & FLAG_SPLIT) {
                    __half h0 = __float2half_rn(v0);
                    __half h1 = __float2half_rn(v1);
                    __half l0 = __float2half_rn(v0 - __half2float(h0));
                    __half l1 = __float2half_rn(v1 - __half2float(h1));
                    size_t ob = erow * (size_t)(2 * N);   // [hi | lo]
                    *(__half2*)((__half*)outS + ob + n)     = __halves2half2(h0, h1);
                    *(__half2*)((__half*)outS + ob + N + n) = __halves2half2(l0, l1);
                } else {
                    float2 o2; o2.x = v0 * sc; o2.y = v1 * sc;
                    *(float2*)(outF + orow * N + n) = o2;
                }
            }
        }
    }
}

// ---------------- conversion kernels ----------------
// x [B,K] fp32 -> xh [B,2K] fp16: [hi | lo]
__global__ __launch_bounds__(256) void convert_x(const float* __restrict__ x,
                                                 unsigned short* __restrict__ xh,
                                                 int K, size_t total)
{
    size_t idx = (size_t)blockIdx.x * blockDim.x + threadIdx.x;
    if (idx >= total) return;
    size_t m = idx / K;
    int    k = (int)(idx % K);
    float v = x[idx];
    __half hi = __float2half_rn(v);
    __half lo = __float2half_rn(v - __half2float(hi));
    __half* o = (__half*)(xh + m * (size_t)(2 * K));
    o[k]     = hi;
    o[K + k] = lo;
}

// W [E,K,N] fp32 -> Wt [E,N,K] fp16 (single) or [E,N,2K] split [hi|lo], transposed
__global__ __launch_bounds__(256) void convert_w(const float* __restrict__ W,
                                                 unsigned short* __restrict__ Wt,
                                                 int K, int N, int split)
{
    const int e = blockIdx.z;
    __shared__ float t[32][33];
    const int n0 = blockIdx.x * 32;
    const int k0 = blockIdx.y * 32;
    const float* We = W + (size_t)e * K * N;
    #pragma unroll
    for (int j = 0; j < 4; j++) {
        int k = k0 + threadIdx.y + j * 8;
        t[threadIdx.y + j * 8][threadIdx.x] = We[(size_t)k * N + n0 + threadIdx.x];
    }
    __syncthreads();
    const int rowlen = split ? 2 * K : K;
    unsigned short* Wte = Wt + (size_t)e * N * (size_t)rowlen;
    #pragma unroll
    for (int j = 0; j < 4; j++) {
        int n = n0 + threadIdx.y + j * 8;
        int k = k0 + threadIdx.x;
        float v = t[threadIdx.x][threadIdx.y + j * 8];
        __half hi = __float2half_rn(v);
        __half* o = (__half*)(Wte + (size_t)n * (size_t)rowlen);
        o[k] = hi;
        if (split) o[K + k] = __float2half_rn(v - __half2float(hi));
    }
}

// ---------------- gating logits: one warp per token, N=8 ----------------
__global__ __launch_bounds__(256) void logits_kernel(
    const float* __restrict__ h, const float* __restrict__ gw2,
    const float* __restrict__ gb2, float* __restrict__ logits)
{
    int warp = (blockIdx.x * blockDim.x + threadIdx.x) >> 5;
    int lane = threadIdx.x & 31;
    if (warp >= B_TOK) return;
    const float4* hrow = (const float4*)(h + (size_t)warp * GHID);
    float acc[NE];
    #pragma unroll
    for (int e = 0; e < NE; e++) acc[e] = 0.0f;
    for (int i = lane; i < GHID / 4; i += 32) {
        float4 hv = hrow[i];
        const float* g = gw2 + (size_t)(i * 4) * NE;
        #pragma unroll
        for (int e = 0; e < NE; e++)
            acc[e] += hv.x * g[e] + hv.y * g[NE + e] + hv.z * g[2 * NE + e] + hv.w * g[3 * NE + e];
    }
    #pragma unroll
    for (int e = 0; e < NE; e++)
        #pragma unroll
        for (int off = 16; off > 0; off >>= 1)
            acc[e] += __shfl_xor_sync(0xFFFFFFFFu, acc[e], off);
    if (lane == 0) {
        #pragma unroll
        for (int e = 0; e < NE; e++)
            logits[(size_t)warp * NE + e] = acc[e] + gb2[e];
    }
}

// ---------------- routing ----------------
__global__ void init_kernel() {
    if (threadIdx.x < NE) g_counts[threadIdx.x] = 0;
}

__global__ __launch_bounds__(256) void route_kernel() {
    int t = blockIdx.x * blockDim.x + threadIdx.x;
    if (t >= B_TOK) return;
    float v[NE];
    #pragma unroll
    for (int e = 0; e < NE; e++) v[e] = g_logits[(size_t)t * NE + e];
    int i0 = 0;
    #pragma unroll
    for (int e = 1; e < NE; e++) if (v[e] > v[i0]) i0 = e;
    int i1 = (i0 == 0) ? 1 : 0;
    #pragma unroll
    for (int e = 0; e < NE; e++) if (e != i0 && v[e] > v[i1]) i1 = e;
    float b = __expf(v[i1] - v[i0]);
    float s = 1.0f + b;
    float w0 = 1.0f / s;
    float w1 = b / s;

    int p0 = atomicAdd(&g_counts[i0], 1);
    g_tokens[i0 * CAP + p0] = t;
    g_wts[i0 * CAP + p0]    = w0;
    g_dests[i0 * CAP + p0]  = 2 * t;

    int p1 = atomicAdd(&g_counts[i1], 1);
    g_tokens[i1 * CAP + p1] = t;
    g_wts[i1 * CAP + p1]    = w1;
    g_dests[i1 * CAP + p1]  = 2 * t + 1;
}

// ---------------- final reduce ----------------
__global__ __launch_bounds__(256) void reduce_kernel(float* __restrict__ out) {
    size_t idx = (size_t)blockIdx.x * blockDim.x + threadIdx.x;
    const size_t total = (size_t)B_TOK * DOUT / 4;
    if (idx >= total) return;
    size_t t  = idx / (DOUT / 4);
    size_t c4 = idx % (DOUT / 4);
    const float4* e4 = (const float4*)g_eout;
    float4 a = e4[(2 * t) * (DOUT / 4) + c4];
    float4 b = e4[(2 * t + 1) * (DOUT / 4) + c4];
    float4 r;
    r.x = a.x + b.x; r.y = a.y + b.y; r.z = a.z + b.z; r.w = a.w + b.w;
    ((float4*)out)[idx] = r;
}

// ---------------- host ----------------
extern "C" void kernel_launch(void* const* d_in, const int* in_sizes, int n_in,
                              void* d_out, int out_size) {
    const float* x   = (const float*)d_in[0];
    const float* w1  = (const float*)d_in[1];
    const float* b1  = (const float*)d_in[2];
    const float* w2  = (const float*)d_in[3];
    const float* b2  = (const float*)d_in[4];
    const float* w3  = (const float*)d_in[5];
    const float* b3  = (const float*)d_in[6];
    const float* wp  = (const float*)d_in[7];
    const float* bp  = (const float*)d_in[8];
    const float* gw1 = (const float*)d_in[9];
    const float* gb1 = (const float*)d_in[10];
    const float* gw2 = (const float*)d_in[11];
    const float* gb2 = (const float*)d_in[12];
    float* out = (float*)d_out;

    unsigned short *p_xh, *p_w1h, *p_wph, *p_w2h, *p_w3h, *p_gwh, *p_hs, *p_os;
    float *p_p, *p_hidden, *p_logits, *p_wts, *p_eout;
    int *p_counts, *p_tokens, *p_dests;
    cudaGetSymbolAddress((void**)&p_xh,     g_xh);
    cudaGetSymbolAddress((void**)&p_w1h,    g_w1h);
    cudaGetSymbolAddress((void**)&p_wph,    g_wph);
    cudaGetSymbolAddress((void**)&p_w2h,    g_w2h);
    cudaGetSymbolAddress((void**)&p_w3h,    g_w3h);
    cudaGetSymbolAddress((void**)&p_gwh,    g_gwh);
    cudaGetSymbolAddress((void**)&p_hs,     g_hs);
    cudaGetSymbolAddress((void**)&p_os,     g_os);
    cudaGetSymbolAddress((void**)&p_p,      g_p);
    cudaGetSymbolAddress((void**)&p_hidden, g_hidden);
    cudaGetSymbolAddress((void**)&p_logits, g_logits);
    cudaGetSymbolAddress((void**)&p_wts,    g_wts);
    cudaGetSymbolAddress((void**)&p_eout,   g_eout);
    cudaGetSymbolAddress((void**)&p_counts, g_counts);
    cudaGetSymbolAddress((void**)&p_tokens, g_tokens);
    cudaGetSymbolAddress((void**)&p_dests,  g_dests);

    cudaFuncSetAttribute(mma_gemm<0,5>, cudaFuncAttributeMaxDynamicSharedMemorySize, DYN_SMEM_E);
    cudaFuncSetAttribute(mma_gemm<1,3>, cudaFuncAttributeMaxDynamicSharedMemorySize, DYN_SMEM_G);

    // conversions
    {
        size_t total = (size_t)B_TOK * DIN;
        convert_x<<<(unsigned)((total + 255) / 256), 256>>>(x, p_xh, DIN, total);
    }
    convert_w<<<dim3(HID / 32, DIN / 32, NE),  dim3(32, 8)>>>(w1,  p_w1h, DIN, HID,  0);
    convert_w<<<dim3(HID / 32, DIN / 32, NE),  dim3(32, 8)>>>(wp,  p_wph, DIN, HID,  0);
    convert_w<<<dim3(HID / 32, HID / 32, NE),  dim3(32, 8)>>>(w2,  p_w2h, HID, HID,  0);
    convert_w<<<dim3(DOUT / 32, HID / 32, NE), dim3(32, 8)>>>(w3,  p_w3h, HID, DOUT, 0);
    convert_w<<<dim3(GHID / 32, DIN / 32, 1),  dim3(32, 8)>>>(gw1, p_gwh, DIN, GHID, 1);

    // G1: gating hidden = relu(x @ gw1 + gb1), 3-term (err ~2^-22, exact routing)
    mma_gemm<1,3><<<dim3(GHID / BN, B_TOK / BM, 1), 256, DYN_SMEM_G>>>(
        p_xh, 2 * DIN, 0, nullptr, p_gwh, 0, 2 * DIN, gb1, 0, nullptr,
        p_hidden, nullptr, nullptr, nullptr, nullptr, B_TOK,
        DIN, GHID, FLAG_RELU);

    // G2 + routing
    logits_kernel<<<B_TOK / 8, 256>>>(p_hidden, gw2, gb2, p_logits);
    init_kernel<<<1, 32>>>();
    route_kernel<<<B_TOK / 256, 256>>>();

    // L1: h = relu(x_g @ w1 + b1) -> split fp16
    mma_gemm<0,5><<<dim3(HID / BN, CAP / BM, NE), 256, DYN_SMEM_E>>>(
        p_xh, 2 * DIN, 0, p_tokens, p_w1h, (size_t)HID * DIN, DIN, b1, HID, nullptr,
        nullptr, p_hs, nullptr, nullptr, p_counts, 0,
        DIN, HID, FLAG_RELU | FLAG_SPLIT);

    // L2: p = x_g @ wp + bp  (fp32, capacity layout)
    mma_gemm<0,5><<<dim3(HID / BN, CAP / BM, NE), 256, DYN_SMEM_E>>>(
        p_xh, 2 * DIN, 0, p_tokens, p_wph, (size_t)HID * DIN, DIN, bp, HID, nullptr,
        p_p, nullptr, nullptr, nullptr, p_counts, 0,
        DIN, HID, FLAG_OCAP);

    // L3: o = relu(h @ w2 + b2 + p) -> split fp16
    mma_gemm<0,5><<<dim3(HID / BN, CAP / BM, NE), 256, DYN_SMEM_E>>>(
        p_hs, 2 * HID, 1, nullptr, p_w2h, (size_t)HID * HID, HID, b2, HID, p_p,
        nullptr, p_os, nullptr, nullptr, p_counts, 0,
        HID, HID, FLAG_RELU | FLAG_ADD | FLAG_SPLIT);

    // L4: eout[dest] = (o @ w3 + b3) * gate_w
    mma_gemm<0,5><<<dim3(DOUT / BN, CAP / BM, NE), 256, DYN_SMEM_E>>>(
        p_os, 2 * HID, 1, nullptr, p_w3h, (size_t)DOUT * HID, HID, b3, DOUT, nullptr,
        p_eout, nullptr, p_wts, p_dests, p_counts, 0,
        HID, DOUT, FLAG_DEST);

    // reduce
    size_t total4 = (size_t)B_TOK * DOUT / 4;
    reduce_kernel<<<(unsigned)((total4 + 255) / 256), 256>>>(out);
}

// round 7
// speedup vs baseline: 2.4042x; 2.2072x over previous
#include <cuda_runtime.h>
#include <cuda_fp16.h>
#include <cstdint>

// ---------------- problem constants ----------------
#define B_TOK 8192
#define DIN   1024
#define HID   2048
#define DOUT  1024
#define NE    8
#define GHID  1024
#define CAP   8192

#define FLAG_RELU  1
#define FLAG_ADD   2
#define FLAG_SPLIT 4
#define FLAG_DEST  8
#define FLAG_OCAP  16

// ---------------- scratch (static device globals) ----------------
__device__ unsigned short g_xh  [(size_t)B_TOK*2*DIN];      // x split fp16 [hi|lo] (lo used by G1 only)
__device__ unsigned short g_w1h [(size_t)NE*HID*DIN];       // w1^T fp16
__device__ unsigned short g_wph [(size_t)NE*HID*DIN];
__device__ unsigned short g_w2h [(size_t)NE*HID*HID];
__device__ unsigned short g_w3h [(size_t)NE*DOUT*HID];
__device__ unsigned short g_gwh [(size_t)GHID*2*DIN];       // gw1^T split [hi|lo]
__device__ unsigned short g_hs  [(size_t)NE*CAP*HID];       // h fp16 (L1 out)
__device__ unsigned short g_os  [(size_t)NE*CAP*HID];       // o fp16 (L3 out)
__device__ float g_p     [(size_t)NE*CAP*HID];              // projection (L2 out)
__device__ float g_hidden[(size_t)B_TOK*GHID];
__device__ float g_logits[(size_t)B_TOK*NE];
__device__ int   g_counts[NE];
__device__ int   g_tokens[(size_t)NE*CAP];
__device__ float g_wts   [(size_t)NE*CAP];
__device__ int   g_dests [(size_t)NE*CAP];
__device__ float g_eout  [(size_t)B_TOK*2*DOUT];

// ---------------- PTX helpers (baseline ISA only) ----------------
__device__ __forceinline__ uint32_t smem_u32(const void* p) {
    uint32_t a;
    asm("{ .reg .u64 t; cvta.to.shared.u64 t, %1; cvt.u32.u64 %0, t; }" : "=r"(a) : "l"(p));
    return a;
}
#define CPA16(dst, src) \
    asm volatile("cp.async.cg.shared.global [%0], [%1], 16;" :: "r"(dst), "l"(src) : "memory")
#define CP_COMMIT() asm volatile("cp.async.commit_group;" ::: "memory")
#define LDSM4(r, addr) \
    asm volatile("ldmatrix.sync.aligned.m8n8.x4.shared.b16 {%0,%1,%2,%3}, [%4];" \
        : "=r"((r)[0]), "=r"((r)[1]), "=r"((r)[2]), "=r"((r)[3]) : "r"(addr))
#define MMA16816(d, a, b0, b1) \
    asm volatile("mma.sync.aligned.m16n8k16.row.col.f32.f16.f16.f32 " \
        "{%0,%1,%2,%3},{%4,%5,%6,%7},{%8,%9},{%0,%1,%2,%3};" \
        : "+f"((d)[0]), "+f"((d)[1]), "+f"((d)[2]), "+f"((d)[3]) \
        : "r"((a)[0]), "r"((a)[1]), "r"((a)[2]), "r"((a)[3]), "r"(b0), "r"(b1))

// ---------------- HMMA GEMM: tile 128x256x32, 8 warps ----------------
// Stage = [A_hi | (A_lo if ATERMS==2) | B_hi | (B_lo if BSPLIT)].
// Per k-block: acc += A_hi*B_hi (+ A_lo*B_hi if ATERMS==2) (+ A_hi*B_lo if BSPLIT).
// Experts: ATERMS=1, BSPLIT=0 (rel err ~2^-11·sqrt(layers)).
// Gating:  ATERMS=2, BSPLIT=1 (rel err ~2^-22 — routing needs near-exact logits).
#define BM 128
#define BN 256
#define BK 32
#define ROWE 40                   // padded row stride (elems): 80B, conflict-free ldmatrix
#define A_B   (BM * ROWE * 2)     // 10240 per A term
#define B_B   (BN * ROWE * 2)     // 20480 per B term
#define DYN_SMEM_E (8 * (A_B + B_B))           // 245760? no: 8*30720=245760 > 227KB -> use 7
#undef  DYN_SMEM_E
#define NSTAGES_E 7
#define DYN_SMEM_E (NSTAGES_E * (A_B + B_B))   // 7*30720 = 215040 (experts)
#define DYN_SMEM_G (3 * (2 * A_B + 2 * B_B))   // 184320 (gating, 3 stages)

template<int ATERMS, int BSPLIT, int NSTAGES>
__global__ __launch_bounds__(256) void mma_gemm(
    const unsigned short* __restrict__ A, int aRL, int aCap,
    const int* __restrict__ gather,
    const unsigned short* __restrict__ W, size_t wStrideE, int bRL,
    const float* __restrict__ bias, int bStrideE,
    const float* __restrict__ addt,
    float* __restrict__ outF, unsigned short* __restrict__ outS,
    const float* __restrict__ scales, const int* __restrict__ dests,
    const int* __restrict__ counts, int Mfixed,
    int K, int N, int flags)
{
    constexpr uint32_t STAGE_B = ATERMS * A_B + (1 + BSPLIT) * B_B;

    const int e  = blockIdx.z;
    const int M  = counts ? counts[e] : Mfixed;
    const int m0 = blockIdx.y * BM;
    if (m0 >= M) return;
    const int n0 = blockIdx.x * BN;

    extern __shared__ char smem[];
    const uint32_t sbase = smem_u32(smem);

    const int tid  = threadIdx.x;
    const int wid  = tid >> 5;
    const int lane = tid & 31;

    // ---- load mapping: 2 threads per row ----
    const int lrow   = tid >> 1;           // 0..127
    const int lchunk = (tid & 1) * 2;      // chunk pair
    const unsigned short* Asrc;            // hi term; lo term at +K (if ATERMS==2)
    {
        int r = m0 + lrow;
        int row = gather ? gather[(size_t)e * CAP + r] : (aCap ? e * CAP + r : r);
        Asrc = A + (size_t)row * aRL + lchunk * 8;
    }
    const unsigned short* Bsrc0 = W + (size_t)e * wStrideE + (size_t)(n0 + lrow) * bRL + lchunk * 8;
    const unsigned short* Bsrc1 = Bsrc0 + (size_t)128 * bRL;
    const uint32_t a0_dst = sbase + lrow * 80 + lchunk * 16;
    const uint32_t a1_dst = a0_dst + A_B;
    const uint32_t b0_dst = sbase + ATERMS * A_B + lrow * 80 + lchunk * 16;
    const uint32_t b1_dst = b0_dst + 128 * 80;

    // ---- fragment smem addresses: warp tile 64x64 ----
    const int wm = wid & 1;    // M half (64)
    const int wn = wid >> 1;   // N quarter (64)
    uint32_t aAddr[4][2], bAddr[4][2];
    {
        int arow = wm * 64 + (lane & 15);
        int acol = (lane >> 4) * 8;
        int brbase = wn * 64 + ((lane >> 4) * 8) + (lane & 7);
        int bcol = ((lane >> 3) & 1) * 8;
        #pragma unroll
        for (int ks = 0; ks < 2; ks++) {
            #pragma unroll
            for (int mt = 0; mt < 4; mt++)
                aAddr[mt][ks] = sbase + ((arow + mt * 16) * ROWE + ks * 16 + acol) * 2;
            #pragma unroll
            for (int nt2 = 0; nt2 < 4; nt2++)
                bAddr[nt2][ks] = sbase + ATERMS * A_B + ((brbase + nt2 * 16) * ROWE + ks * 16 + bcol) * 2;
        }
    }

    float acc[4][8][4];
    #pragma unroll
    for (int mt = 0; mt < 4; mt++)
        #pragma unroll
        for (int nt = 0; nt < 8; nt++)
            #pragma unroll
            for (int k = 0; k < 4; k++) acc[mt][nt][k] = 0.0f;

    const int NIT = K >> 5;

    auto load_stage = [&](int s, int it) {
        uint32_t off = s * STAGE_B;
        const unsigned short* ah = Asrc + it * BK;
        const unsigned short* b0 = Bsrc0 + it * BK;
        const unsigned short* b1 = Bsrc1 + it * BK;
        CPA16(a0_dst + off,      ah);
        CPA16(a0_dst + off + 16, ah + 8);
        if (ATERMS == 2) {
            const unsigned short* al = ah + K;
            CPA16(a1_dst + off,      al);
            CPA16(a1_dst + off + 16, al + 8);
        }
        CPA16(b0_dst + off,      b0);
        CPA16(b0_dst + off + 16, b0 + 8);
        CPA16(b1_dst + off,      b1);
        CPA16(b1_dst + off + 16, b1 + 8);
        if (BSPLIT) {
            const unsigned short* b0l = b0 + K;
            const unsigned short* b1l = b1 + K;
            CPA16(b0_dst + off + B_B,      b0l);
            CPA16(b0_dst + off + B_B + 16, b0l + 8);
            CPA16(b1_dst + off + B_B,      b1l);
            CPA16(b1_dst + off + B_B + 16, b1l + 8);
        }
    };

    #pragma unroll
    for (int s = 0; s < NSTAGES - 1; s++) {
        if (s < NIT) load_stage(s, s);
        CP_COMMIT();
    }

    for (int it = 0; it < NIT; it++) {
        asm volatile("cp.async.wait_group %0;" :: "n"(NSTAGES - 2) : "memory");
        __syncthreads();
        if (it + NSTAGES - 1 < NIT) load_stage((it + NSTAGES - 1) % NSTAGES, it + NSTAGES - 1);
        CP_COMMIT();

        const uint32_t soff = (it % NSTAGES) * STAGE_B;
        #pragma unroll
        for (int ks = 0; ks < 2; ks++) {
            uint32_t af0[4][4], bf[4][4];
            #pragma unroll
            for (int mt = 0; mt < 4; mt++) LDSM4(af0[mt], aAddr[mt][ks] + soff);
            #pragma unroll
            for (int nt2 = 0; nt2 < 4; nt2++) LDSM4(bf[nt2], bAddr[nt2][ks] + soff);
            #pragma unroll
            for (int mt = 0; mt < 4; mt++)
                #pragma unroll
                for (int nt = 0; nt < 8; nt++)
                    MMA16816(acc[mt][nt], af0[mt], bf[nt >> 1][(nt & 1) * 2], bf[nt >> 1][(nt & 1) * 2 + 1]);
            if (ATERMS == 2) {
                uint32_t af1[4][4];
                #pragma unroll
                for (int mt = 0; mt < 4; mt++) LDSM4(af1[mt], aAddr[mt][ks] + soff + A_B);
                #pragma unroll
                for (int mt = 0; mt < 4; mt++)
                    #pragma unroll
                    for (int nt = 0; nt < 8; nt++)
                        MMA16816(acc[mt][nt], af1[mt], bf[nt >> 1][(nt & 1) * 2], bf[nt >> 1][(nt & 1) * 2 + 1]);
            }
            if (BSPLIT) {
                uint32_t bfl[4][4];
                #pragma unroll
                for (int nt2 = 0; nt2 < 4; nt2++) LDSM4(bfl[nt2], bAddr[nt2][ks] + soff + B_B);
                #pragma unroll
                for (int mt = 0; mt < 4; mt++)
                    #pragma unroll
                    for (int nt = 0; nt < 8; nt++)
                        MMA16816(acc[mt][nt], af0[mt], bfl[nt >> 1][(nt & 1) * 2], bfl[nt >> 1][(nt & 1) * 2 + 1]);
            }
        }
    }

    // ---- epilogue: direct from c-fragments ----
    const float* biasE = bias + (size_t)e * bStrideE;
    const int cq = (lane & 3) * 2;
    const int r0 = lane >> 2;
    float b2v[8][2];
    #pragma unroll
    for (int nt = 0; nt < 8; nt++) {
        int n = n0 + wn * 64 + nt * 8 + cq;
        b2v[nt][0] = biasE[n];
        b2v[nt][1] = biasE[n + 1];
    }

    #pragma unroll
    for (int mt = 0; mt < 4; mt++) {
        #pragma unroll
        for (int h = 0; h < 2; h++) {
            int row = m0 + wm * 64 + mt * 16 + r0 + h * 8;
            if (row >= M) continue;
            size_t erow = (size_t)e * CAP + row;
            float  sc = 1.0f;
            size_t orow = 0;
            if (flags & FLAG_DEST) {
                sc   = scales[erow];
                orow = (size_t)dests[erow];
            } else if (flags & FLAG_OCAP) {
                orow = erow;
            } else {
                orow = (size_t)row;
            }
            #pragma unroll
            for (int nt = 0; nt < 8; nt++) {
                int n = n0 + wn * 64 + nt * 8 + cq;
                float v0 = acc[mt][nt][h * 2]     + b2v[nt][0];
                float v1 = acc[mt][nt][h * 2 + 1] + b2v[nt][1];
                if (flags & FLAG_ADD) {
                    float2 ad = *(const float2*)(addt + erow * N + n);
                    v0 += ad.x; v1 += ad.y;
                }
                if (flags & FLAG_RELU) { v0 = fmaxf(v0, 0.0f); v1 = fmaxf(v1, 0.0f); }
                if (flags & FLAG_SPLIT) {
                    // single fp16 plane (hi only)
                    *(__half2*)((__half*)outS + erow * N + n) =
                        __halves2half2(__float2half_rn(v0), __float2half_rn(v1));
                } else {
                    float2 o2; o2.x = v0 * sc; o2.y = v1 * sc;
                    *(float2*)(outF + orow * N + n) = o2;
                }
            }
        }
    }
}

// ---------------- conversion kernels ----------------
// x [B,K] fp32 -> xh [B,2K] fp16: [hi | lo]
__global__ __launch_bounds__(256) void convert_x(const float* __restrict__ x,
                                                 unsigned short* __restrict__ xh,
                                                 int K, size_t total)
{
    size_t idx = (size_t)blockIdx.x * blockDim.x + threadIdx.x;
    if (idx >= total) return;
    size_t m = idx / K;
    int    k = (int)(idx % K);
    float v = x[idx];
    __half hi = __float2half_rn(v);
    __half lo = __float2half_rn(v - __half2float(hi));
    __half* o = (__half*)(xh + m * (size_t)(2 * K));
    o[k]     = hi;
    o[K + k] = lo;
}

// W [E,K,N] fp32 -> Wt [E,N,K] fp16 (single) or [E,N,2K] split [hi|lo], transposed
__global__ __launch_bounds__(256) void convert_w(const float* __restrict__ W,
                                                 unsigned short* __restrict__ Wt,
                                                 int K, int N, int split)
{
    const int e = blockIdx.z;
    __shared__ float t[32][33];
    const int n0 = blockIdx.x * 32;
    const int k0 = blockIdx.y * 32;
    const float* We = W + (size_t)e * K * N;
    #pragma unroll
    for (int j = 0; j < 4; j++) {
        int k = k0 + threadIdx.y + j * 8;
        t[threadIdx.y + j * 8][threadIdx.x] = We[(size_t)k * N + n0 + threadIdx.x];
    }
    __syncthreads();
    const int rowlen = split ? 2 * K : K;
    unsigned short* Wte = Wt + (size_t)e * N * (size_t)rowlen;
    #pragma unroll
    for (int j = 0; j < 4; j++) {
        int n = n0 + threadIdx.y + j * 8;
        int k = k0 + threadIdx.x;
        float v = t[threadIdx.x][threadIdx.y + j * 8];
        __half hi = __float2half_rn(v);
        __half* o = (__half*)(Wte + (size_t)n * (size_t)rowlen);
        o[k] = hi;
        if (split) o[K + k] = __float2half_rn(v - __half2float(hi));
    }
}

// ---------------- gating logits: one warp per token, N=8 ----------------
__global__ __launch_bounds__(256) void logits_kernel(
    const float* __restrict__ h, const float* __restrict__ gw2,
    const float* __restrict__ gb2, float* __restrict__ logits)
{
    int warp = (blockIdx.x * blockDim.x + threadIdx.x) >> 5;
    int lane = threadIdx.x & 31;
    if (warp >= B_TOK) return;
    const float4* hrow = (const float4*)(h + (size_t)warp * GHID);
    float acc[NE];
    #pragma unroll
    for (int e = 0; e < NE; e++) acc[e] = 0.0f;
    for (int i = lane; i < GHID / 4; i += 32) {
        float4 hv = hrow[i];
        const float* g = gw2 + (size_t)(i * 4) * NE;
        #pragma unroll
        for (int e = 0; e < NE; e++)
            acc[e] += hv.x * g[e] + hv.y * g[NE + e] + hv.z * g[2 * NE + e] + hv.w * g[3 * NE + e];
    }
    #pragma unroll
    for (int e = 0; e < NE; e++)
        #pragma unroll
        for (int off = 16; off > 0; off >>= 1)
            acc[e] += __shfl_xor_sync(0xFFFFFFFFu, acc[e], off);
    if (lane == 0) {
        #pragma unroll
        for (int e = 0; e < NE; e++)
            logits[(size_t)warp * NE + e] = acc[e] + gb2[e];
    }
}

// ---------------- routing ----------------
__global__ void init_kernel() {
    if (threadIdx.x < NE) g_counts[threadIdx.x] = 0;
}

__global__ __launch_bounds__(256) void route_kernel() {
    int t = blockIdx.x * blockDim.x + threadIdx.x;
    if (t >= B_TOK) return;
    float v[NE];
    #pragma unroll
    for (int e = 0; e < NE; e++) v[e] = g_logits[(size_t)t * NE + e];
    int i0 = 0;
    #pragma unroll
    for (int e = 1; e < NE; e++) if (v[e] > v[i0]) i0 = e;
    int i1 = (i0 == 0) ? 1 : 0;
    #pragma unroll
    for (int e = 0; e < NE; e++) if (e != i0 && v[e] > v[i1]) i1 = e;
    float b = __expf(v[i1] - v[i0]);
    float s = 1.0f + b;
    float w0 = 1.0f / s;
    float w1 = b / s;

    int p0 = atomicAdd(&g_counts[i0], 1);
    g_tokens[i0 * CAP + p0] = t;
    g_wts[i0 * CAP + p0]    = w0;
    g_dests[i0 * CAP + p0]  = 2 * t;

    int p1 = atomicAdd(&g_counts[i1], 1);
    g_tokens[i1 * CAP + p1] = t;
    g_wts[i1 * CAP + p1]    = w1;
    g_dests[i1 * CAP + p1]  = 2 * t + 1;
}

// ---------------- final reduce ----------------
__global__ __launch_bounds__(256) void reduce_kernel(float* __restrict__ out) {
    size_t idx = (size_t)blockIdx.x * blockDim.x + threadIdx.x;
    const size_t total = (size_t)B_TOK * DOUT / 4;
    if (idx >= total) return;
    size_t t  = idx / (DOUT / 4);
    size_t c4 = idx % (DOUT / 4);
    const float4* e4 = (const float4*)g_eout;
    float4 a = e4[(2 * t) * (DOUT / 4) + c4];
    float4 b = e4[(2 * t + 1) * (DOUT / 4) + c4];
    float4 r;
    r.x = a.x + b.x; r.y = a.y + b.y; r.z = a.z + b.z; r.w = a.w + b.w;
    ((float4*)out)[idx] = r;
}

// ---------------- host ----------------
extern "C" void kernel_launch(void* const* d_in, const int* in_sizes, int n_in,
                              void* d_out, int out_size) {
    const float* x   = (const float*)d_in[0];
    const float* w1  = (const float*)d_in[1];
    const float* b1  = (const float*)d_in[2];
    const float* w2  = (const float*)d_in[3];
    const float* b2  = (const float*)d_in[4];
    const float* w3  = (const float*)d_in[5];
    const float* b3  = (const float*)d_in[6];
    const float* wp  = (const float*)d_in[7];
    const float* bp  = (const float*)d_in[8];
    const float* gw1 = (const float*)d_in[9];
    const float* gb1 = (const float*)d_in[10];
    const float* gw2 = (const float*)d_in[11];
    const float* gb2 = (const float*)d_in[12];
    float* out = (float*)d_out;

    unsigned short *p_xh, *p_w1h, *p_wph, *p_w2h, *p_w3h, *p_gwh, *p_hs, *p_os;
    float *p_p, *p_hidden, *p_logits, *p_wts, *p_eout;
    int *p_counts, *p_tokens, *p_dests;
    cudaGetSymbolAddress((void**)&p_xh,     g_xh);
    cudaGetSymbolAddress((void**)&p_w1h,    g_w1h);
    cudaGetSymbolAddress((void**)&p_wph,    g_wph);
    cudaGetSymbolAddress((void**)&p_w2h,    g_w2h);
    cudaGetSymbolAddress((void**)&p_w3h,    g_w3h);
    cudaGetSymbolAddress((void**)&p_gwh,    g_gwh);
    cudaGetSymbolAddress((void**)&p_hs,     g_hs);
    cudaGetSymbolAddress((void**)&p_os,     g_os);
    cudaGetSymbolAddress((void**)&p_p,      g_p);
    cudaGetSymbolAddress((void**)&p_hidden, g_hidden);
    cudaGetSymbolAddress((void**)&p_logits, g_logits);
    cudaGetSymbolAddress((void**)&p_wts,    g_wts);
    cudaGetSymbolAddress((void**)&p_eout,   g_eout);
    cudaGetSymbolAddress((void**)&p_counts, g_counts);
    cudaGetSymbolAddress((void**)&p_tokens, g_tokens);
    cudaGetSymbolAddress((void**)&p_dests,  g_dests);

    cudaFuncSetAttribute((const void*)mma_gemm<1,0,NSTAGES_E>,
                         cudaFuncAttributeMaxDynamicSharedMemorySize, DYN_SMEM_E);
    cudaFuncSetAttribute((const void*)mma_gemm<2,1,3>,
                         cudaFuncAttributeMaxDynamicSharedMemorySize, DYN_SMEM_G);

    // conversions
    {
        size_t total = (size_t)B_TOK * DIN;
        convert_x<<<(unsigned)((total + 255) / 256), 256>>>(x, p_xh, DIN, total);
    }
    convert_w<<<dim3(HID / 32, DIN / 32, NE),  dim3(32, 8)>>>(w1,  p_w1h, DIN, HID,  0);
    convert_w<<<dim3(HID / 32, DIN / 32, NE),  dim3(32, 8)>>>(wp,  p_wph, DIN, HID,  0);
    convert_w<<<dim3(HID / 32, HID / 32, NE),  dim3(32, 8)>>>(w2,  p_w2h, HID, HID,  0);
    convert_w<<<dim3(DOUT / 32, HID / 32, NE), dim3(32, 8)>>>(w3,  p_w3h, HID, DOUT, 0);
    convert_w<<<dim3(GHID / 32, DIN / 32, 1),  dim3(32, 8)>>>(gw1, p_gwh, DIN, GHID, 1);

    // G1: gating hidden = relu(x @ gw1 + gb1), 3-term (err ~2^-22, exact routing)
    mma_gemm<2,1,3><<<dim3(GHID / BN, B_TOK / BM, 1), 256, DYN_SMEM_G>>>(
        p_xh, 2 * DIN, 0, nullptr, p_gwh, 0, 2 * DIN, gb1, 0, nullptr,
        p_hidden, nullptr, nullptr, nullptr, nullptr, B_TOK,
        DIN, GHID, FLAG_RELU);

    // G2 + routing
    logits_kernel<<<B_TOK / 8, 256>>>(p_hidden, gw2, gb2, p_logits);
    init_kernel<<<1, 32>>>();
    route_kernel<<<B_TOK / 256, 256>>>();

    // L1: h = relu(x_g @ w1 + b1) -> fp16
    mma_gemm<1,0,NSTAGES_E><<<dim3(HID / BN, CAP / BM, NE), 256, DYN_SMEM_E>>>(
        p_xh, 2 * DIN, 0, p_tokens, p_w1h, (size_t)HID * DIN, DIN, b1, HID, nullptr,
        nullptr, p_hs, nullptr, nullptr, p_counts, 0,
        DIN, HID, FLAG_RELU | FLAG_SPLIT);

    // L2: p = x_g @ wp + bp  (fp32, capacity layout)
    mma_gemm<1,0,NSTAGES_E><<<dim3(HID / BN, CAP / BM, NE), 256, DYN_SMEM_E>>>(
        p_xh, 2 * DIN, 0, p_tokens, p_wph, (size_t)HID * DIN, DIN, bp, HID, nullptr,
        p_p, nullptr, nullptr, nullptr, p_counts, 0,
        DIN, HID, FLAG_OCAP);

    // L3: o = relu(h @ w2 + b2 + p) -> fp16
    mma_gemm<1,0,NSTAGES_E><<<dim3(HID / BN, CAP / BM, NE), 256, DYN_SMEM_E>>>(
        p_hs, HID, 1, nullptr, p_w2h, (size_t)HID * HID, HID, b2, HID, p_p,
        nullptr, p_os, nullptr, nullptr, p_counts, 0,
        HID, HID, FLAG_RELU | FLAG_ADD | FLAG_SPLIT);

    // L4: eout[dest] = (o @ w3 + b3) * gate_w
    mma_gemm<1,0,NSTAGES_E><<<dim3(DOUT / BN, CAP / BM, NE), 256, DYN_SMEM_E>>>(
        p_os, HID, 1, nullptr, p_w3h, (size_t)DOUT * HID, HID, b3, DOUT, nullptr,
        p_eout, nullptr, p_wts, p_dests, p_counts, 0,
        HID, DOUT, FLAG_DEST);

    // reduce
    size_t total4 = (size_t)B_TOK * DOUT / 4;
    reduce_kernel<<<(unsigned)((total4 + 255) / 256), 256>>>(out);
}

// round 8
// speedup vs baseline: 3.0351x; 1.2624x over previous
#include <cuda_runtime.h>
#include <cuda_fp16.h>
#include <cstdint>

// ---------------- problem constants ----------------
#define B_TOK 8192
#define DIN   1024
#define HID   2048
#define DOUT  1024
#define NE    8
#define GHID  1024
#define CAP   8192

#define FLAG_RELU  1
#define FLAG_ADD   2
#define FLAG_SPLIT 4
#define FLAG_DEST  8
#define FLAG_OCAP  16

// ---------------- tile geometry ----------------
#define BM 128
#define BN 256
#define BK 32
#define ROWE 40                   // padded row stride: 80B (32 fp16 + 16B pad)
#define A_B   10240               // A block bytes: 128 rows x 80B
#define B_B   20480               // B block bytes: 256 rows x 80B
#define A_EL  5120                // A block elems
#define B_EL  10240               // B block elems

// tiled layout block counts
#define XT_TERM   ((size_t)(B_TOK/128) * (DIN/32) * A_EL)     // one term of tiled x
#define GWT_TERM  ((size_t)(GHID/256) * (DIN/32) * B_EL)      // one term of tiled gw1

// ---------------- scratch (static device globals; 128B aligned for bulk) ----------------
__device__ __align__(128) unsigned short g_xflat[(size_t)B_TOK*DIN];            // x hi, flat (gather src)
__device__ __align__(128) unsigned short g_xt  [2*XT_TERM];                     // x tiled [hi|lo] (G1)
__device__ __align__(128) unsigned short g_gwt [2*GWT_TERM];                    // gw1^T tiled [hi|lo]
__device__ __align__(128) unsigned short g_w1t [(size_t)NE*(HID/256)*(DIN/32)*B_EL];
__device__ __align__(128) unsigned short g_wpt [(size_t)NE*(HID/256)*(DIN/32)*B_EL];
__device__ __align__(128) unsigned short g_w2t [(size_t)NE*(HID/256)*(HID/32)*B_EL];
__device__ __align__(128) unsigned short g_w3t [(size_t)NE*(DOUT/256)*(HID/32)*B_EL];
__device__ __align__(128) unsigned short g_hst [(size_t)NE*(CAP/128)*(HID/32)*A_EL];  // h tiled (L1 out)
__device__ __align__(128) unsigned short g_ost [(size_t)NE*(CAP/128)*(HID/32)*A_EL];  // o tiled (L3 out)
__device__ float g_p     [(size_t)NE*CAP*HID];              // projection (L2 out, flat fp32)
__device__ float g_hidden[(size_t)B_TOK*GHID];
__device__ float g_logits[(size_t)B_TOK*NE];
__device__ int   g_counts[NE];
__device__ int   g_tokens[(size_t)NE*CAP];
__device__ float g_wts   [(size_t)NE*CAP];
__device__ int   g_dests [(size_t)NE*CAP];
__device__ float g_eout  [(size_t)B_TOK*2*DOUT];

// ---------------- PTX helpers (sm_90 baseline features only) ----------------
__device__ __forceinline__ uint32_t smem_u32(const void* p) {
    uint32_t a;
    asm("{ .reg .u64 t; cvta.to.shared.u64 t, %1; cvt.u32.u64 %0, t; }" : "=r"(a) : "l"(p));
    return a;
}
#define CPA16(dst, src) \
    asm volatile("cp.async.cg.shared.global [%0], [%1], 16;" :: "r"(dst), "l"(src) : "memory")
#define CP_COMMIT() asm volatile("cp.async.commit_group;" ::: "memory")
#define BULK_G2S(dst, src, nbytes, mbar) \
    asm volatile("cp.async.bulk.shared::cluster.global.mbarrier::complete_tx::bytes [%0], [%1], %2, [%3];" \
        :: "r"(dst), "l"(src), "r"(nbytes), "r"(mbar) : "memory")
#define MBAR_INIT(addr, cnt) \
    asm volatile("mbarrier.init.shared.b64 [%0], %1;" :: "r"(addr), "r"(cnt) : "memory")
#define MBAR_EXPECT_TX(addr, tx) \
    asm volatile("mbarrier.arrive.expect_tx.shared.b64 _, [%0], %1;" :: "r"(addr), "r"(tx) : "memory")
__device__ __forceinline__ void mbar_wait(uint32_t addr, uint32_t parity) {
    asm volatile("{\n\t.reg .pred P;\n"
        "LW%=:\n\tmbarrier.try_wait.parity.acquire.cta.shared::cta.b64 P, [%0], %1, 0x989680;\n"
        "\t@!P bra LW%=;\n\t}" :: "r"(addr), "r"(parity) : "memory");
}
#define LDSM4(r, addr) \
    asm volatile("ldmatrix.sync.aligned.m8n8.x4.shared.b16 {%0,%1,%2,%3}, [%4];" \
        : "=r"((r)[0]), "=r"((r)[1]), "=r"((r)[2]), "=r"((r)[3]) : "r"(addr))
#define MMA16816(d, a, b0, b1) \
    asm volatile("mma.sync.aligned.m16n8k16.row.col.f32.f16.f16.f32 " \
        "{%0,%1,%2,%3},{%4,%5,%6,%7},{%8,%9},{%0,%1,%2,%3};" \
        : "+f"((d)[0]), "+f"((d)[1]), "+f"((d)[2]), "+f"((d)[3]) \
        : "r"((a)[0]), "r"((a)[1]), "r"((a)[2]), "r"((a)[3]), "r"(b0), "r"(b1))

// ---------------- HMMA GEMM: tile 128x256x32, bulk-loaded tiled operands ----------------
// Stage smem = [A terms][B terms], each block an exact image of the tiled global layout.
// AGATHER=1: A gathered per-row from flat layout via cp.async (L1/L2). Else bulk tiled A.
// Compute: acc += A0*B0 (+ A1*B0 if ATERMS==2) (+ A0*B1 if BTERMS==2).
template<int AGATHER, int ATERMS, int BTERMS, int NSTAGES>
__global__ __launch_bounds__(256) void mma_gemm(
    const unsigned short* __restrict__ Atiled, size_t aTermOff, int aMtPerE,
    const unsigned short* __restrict__ Aflat, int aRL, const int* __restrict__ gather,
    const unsigned short* __restrict__ Btiled, size_t bTermOff,
    const float* __restrict__ bias, int bStrideE,
    const float* __restrict__ addt,
    float* __restrict__ outF, unsigned short* __restrict__ outS,
    const float* __restrict__ scales, const int* __restrict__ dests,
    const int* __restrict__ counts, int Mfixed,
    int K, int N, int flags)
{
    constexpr uint32_t STAGE_B = ATERMS * A_B + BTERMS * B_B;
    constexpr uint32_t TXB = (AGATHER ? 0 : ATERMS * A_B) + BTERMS * B_B;

    const int e  = blockIdx.z;
    const int M  = counts ? counts[e] : Mfixed;
    const int m0 = blockIdx.y * BM;
    if (m0 >= M) return;
    const int n0 = blockIdx.x * BN;

    const int KPC = K >> 5;
    const int NT  = N >> 8;

    extern __shared__ char smem[];
    const uint32_t sbase = smem_u32(smem);
    const uint32_t mbar0 = sbase + NSTAGES * STAGE_B;

    const int tid  = threadIdx.x;
    const int wid  = tid >> 5;
    const int lane = tid & 31;

    // tiled block bases
    const size_t bBlk0 = ((size_t)(e * NT + blockIdx.x) * KPC) * B_EL;
    const size_t aBlk0 = ((size_t)(e * aMtPerE + blockIdx.y) * KPC) * A_EL;

    // gather-A mapping (2 threads per row, 2x16B each)
    const int lrow   = tid >> 1;
    const int lchunk = (tid & 1) * 2;
    const unsigned short* AsrcG = nullptr;
    if (AGATHER) {
        int r = m0 + lrow;
        int row = gather[(size_t)e * CAP + r];
        AsrcG = Aflat + (size_t)row * aRL + lchunk * 8;
    }
    const uint32_t ag_dst = sbase + lrow * 80 + lchunk * 16;

    if (tid == 0) {
        #pragma unroll
        for (int s = 0; s < NSTAGES; s++) MBAR_INIT(mbar0 + s * 8, 1);
    }
    __syncthreads();

    // ---- fragment smem addresses: warp tile 64x64 ----
    const int wm = wid & 1;
    const int wn = wid >> 1;
    uint32_t aAddr[4][2], bAddr[4][2];
    {
        int arow = wm * 64 + (lane & 15);
        int acol = (lane >> 4) * 8;
        int brbase = wn * 64 + ((lane >> 4) * 8) + (lane & 7);
        int bcol = ((lane >> 3) & 1) * 8;
        #pragma unroll
        for (int ks = 0; ks < 2; ks++) {
            #pragma unroll
            for (int mt = 0; mt < 4; mt++)
                aAddr[mt][ks] = sbase + ((arow + mt * 16) * ROWE + ks * 16 + acol) * 2;
            #pragma unroll
            for (int nt2 = 0; nt2 < 4; nt2++)
                bAddr[nt2][ks] = sbase + ATERMS * A_B + ((brbase + nt2 * 16) * ROWE + ks * 16 + bcol) * 2;
        }
    }

    float acc[4][8][4];
    #pragma unroll
    for (int mt = 0; mt < 4; mt++)
        #pragma unroll
        for (int nt = 0; nt < 8; nt++)
            #pragma unroll
            for (int k = 0; k < 4; k++) acc[mt][nt][k] = 0.0f;

    const int NIT = KPC;

    auto load_stage = [&](int s, int it) {
        const uint32_t stg = sbase + s * STAGE_B;
        if (tid == 0) {
            const uint32_t mb = mbar0 + s * 8;
            MBAR_EXPECT_TX(mb, TXB);
            BULK_G2S(stg + ATERMS * A_B, Btiled + bBlk0 + (size_t)it * B_EL, B_B, mb);
            if (BTERMS == 2)
                BULK_G2S(stg + ATERMS * A_B + B_B, Btiled + bTermOff + bBlk0 + (size_t)it * B_EL, B_B, mb);
            if (!AGATHER) {
                BULK_G2S(stg, Atiled + aBlk0 + (size_t)it * A_EL, A_B, mb);
                if (ATERMS == 2)
                    BULK_G2S(stg + A_B, Atiled + aTermOff + aBlk0 + (size_t)it * A_EL, A_B, mb);
            }
        }
        if (AGATHER) {
            const unsigned short* ah = AsrcG + it * BK;
            CPA16(ag_dst + s * STAGE_B,      ah);
            CPA16(ag_dst + s * STAGE_B + 16, ah + 8);
            CP_COMMIT();
        }
    };

    #pragma unroll
    for (int s = 0; s < NSTAGES - 1; s++)
        if (s < NIT) load_stage(s, s);

    for (int it = 0; it < NIT; it++) {
        if (AGATHER)
            asm volatile("cp.async.wait_group %0;" :: "n"(NSTAGES - 2) : "memory");
        mbar_wait(mbar0 + (it % NSTAGES) * 8, (it / NSTAGES) & 1);
        __syncthreads();
        if (it + NSTAGES - 1 < NIT) load_stage((it + NSTAGES - 1) % NSTAGES, it + NSTAGES - 1);

        const uint32_t soff = (it % NSTAGES) * STAGE_B;
        #pragma unroll
        for (int ks = 0; ks < 2; ks++) {
            uint32_t af0[4][4], bf[4][4];
            #pragma unroll
            for (int mt = 0; mt < 4; mt++) LDSM4(af0[mt], aAddr[mt][ks] + soff);
            #pragma unroll
            for (int nt2 = 0; nt2 < 4; nt2++) LDSM4(bf[nt2], bAddr[nt2][ks] + soff);
            #pragma unroll
            for (int mt = 0; mt < 4; mt++)
                #pragma unroll
                for (int nt = 0; nt < 8; nt++)
                    MMA16816(acc[mt][nt], af0[mt], bf[nt >> 1][(nt & 1) * 2], bf[nt >> 1][(nt & 1) * 2 + 1]);
            if (ATERMS == 2) {
                uint32_t af1[4][4];
                #pragma unroll
                for (int mt = 0; mt < 4; mt++) LDSM4(af1[mt], aAddr[mt][ks] + soff + A_B);
                #pragma unroll
                for (int mt = 0; mt < 4; mt++)
                    #pragma unroll
                    for (int nt = 0; nt < 8; nt++)
                        MMA16816(acc[mt][nt], af1[mt], bf[nt >> 1][(nt & 1) * 2], bf[nt >> 1][(nt & 1) * 2 + 1]);
            }
            if (BTERMS == 2) {
                uint32_t bfl[4][4];
                #pragma unroll
                for (int nt2 = 0; nt2 < 4; nt2++) LDSM4(bfl[nt2], bAddr[nt2][ks] + soff + B_B);
                #pragma unroll
                for (int mt = 0; mt < 4; mt++)
                    #pragma unroll
                    for (int nt = 0; nt < 8; nt++)
                        MMA16816(acc[mt][nt], af0[mt], bfl[nt >> 1][(nt & 1) * 2], bfl[nt >> 1][(nt & 1) * 2 + 1]);
            }
        }
    }

    // ---- epilogue: direct from c-fragments ----
    const float* biasE = bias + (size_t)e * bStrideE;
    const int cq = (lane & 3) * 2;
    const int r0 = lane >> 2;
    float b2v[8][2];
    #pragma unroll
    for (int nt = 0; nt < 8; nt++) {
        int n = n0 + wn * 64 + nt * 8 + cq;
        b2v[nt][0] = biasE[n];
        b2v[nt][1] = biasE[n + 1];
    }

    #pragma unroll
    for (int mt = 0; mt < 4; mt++) {
        #pragma unroll
        for (int h = 0; h < 2; h++) {
            int row = m0 + wm * 64 + mt * 16 + r0 + h * 8;
            if (row >= M) continue;
            size_t erow = (size_t)e * CAP + row;
            float  sc = 1.0f;
            size_t orow = 0;
            if (flags & FLAG_DEST) {
                sc   = scales[erow];
                orow = (size_t)dests[erow];
            } else if (flags & FLAG_OCAP) {
                orow = erow;
            } else {
                orow = (size_t)row;
            }
            #pragma unroll
            for (int nt = 0; nt < 8; nt++) {
                int n = n0 + wn * 64 + nt * 8 + cq;
                float v0 = acc[mt][nt][h * 2]     + b2v[nt][0];
                float v1 = acc[mt][nt][h * 2 + 1] + b2v[nt][1];
                if (flags & FLAG_ADD) {
                    float2 ad = *(const float2*)(addt + erow * N + n);
                    v0 += ad.x; v1 += ad.y;
                }
                if (flags & FLAG_RELU) { v0 = fmaxf(v0, 0.0f); v1 = fmaxf(v1, 0.0f); }
                if (flags & FLAG_SPLIT) {
                    // tiled fp16 write: block image matches next layer's bulk-A layout
                    size_t blk = ((erow >> 7) * (size_t)(N >> 5) + (size_t)(n >> 5)) * A_EL;
                    *(__half2*)((__half*)outS + blk + (erow & 127) * 40 + (n & 31)) =
                        __halves2half2(__float2half_rn(v0), __float2half_rn(v1));
                } else {
                    float2 o2; o2.x = v0 * sc; o2.y = v1 * sc;
                    *(float2*)(outF + orow * N + n) = o2;
                }
            }
        }
    }
}

// ---------------- conversion kernels ----------------
// x: flat hi [B,K] fp16 + tiled [hi|lo] images
__global__ __launch_bounds__(256) void convert_x(const float* __restrict__ x,
                                                 unsigned short* __restrict__ xflat,
                                                 unsigned short* __restrict__ xt,
                                                 int K, size_t total)
{
    size_t idx = (size_t)blockIdx.x * blockDim.x + threadIdx.x;
    if (idx >= total) return;
    size_t t = idx / K;
    int    k = (int)(idx % K);
    float v = x[idx];
    __half hi = __float2half_rn(v);
    __half lo = __float2half_rn(v - __half2float(hi));
    ((__half*)xflat)[idx] = hi;
    size_t blk = ((t >> 7) * (size_t)(K >> 5) + (size_t)(k >> 5)) * A_EL
               + (t & 127) * 40 + (k & 31);
    ((__half*)xt)[blk]           = hi;
    ((__half*)xt)[XT_TERM + blk] = lo;
}

// W [E,K,N] fp32 -> tiled transposed fp16 blocks (hi; optionally +lo at termOff)
__global__ __launch_bounds__(256) void convert_w(const float* __restrict__ W,
                                                 unsigned short* __restrict__ Wt,
                                                 int K, int N, size_t termOff)
{
    const int e = blockIdx.z;
    __shared__ float t[32][33];
    const int n0 = blockIdx.x * 32;
    const int k0 = blockIdx.y * 32;
    const float* We = W + (size_t)e * K * N;
    #pragma unroll
    for (int j = 0; j < 4; j++) {
        int k = k0 + threadIdx.y + j * 8;
        t[threadIdx.y + j * 8][threadIdx.x] = We[(size_t)k * N + n0 + threadIdx.x];
    }
    __syncthreads();
    const size_t blkBase = (((size_t)e * (N >> 8) + (size_t)(n0 >> 8)) * (K >> 5) + (size_t)(k0 >> 5)) * B_EL;
    #pragma unroll
    for (int j = 0; j < 4; j++) {
        int n = n0 + threadIdx.y + j * 8;
        int k = k0 + threadIdx.x;
        float v = t[threadIdx.x][threadIdx.y + j * 8];
        __half hi = __float2half_rn(v);
        size_t off = blkBase + (n & 255) * 40 + (k & 31);
        ((__half*)Wt)[off] = hi;
        if (termOff) ((__half*)Wt)[termOff + off] = __float2half_rn(v - __half2float(hi));
    }
}

// ---------------- gating logits: one warp per token, N=8 ----------------
__global__ __launch_bounds__(256) void logits_kernel(
    const float* __restrict__ h, const float* __restrict__ gw2,
    const float* __restrict__ gb2, float* __restrict__ logits)
{
    int warp = (blockIdx.x * blockDim.x + threadIdx.x) >> 5;
    int lane = threadIdx.x & 31;
    if (warp >= B_TOK) return;
    const float4* hrow = (const float4*)(h + (size_t)warp * GHID);
    float acc[NE];
    #pragma unroll
    for (int e = 0; e < NE; e++) acc[e] = 0.0f;
    for (int i = lane; i < GHID / 4; i += 32) {
        float4 hv = hrow[i];
        const float* g = gw2 + (size_t)(i * 4) * NE;
        #pragma unroll
        for (int e = 0; e < NE; e++)
            acc[e] += hv.x * g[e] + hv.y * g[NE + e] + hv.z * g[2 * NE + e] + hv.w * g[3 * NE + e];
    }
    #pragma unroll
    for (int e = 0; e < NE; e++)
        #pragma unroll
        for (int off = 16; off > 0; off >>= 1)
            acc[e] += __shfl_xor_sync(0xFFFFFFFFu, acc[e], off);
    if (lane == 0) {
        #pragma unroll
        for (int e = 0; e < NE; e++)
            logits[(size_t)warp * NE + e] = acc[e] + gb2[e];
    }
}

// ---------------- routing ----------------
__global__ void init_kernel() {
    if (threadIdx.x < NE) g_counts[threadIdx.x] = 0;
}

__global__ __launch_bounds__(256) void route_kernel() {
    int t = blockIdx.x * blockDim.x + threadIdx.x;
    if (t >= B_TOK) return;
    float v[NE];
    #pragma unroll
    for (int e = 0; e < NE; e++) v[e] = g_logits[(size_t)t * NE + e];
    int i0 = 0;
    #pragma unroll
    for (int e = 1; e < NE; e++) if (v[e] > v[i0]) i0 = e;
    int i1 = (i0 == 0) ? 1 : 0;
    #pragma unroll
    for (int e = 0; e < NE; e++) if (e != i0 && v[e] > v[i1]) i1 = e;
    float b = __expf(v[i1] - v[i0]);
    float s = 1.0f + b;
    float w0 = 1.0f / s;
    float w1 = b / s;

    int p0 = atomicAdd(&g_counts[i0], 1);
    g_tokens[i0 * CAP + p0] = t;
    g_wts[i0 * CAP + p0]    = w0;
    g_dests[i0 * CAP + p0]  = 2 * t;

    int p1 = atomicAdd(&g_counts[i1], 1);
    g_tokens[i1 * CAP + p1] = t;
    g_wts[i1 * CAP + p1]    = w1;
    g_dests[i1 * CAP + p1]  = 2 * t + 1;
}

// ---------------- final reduce ----------------
__global__ __launch_bounds__(256) void reduce_kernel(float* __restrict__ out) {
    size_t idx = (size_t)blockIdx.x * blockDim.x + threadIdx.x;
    const size_t total = (size_t)B_TOK * DOUT / 4;
    if (idx >= total) return;
    size_t t  = idx / (DOUT / 4);
    size_t c4 = idx % (DOUT / 4);
    const float4* e4 = (const float4*)g_eout;
    float4 a = e4[(2 * t) * (DOUT / 4) + c4];
    float4 b = e4[(2 * t + 1) * (DOUT / 4) + c4];
    float4 r;
    r.x = a.x + b.x; r.y = a.y + b.y; r.z = a.z + b.z; r.w = a.w + b.w;
    ((float4*)out)[idx] = r;
}

// ---------------- host ----------------
#define NST_E 7
#define DSM_E (NST_E * (1 * A_B + 1 * B_B) + 64)    // 215104
#define DSM_G (3 * (2 * A_B + 2 * B_B) + 64)        // 184384

extern "C" void kernel_launch(void* const* d_in, const int* in_sizes, int n_in,
                              void* d_out, int out_size) {
    const float* x   = (const float*)d_in[0];
    const float* w1  = (const float*)d_in[1];
    const float* b1  = (const float*)d_in[2];
    const float* w2  = (const float*)d_in[3];
    const float* b2  = (const float*)d_in[4];
    const float* w3  = (const float*)d_in[5];
    const float* b3  = (const float*)d_in[6];
    const float* wp  = (const float*)d_in[7];
    const float* bp  = (const float*)d_in[8];
    const float* gw1 = (const float*)d_in[9];
    const float* gb1 = (const float*)d_in[10];
    const float* gw2 = (const float*)d_in[11];
    const float* gb2 = (const float*)d_in[12];
    float* out = (float*)d_out;

    unsigned short *p_xflat, *p_xt, *p_gwt, *p_w1t, *p_wpt, *p_w2t, *p_w3t, *p_hst, *p_ost;
    float *p_p, *p_hidden, *p_logits, *p_wts, *p_eout;
    int *p_counts, *p_tokens, *p_dests;
    cudaGetSymbolAddress((void**)&p_xflat,  g_xflat);
    cudaGetSymbolAddress((void**)&p_xt,     g_xt);
    cudaGetSymbolAddress((void**)&p_gwt,    g_gwt);
    cudaGetSymbolAddress((void**)&p_w1t,    g_w1t);
    cudaGetSymbolAddress((void**)&p_wpt,    g_wpt);
    cudaGetSymbolAddress((void**)&p_w2t,    g_w2t);
    cudaGetSymbolAddress((void**)&p_w3t,    g_w3t);
    cudaGetSymbolAddress((void**)&p_hst,    g_hst);
    cudaGetSymbolAddress((void**)&p_ost,    g_ost);
    cudaGetSymbolAddress((void**)&p_p,      g_p);
    cudaGetSymbolAddress((void**)&p_hidden, g_hidden);
    cudaGetSymbolAddress((void**)&p_logits, g_logits);
    cudaGetSymbolAddress((void**)&p_wts,    g_wts);
    cudaGetSymbolAddress((void**)&p_eout,   g_eout);
    cudaGetSymbolAddress((void**)&p_counts, g_counts);
    cudaGetSymbolAddress((void**)&p_tokens, g_tokens);
    cudaGetSymbolAddress((void**)&p_dests,  g_dests);

    cudaFuncSetAttribute((const void*)mma_gemm<1,1,1,NST_E>,
                         cudaFuncAttributeMaxDynamicSharedMemorySize, DSM_E);
    cudaFuncSetAttribute((const void*)mma_gemm<0,1,1,NST_E>,
                         cudaFuncAttributeMaxDynamicSharedMemorySize, DSM_E);
    cudaFuncSetAttribute((const void*)mma_gemm<0,2,2,3>,
                         cudaFuncAttributeMaxDynamicSharedMemorySize, DSM_G);

    // conversions (tiled layouts)
    {
        size_t total = (size_t)B_TOK * DIN;
        convert_x<<<(unsigned)((total + 255) / 256), 256>>>(x, p_xflat, p_xt, DIN, total);
    }
    convert_w<<<dim3(HID / 32, DIN / 32, NE),  dim3(32, 8)>>>(w1,  p_w1t, DIN, HID,  0);
    convert_w<<<dim3(HID / 32, DIN / 32, NE),  dim3(32, 8)>>>(wp,  p_wpt, DIN, HID,  0);
    convert_w<<<dim3(HID / 32, HID / 32, NE),  dim3(32, 8)>>>(w2,  p_w2t, HID, HID,  0);
    convert_w<<<dim3(DOUT / 32, HID / 32, NE), dim3(32, 8)>>>(w3,  p_w3t, HID, DOUT, 0);
    convert_w<<<dim3(GHID / 32, DIN / 32, 1),  dim3(32, 8)>>>(gw1, p_gwt, DIN, GHID, GWT_TERM);

    // G1: gating hidden = relu(x @ gw1 + gb1), 3-term (err ~2^-22, exact routing)
    mma_gemm<0,2,2,3><<<dim3(GHID / BN, B_TOK / BM, 1), 256, DSM_G>>>(
        p_xt, XT_TERM, B_TOK / 128, nullptr, 0, nullptr,
        p_gwt, GWT_TERM, gb1, 0, nullptr,
        p_hidden, nullptr, nullptr, nullptr, nullptr, B_TOK,
        DIN, GHID, FLAG_RELU);

    // G2 + routing
    logits_kernel<<<B_TOK / 8, 256>>>(p_hidden, gw2, gb2, p_logits);
    init_kernel<<<1, 32>>>();
    route_kernel<<<B_TOK / 256, 256>>>();

    // L1: h = relu(x_g @ w1 + b1) -> tiled fp16
    mma_gemm<1,1,1,NST_E><<<dim3(HID / BN, CAP / BM, NE), 256, DSM_E>>>(
        nullptr, 0, 0, p_xflat, DIN, p_tokens,
        p_w1t, 0, b1, HID, nullptr,
        nullptr, p_hst, nullptr, nullptr, p_counts, 0,
        DIN, HID, FLAG_RELU | FLAG_SPLIT);

    // L2: p = x_g @ wp + bp  (fp32, capacity layout)
    mma_gemm<1,1,1,NST_E><<<dim3(HID / BN, CAP / BM, NE), 256, DSM_E>>>(
        nullptr, 0, 0, p_xflat, DIN, p_tokens,
        p_wpt, 0, bp, HID, nullptr,
        p_p, nullptr, nullptr, nullptr, p_counts, 0,
        DIN, HID, FLAG_OCAP);

    // L3: o = relu(h @ w2 + b2 + p) -> tiled fp16
    mma_gemm<0,1,1,NST_E><<<dim3(HID / BN, CAP / BM, NE), 256, DSM_E>>>(
        p_hst, 0, CAP / 128, nullptr, 0, nullptr,
        p_w2t, 0, b2, HID, p_p,
        nullptr, p_ost, nullptr, nullptr, p_counts, 0,
        HID, HID, FLAG_RELU | FLAG_ADD | FLAG_SPLIT);

    // L4: eout[dest] = (o @ w3 + b3) * gate_w
    mma_gemm<0,1,1,NST_E><<<dim3(DOUT / BN, CAP / BM, NE), 256, DSM_E>>>(
        p_ost, 0, CAP / 128, nullptr, 0, nullptr,
        p_w3t, 0, b3, DOUT, nullptr,
        p_eout, nullptr, p_wts, p_dests, p_counts, 0,
        HID, DOUT, FLAG_DEST);

    // reduce
    size_t total4 = (size_t)B_TOK * DOUT / 4;
    reduce_kernel<<<(unsigned)((total4 + 255) / 256), 256>>>(out);
}

// round 9
// speedup vs baseline: 3.2381x; 1.0669x over previous
#include <cuda_runtime.h>
#include <cuda_fp16.h>
#include <cstdint>

// ---------------- problem constants ----------------
#define B_TOK 8192
#define DIN   1024
#define HID   2048
#define DOUT  1024
#define NE    8
#define GHID  1024
#define CAP   8192

#define FLAG_RELU  1
#define FLAG_ADD   2
#define FLAG_SPLIT 4
#define FLAG_DEST  8
#define FLAG_OCAP  16

// ---------------- tile geometry ----------------
#define BM 128
#define BN 128
#define BK 32
#define ROWE 40                   // padded row stride: 80B (32 fp16 + 16B pad)
#define BLK_B  10240              // block bytes: 128 rows x 80B (A and B identical)
#define BLK_EL 5120

#define XT_TERM  ((size_t)(B_TOK/128) * (DIN/32) * BLK_EL)
#define GWT_TERM ((size_t)(GHID/128)  * (DIN/32) * BLK_EL)

// ---------------- scratch (static device globals; 128B aligned for bulk) ----------------
__device__ __align__(128) unsigned short g_xt [2*XT_TERM];                      // x tiled [hi|lo] (G1)
__device__ __align__(128) unsigned short g_gwt[2*GWT_TERM];                     // gw1^T tiled [hi|lo]
__device__ __align__(128) unsigned short g_xg [(size_t)NE*(CAP/128)*(DIN/32)*BLK_EL];  // gathered x tiled
__device__ __align__(128) unsigned short g_w1t[(size_t)NE*(HID/128)*(DIN/32)*BLK_EL];
__device__ __align__(128) unsigned short g_wpt[(size_t)NE*(HID/128)*(DIN/32)*BLK_EL];
__device__ __align__(128) unsigned short g_w2t[(size_t)NE*(HID/128)*(HID/32)*BLK_EL];
__device__ __align__(128) unsigned short g_w3t[(size_t)NE*(DOUT/128)*(HID/32)*BLK_EL];
__device__ __align__(128) unsigned short g_hst[(size_t)NE*(CAP/128)*(HID/32)*BLK_EL]; // h tiled
__device__ __align__(128) unsigned short g_ost[(size_t)NE*(CAP/128)*(HID/32)*BLK_EL]; // o tiled
__device__ float g_p     [(size_t)NE*CAP*HID];              // projection (L2 out, flat fp32)
__device__ float g_hidden[(size_t)B_TOK*GHID];
__device__ float g_logits[(size_t)B_TOK*NE];
__device__ int   g_counts[NE];
__device__ int   g_tokens[(size_t)NE*CAP];
__device__ float g_wts   [(size_t)NE*CAP];
__device__ int   g_dests [(size_t)NE*CAP];
__device__ float g_eout  [(size_t)B_TOK*2*DOUT];

// ---------------- PTX helpers (sm_90 baseline features only) ----------------
__device__ __forceinline__ uint32_t smem_u32(const void* p) {
    uint32_t a;
    asm("{ .reg .u64 t; cvta.to.shared.u64 t, %1; cvt.u32.u64 %0, t; }" : "=r"(a) : "l"(p));
    return a;
}
#define BULK_G2S(dst, src, nbytes, mbar) \
    asm volatile("cp.async.bulk.shared::cluster.global.mbarrier::complete_tx::bytes [%0], [%1], %2, [%3];" \
        :: "r"(dst), "l"(src), "r"(nbytes), "r"(mbar) : "memory")
#define MBAR_INIT(addr, cnt) \
    asm volatile("mbarrier.init.shared.b64 [%0], %1;" :: "r"(addr), "r"(cnt) : "memory")
#define MBAR_EXPECT_TX(addr, tx) \
    asm volatile("mbarrier.arrive.expect_tx.shared.b64 _, [%0], %1;" :: "r"(addr), "r"(tx) : "memory")
__device__ __forceinline__ void mbar_wait(uint32_t addr, uint32_t parity) {
    asm volatile("{\n\t.reg .pred P;\n"
        "LW%=:\n\tmbarrier.try_wait.parity.acquire.cta.shared::cta.b64 P, [%0], %1, 0x989680;\n"
        "\t@!P bra LW%=;\n\t}" :: "r"(addr), "r"(parity) : "memory");
}
#define LDSM4(r, addr) \
    asm volatile("ldmatrix.sync.aligned.m8n8.x4.shared.b16 {%0,%1,%2,%3}, [%4];" \
        : "=r"((r)[0]), "=r"((r)[1]), "=r"((r)[2]), "=r"((r)[3]) : "r"(addr))
#define MMA16816(d, a, b0, b1) \
    asm volatile("mma.sync.aligned.m16n8k16.row.col.f32.f16.f16.f32 " \
        "{%0,%1,%2,%3},{%4,%5,%6,%7},{%8,%9},{%0,%1,%2,%3};" \
        : "+f"((d)[0]), "+f"((d)[1]), "+f"((d)[2]), "+f"((d)[3]) \
        : "r"((a)[0]), "r"((a)[1]), "r"((a)[2]), "r"((a)[3]), "r"(b0), "r"(b1))

// ---------------- HMMA GEMM: tile 128x128x32, bulk-loaded tiled operands, 2 CTA/SM ----------------
// Stage smem = [A terms][B terms], blocks are byte-images of the tiled global layout.
// LFUSE: grid.x = 2*NT; first NT tiles use Btiled/bias/flags, rest Btiled2/bias2/flags2.
template<int ATERMS, int BTERMS, int NSTAGES, int LFUSE>
__global__ __launch_bounds__(256, 2) void mma_gemm(
    const unsigned short* __restrict__ Atiled, size_t aTermOff, int aMtPerE,
    const unsigned short* __restrict__ Btiled, size_t bTermOff,
    const unsigned short* __restrict__ Btiled2,
    const float* __restrict__ bias, const float* __restrict__ bias2, int bStrideE,
    const float* __restrict__ addt,
    float* __restrict__ outF, unsigned short* __restrict__ outS,
    const float* __restrict__ scales, const int* __restrict__ dests,
    const int* __restrict__ counts, int Mfixed,
    int K, int N, int flags, int flags2)
{
    constexpr uint32_t STAGE_B = (ATERMS + BTERMS) * BLK_B;
    constexpr uint32_t TXB = STAGE_B;

    const int e  = blockIdx.z;
    const int M  = counts ? counts[e] : Mfixed;
    const int m0 = blockIdx.y * BM;
    if (m0 >= M) return;

    const int NT = N >> 7;
    int bx = blockIdx.x;
    int fl = flags;
    const unsigned short* Bt = Btiled;
    const float* bsp = bias;
    if (LFUSE && bx >= NT) { bx -= NT; Bt = Btiled2; bsp = bias2; fl = flags2; }
    const int n0 = bx * BN;

    const int KPC = K >> 5;

    extern __shared__ char smem[];
    const uint32_t sbase = smem_u32(smem);
    const uint32_t mbar0 = sbase + NSTAGES * STAGE_B;

    const int tid  = threadIdx.x;
    const int wid  = tid >> 5;
    const int lane = tid & 31;

    const size_t bBlk0 = ((size_t)(e * NT + bx) * KPC) * BLK_EL;
    const size_t aBlk0 = ((size_t)(e * aMtPerE + blockIdx.y) * KPC) * BLK_EL;

    if (tid == 0) {
        #pragma unroll
        for (int s = 0; s < NSTAGES; s++) MBAR_INIT(mbar0 + s * 8, 1);
    }
    __syncthreads();

    // ---- fragment smem addresses: warp tile 64x32 ----
    const int wm = wid & 1;    // M half (64)
    const int wn = wid >> 1;   // N quarter (32)
    uint32_t aAddr[4][2], bAddr[2][2];
    {
        int arow = wm * 64 + (lane & 15);
        int acol = (lane >> 4) * 8;
        int brbase = wn * 32 + ((lane >> 4) * 8) + (lane & 7);
        int bcol = ((lane >> 3) & 1) * 8;
        #pragma unroll
        for (int ks = 0; ks < 2; ks++) {
            #pragma unroll
            for (int mt = 0; mt < 4; mt++)
                aAddr[mt][ks] = sbase + ((arow + mt * 16) * ROWE + ks * 16 + acol) * 2;
            #pragma unroll
            for (int nt2 = 0; nt2 < 2; nt2++)
                bAddr[nt2][ks] = sbase + ATERMS * BLK_B + ((brbase + nt2 * 16) * ROWE + ks * 16 + bcol) * 2;
        }
    }

    float acc[4][4][4];
    #pragma unroll
    for (int mt = 0; mt < 4; mt++)
        #pragma unroll
        for (int nt = 0; nt < 4; nt++)
            #pragma unroll
            for (int k = 0; k < 4; k++) acc[mt][nt][k] = 0.0f;

    const int NIT = KPC;

    auto load_stage = [&](int s, int it) {
        if (tid == 0) {
            const uint32_t stg = sbase + s * STAGE_B;
            const uint32_t mb = mbar0 + s * 8;
            MBAR_EXPECT_TX(mb, TXB);
            BULK_G2S(stg, Atiled + aBlk0 + (size_t)it * BLK_EL, BLK_B, mb);
            if (ATERMS == 2)
                BULK_G2S(stg + BLK_B, Atiled + aTermOff + aBlk0 + (size_t)it * BLK_EL, BLK_B, mb);
            BULK_G2S(stg + ATERMS * BLK_B, Bt + bBlk0 + (size_t)it * BLK_EL, BLK_B, mb);
            if (BTERMS == 2)
                BULK_G2S(stg + ATERMS * BLK_B + BLK_B, Bt + bTermOff + bBlk0 + (size_t)it * BLK_EL, BLK_B, mb);
        }
    };

    #pragma unroll
    for (int s = 0; s < NSTAGES - 1; s++)
        if (s < NIT) load_stage(s, s);

    for (int it = 0; it < NIT; it++) {
        mbar_wait(mbar0 + (it % NSTAGES) * 8, (it / NSTAGES) & 1);
        __syncthreads();
        if (it + NSTAGES - 1 < NIT) load_stage((it + NSTAGES - 1) % NSTAGES, it + NSTAGES - 1);

        const uint32_t soff = (it % NSTAGES) * STAGE_B;
        #pragma unroll
        for (int ks = 0; ks < 2; ks++) {
            uint32_t af0[4][4], bf[2][4];
            #pragma unroll
            for (int mt = 0; mt < 4; mt++) LDSM4(af0[mt], aAddr[mt][ks] + soff);
            #pragma unroll
            for (int nt2 = 0; nt2 < 2; nt2++) LDSM4(bf[nt2], bAddr[nt2][ks] + soff);
            #pragma unroll
            for (int mt = 0; mt < 4; mt++)
                #pragma unroll
                for (int nt = 0; nt < 4; nt++)
                    MMA16816(acc[mt][nt], af0[mt], bf[nt >> 1][(nt & 1) * 2], bf[nt >> 1][(nt & 1) * 2 + 1]);
            if (ATERMS == 2) {
                uint32_t af1[4][4];
                #pragma unroll
                for (int mt = 0; mt < 4; mt++) LDSM4(af1[mt], aAddr[mt][ks] + soff + BLK_B);
                #pragma unroll
                for (int mt = 0; mt < 4; mt++)
                    #pragma unroll
                    for (int nt = 0; nt < 4; nt++)
                        MMA16816(acc[mt][nt], af1[mt], bf[nt >> 1][(nt & 1) * 2], bf[nt >> 1][(nt & 1) * 2 + 1]);
            }
            if (BTERMS == 2) {
                uint32_t bfl[2][4];
                #pragma unroll
                for (int nt2 = 0; nt2 < 2; nt2++) LDSM4(bfl[nt2], bAddr[nt2][ks] + soff + BLK_B);
                #pragma unroll
                for (int mt = 0; mt < 4; mt++)
                    #pragma unroll
                    for (int nt = 0; nt < 4; nt++)
                        MMA16816(acc[mt][nt], af0[mt], bfl[nt >> 1][(nt & 1) * 2], bfl[nt >> 1][(nt & 1) * 2 + 1]);
            }
        }
    }

    // ---- epilogue: direct from c-fragments ----
    const float* biasE = bsp + (size_t)e * bStrideE;
    const int cq = (lane & 3) * 2;
    const int r0 = lane >> 2;
    float b2v[4][2];
    #pragma unroll
    for (int nt = 0; nt < 4; nt++) {
        int n = n0 + wn * 32 + nt * 8 + cq;
        b2v[nt][0] = biasE[n];
        b2v[nt][1] = biasE[n + 1];
    }

    #pragma unroll
    for (int mt = 0; mt < 4; mt++) {
        #pragma unroll
        for (int h = 0; h < 2; h++) {
            int row = m0 + wm * 64 + mt * 16 + r0 + h * 8;
            if (row >= M) continue;
            size_t erow = (size_t)e * CAP + row;
            float  sc = 1.0f;
            size_t orow = 0;
            if (fl & FLAG_DEST) {
                sc   = scales[erow];
                orow = (size_t)dests[erow];
            } else if (fl & FLAG_OCAP) {
                orow = erow;
            } else {
                orow = (size_t)row;
            }
            #pragma unroll
            for (int nt = 0; nt < 4; nt++) {
                int n = n0 + wn * 32 + nt * 8 + cq;
                float v0 = acc[mt][nt][h * 2]     + b2v[nt][0];
                float v1 = acc[mt][nt][h * 2 + 1] + b2v[nt][1];
                if (fl & FLAG_ADD) {
                    float2 ad = *(const float2*)(addt + erow * N + n);
                    v0 += ad.x; v1 += ad.y;
                }
                if (fl & FLAG_RELU) { v0 = fmaxf(v0, 0.0f); v1 = fmaxf(v1, 0.0f); }
                if (fl & FLAG_SPLIT) {
                    // tiled fp16 write: block image matches next layer's bulk-A layout
                    size_t blk = ((erow >> 7) * (size_t)(N >> 5) + (size_t)(n >> 5)) * BLK_EL;
                    *(__half2*)((__half*)outS + blk + (erow & 127) * 40 + (n & 31)) =
                        __halves2half2(__float2half_rn(v0), __float2half_rn(v1));
                } else {
                    float2 o2; o2.x = v0 * sc; o2.y = v1 * sc;
                    *(float2*)(outF + orow * N + n) = o2;
                }
            }
        }
    }
}

// ---------------- conversion / gather kernels ----------------
// x [B,K] fp32 -> tiled [hi|lo] images (G1 A operand)
__global__ __launch_bounds__(256) void convert_x(const float* __restrict__ x,
                                                 unsigned short* __restrict__ xt,
                                                 int K, size_t total)
{
    size_t idx = (size_t)blockIdx.x * blockDim.x + threadIdx.x;
    if (idx >= total) return;
    size_t t = idx / K;
    int    k = (int)(idx % K);
    float v = x[idx];
    __half hi = __float2half_rn(v);
    __half lo = __float2half_rn(v - __half2float(hi));
    size_t blk = ((t >> 7) * (size_t)(K >> 5) + (size_t)(k >> 5)) * BLK_EL
               + (t & 127) * 40 + (k & 31);
    ((__half*)xt)[blk]           = hi;
    ((__half*)xt)[XT_TERM + blk] = lo;
}

// W [E,K,N] fp32 -> tiled transposed fp16 blocks (hi; optionally +lo at termOff)
__global__ __launch_bounds__(256) void convert_w(const float* __restrict__ W,
                                                 unsigned short* __restrict__ Wt,
                                                 int K, int N, size_t termOff)
{
    const int e = blockIdx.z;
    __shared__ float t[32][33];
    const int n0 = blockIdx.x * 32;
    const int k0 = blockIdx.y * 32;
    const float* We = W + (size_t)e * K * N;
    #pragma unroll
    for (int j = 0; j < 4; j++) {
        int k = k0 + threadIdx.y + j * 8;
        t[threadIdx.y + j * 8][threadIdx.x] = We[(size_t)k * N + n0 + threadIdx.x];
    }
    __syncthreads();
    const size_t blkBase = (((size_t)e * (N >> 7) + (size_t)(n0 >> 7)) * (K >> 5) + (size_t)(k0 >> 5)) * BLK_EL;
    #pragma unroll
    for (int j = 0; j < 4; j++) {
        int n = n0 + threadIdx.y + j * 8;
        int k = k0 + threadIdx.x;
        float v = t[threadIdx.x][threadIdx.y + j * 8];
        __half hi = __float2half_rn(v);
        size_t off = blkBase + (n & 127) * 40 + (k & 31);
        ((__half*)Wt)[off] = hi;
        if (termOff) ((__half*)Wt)[termOff + off] = __float2half_rn(v - __half2float(hi));
    }
}

// gather routed tokens of x into tiled fp16 blocks (per-expert capacity layout)
__global__ __launch_bounds__(256) void tile_gather_x(const float* __restrict__ x,
                                                     unsigned short* __restrict__ xg)
{
    const int e  = blockIdx.y;
    const int mt = blockIdx.x;
    const int M  = g_counts[e];
    const int m0 = mt * 128;
    if (m0 >= M) return;
    const int nrows = min(128, M - m0);
    const size_t base = ((size_t)(e * (CAP / 128) + mt) * (DIN / 32)) * BLK_EL;
    for (int idx = threadIdx.x; idx < nrows * DIN; idx += 256) {
        int row = idx >> 10;
        int k   = idx & (DIN - 1);
        int tok = g_tokens[e * CAP + m0 + row];
        float v = x[(size_t)tok * DIN + k];
        ((__half*)xg)[base + (size_t)(k >> 5) * BLK_EL + row * 40 + (k & 31)] = __float2half_rn(v);
    }
}

// ---------------- gating logits: one warp per token, N=8 ----------------
__global__ __launch_bounds__(256) void logits_kernel(
    const float* __restrict__ h, const float* __restrict__ gw2,
    const float* __restrict__ gb2, float* __restrict__ logits)
{
    int warp = (blockIdx.x * blockDim.x + threadIdx.x) >> 5;
    int lane = threadIdx.x & 31;
    if (warp >= B_TOK) return;
    const float4* hrow = (const float4*)(h + (size_t)warp * GHID);
    float acc[NE];
    #pragma unroll
    for (int e = 0; e < NE; e++) acc[e] = 0.0f;
    for (int i = lane; i < GHID / 4; i += 32) {
        float4 hv = hrow[i];
        const float* g = gw2 + (size_t)(i * 4) * NE;
        #pragma unroll
        for (int e = 0; e < NE; e++)
            acc[e] += hv.x * g[e] + hv.y * g[NE + e] + hv.z * g[2 * NE + e] + hv.w * g[3 * NE + e];
    }
    #pragma unroll
    for (int e = 0; e < NE; e++)
        #pragma unroll
        for (int off = 16; off > 0; off >>= 1)
            acc[e] += __shfl_xor_sync(0xFFFFFFFFu, acc[e], off);
    if (lane == 0) {
        #pragma unroll
        for (int e = 0; e < NE; e++)
            logits[(size_t)warp * NE + e] = acc[e] + gb2[e];
    }
}

// ---------------- routing ----------------
__global__ void init_kernel() {
    if (threadIdx.x < NE) g_counts[threadIdx.x] = 0;
}

__global__ __launch_bounds__(256) void route_kernel() {
    int t = blockIdx.x * blockDim.x + threadIdx.x;
    if (t >= B_TOK) return;
    float v[NE];
    #pragma unroll
    for (int e = 0; e < NE; e++) v[e] = g_logits[(size_t)t * NE + e];
    int i0 = 0;
    #pragma unroll
    for (int e = 1; e < NE; e++) if (v[e] > v[i0]) i0 = e;
    int i1 = (i0 == 0) ? 1 : 0;
    #pragma unroll
    for (int e = 0; e < NE; e++) if (e != i0 && v[e] > v[i1]) i1 = e;
    float b = __expf(v[i1] - v[i0]);
    float s = 1.0f + b;
    float w0 = 1.0f / s;
    float w1 = b / s;

    int p0 = atomicAdd(&g_counts[i0], 1);
    g_tokens[i0 * CAP + p0] = t;
    g_wts[i0 * CAP + p0]    = w0;
    g_dests[i0 * CAP + p0]  = 2 * t;

    int p1 = atomicAdd(&g_counts[i1], 1);
    g_tokens[i1 * CAP + p1] = t;
    g_wts[i1 * CAP + p1]    = w1;
    g_dests[i1 * CAP + p1]  = 2 * t + 1;
}

// ---------------- final reduce ----------------
__global__ __launch_bounds__(256) void reduce_kernel(float* __restrict__ out) {
    size_t idx = (size_t)blockIdx.x * blockDim.x + threadIdx.x;
    const size_t total = (size_t)B_TOK * DOUT / 4;
    if (idx >= total) return;
    size_t t  = idx / (DOUT / 4);
    size_t c4 = idx % (DOUT / 4);
    const float4* e4 = (const float4*)g_eout;
    float4 a = e4[(2 * t) * (DOUT / 4) + c4];
    float4 b = e4[(2 * t + 1) * (DOUT / 4) + c4];
    float4 r;
    r.x = a.x + b.x; r.y = a.y + b.y; r.z = a.z + b.z; r.w = a.w + b.w;
    ((float4*)out)[idx] = r;
}

// ---------------- host ----------------
#define NST_E 5
#define DSM_E (NST_E * 2 * BLK_B + 64)      // 102464; x2 CTAs = 204928
#define DSM_G (3 * 4 * BLK_B + 64)          // 122944

extern "C" void kernel_launch(void* const* d_in, const int* in_sizes, int n_in,
                              void* d_out, int out_size) {
    const float* x   = (const float*)d_in[0];
    const float* w1  = (const float*)d_in[1];
    const float* b1  = (const float*)d_in[2];
    const float* w2  = (const float*)d_in[3];
    const float* b2  = (const float*)d_in[4];
    const float* w3  = (const float*)d_in[5];
    const float* b3  = (const float*)d_in[6];
    const float* wp  = (const float*)d_in[7];
    const float* bp  = (const float*)d_in[8];
    const float* gw1 = (const float*)d_in[9];
    const float* gb1 = (const float*)d_in[10];
    const float* gw2 = (const float*)d_in[11];
    const float* gb2 = (const float*)d_in[12];
    float* out = (float*)d_out;

    unsigned short *p_xt, *p_gwt, *p_xg, *p_w1t, *p_wpt, *p_w2t, *p_w3t, *p_hst, *p_ost;
    float *p_p, *p_hidden, *p_logits, *p_wts, *p_eout;
    int *p_counts, *p_tokens, *p_dests;
    cudaGetSymbolAddress((void**)&p_xt,     g_xt);
    cudaGetSymbolAddress((void**)&p_gwt,    g_gwt);
    cudaGetSymbolAddress((void**)&p_xg,     g_xg);
    cudaGetSymbolAddress((void**)&p_w1t,    g_w1t);
    cudaGetSymbolAddress((void**)&p_wpt,    g_wpt);
    cudaGetSymbolAddress((void**)&p_w2t,    g_w2t);
    cudaGetSymbolAddress((void**)&p_w3t,    g_w3t);
    cudaGetSymbolAddress((void**)&p_hst,    g_hst);
    cudaGetSymbolAddress((void**)&p_ost,    g_ost);
    cudaGetSymbolAddress((void**)&p_p,      g_p);
    cudaGetSymbolAddress((void**)&p_hidden, g_hidden);
    cudaGetSymbolAddress((void**)&p_logits, g_logits);
    cudaGetSymbolAddress((void**)&p_wts,    g_wts);
    cudaGetSymbolAddress((void**)&p_eout,   g_eout);
    cudaGetSymbolAddress((void**)&p_counts, g_counts);
    cudaGetSymbolAddress((void**)&p_tokens, g_tokens);
    cudaGetSymbolAddress((void**)&p_dests,  g_dests);

    cudaFuncSetAttribute((const void*)mma_gemm<1,1,NST_E,0>,
                         cudaFuncAttributeMaxDynamicSharedMemorySize, DSM_E);
    cudaFuncSetAttribute((const void*)mma_gemm<1,1,NST_E,1>,
                         cudaFuncAttributeMaxDynamicSharedMemorySize, DSM_E);
    cudaFuncSetAttribute((const void*)mma_gemm<2,2,3,0>,
                         cudaFuncAttributeMaxDynamicSharedMemorySize, DSM_G);

    // conversions (tiled layouts)
    {
        size_t total = (size_t)B_TOK * DIN;
        convert_x<<<(unsigned)((total + 255) / 256), 256>>>(x, p_xt, DIN, total);
    }
    convert_w<<<dim3(HID / 32, DIN / 32, NE),  dim3(32, 8)>>>(w1,  p_w1t, DIN, HID,  0);
    convert_w<<<dim3(HID / 32, DIN / 32, NE),  dim3(32, 8)>>>(wp,  p_wpt, DIN, HID,  0);
    convert_w<<<dim3(HID / 32, HID / 32, NE),  dim3(32, 8)>>>(w2,  p_w2t, HID, HID,  0);
    convert_w<<<dim3(DOUT / 32, HID / 32, NE), dim3(32, 8)>>>(w3,  p_w3t, HID, DOUT, 0);
    convert_w<<<dim3(GHID / 32, DIN / 32, 1),  dim3(32, 8)>>>(gw1, p_gwt, DIN, GHID, GWT_TERM);

    // G1: gating hidden = relu(x @ gw1 + gb1), 3-term (err ~2^-22, exact routing)
    mma_gemm<2,2,3,0><<<dim3(GHID / BN, B_TOK / BM, 1), 256, DSM_G>>>(
        p_xt, XT_TERM, B_TOK / 128,
        p_gwt, GWT_TERM, nullptr,
        gb1, nullptr, 0, nullptr,
        p_hidden, nullptr, nullptr, nullptr, nullptr, B_TOK,
        DIN, GHID, FLAG_RELU, 0);

    // G2 + routing
    logits_kernel<<<B_TOK / 8, 256>>>(p_hidden, gw2, gb2, p_logits);
    init_kernel<<<1, 32>>>();
    route_kernel<<<B_TOK / 256, 256>>>();

    // gather routed x into tiled layout (makes L1/L2 pure-bulk)
    tile_gather_x<<<dim3(CAP / 128, NE), 256>>>(x, p_xg);

    // L1+L2 fused: tiles [0,16) -> h = relu(x_g@w1+b1) tiled fp16; [16,32) -> p = x_g@wp+bp fp32
    mma_gemm<1,1,NST_E,1><<<dim3(2 * HID / BN, CAP / BM, NE), 256, DSM_E>>>(
        p_xg, 0, CAP / 128,
        p_w1t, 0, p_wpt,
        b1, bp, HID, nullptr,
        p_p, p_hst, nullptr, nullptr, p_counts, 0,
        DIN, HID, FLAG_RELU | FLAG_SPLIT, FLAG_OCAP);

    // L3: o = relu(h @ w2 + b2 + p) -> tiled fp16
    mma_gemm<1,1,NST_E,0><<<dim3(HID / BN, CAP / BM, NE), 256, DSM_E>>>(
        p_hst, 0, CAP / 128,
        p_w2t, 0, nullptr,
        b2, nullptr, HID, p_p,
        nullptr, p_ost, nullptr, nullptr, p_counts, 0,
        HID, HID, FLAG_RELU | FLAG_ADD | FLAG_SPLIT, 0);

    // L4: eout[dest] = (o @ w3 + b3) * gate_w
    mma_gemm<1,1,NST_E,0><<<dim3(DOUT / BN, CAP / BM, NE), 256, DSM_E>>>(
        p_ost, 0, CAP / 128,
        p_w3t, 0, nullptr,
        b3, nullptr, DOUT, nullptr,
        p_eout, nullptr, p_wts, p_dests, p_counts, 0,
        HID, DOUT, FLAG_DEST, 0);

    // reduce
    size_t total4 = (size_t)B_TOK * DOUT / 4;
    reduce_kernel<<<(unsigned)((total4 + 255) / 256), 256>>>(out);
}

// round 10
// speedup vs baseline: 3.3883x; 1.0464x over previous
#include <cuda_runtime.h>
#include <cuda_fp16.h>
#include <cstdint>

// ---------------- problem constants ----------------
#define B_TOK 8192
#define DIN   1024
#define HID   2048
#define DOUT  1024
#define NE    8
#define GHID  1024
#define CAP   8192

#define FLAG_RELU  1
#define FLAG_SPLIT 4
#define FLAG_DEST  8

// ---------------- tile geometry ----------------
#define BM 128
#define BN 128
#define BK 32
#define ROWE 40                   // padded row stride: 80B (32 fp16 + 16B pad)
#define BLK_B  10240              // block bytes: 128 rows x 80B
#define BLK_EL 5120

#define XT_TERM  ((size_t)(B_TOK/128) * (DIN/32) * BLK_EL)
#define GWT_TERM ((size_t)(GHID/128)  * (DIN/32) * BLK_EL)

// ---------------- scratch (static device globals; 128B aligned for bulk) ----------------
__device__ __align__(128) unsigned short g_xt [2*XT_TERM];                      // x tiled [hi|lo] (G1)
__device__ __align__(128) unsigned short g_gwt[2*GWT_TERM];                     // gw1^T tiled [hi|lo]
__device__ __align__(128) unsigned short g_xg [(size_t)NE*(CAP/128)*(DIN/32)*BLK_EL];  // gathered x tiled
__device__ __align__(128) unsigned short g_w1t[(size_t)NE*(HID/128)*(DIN/32)*BLK_EL];
__device__ __align__(128) unsigned short g_wpt[(size_t)NE*(HID/128)*(DIN/32)*BLK_EL];
__device__ __align__(128) unsigned short g_w2t[(size_t)NE*(HID/128)*(HID/32)*BLK_EL];
__device__ __align__(128) unsigned short g_w3t[(size_t)NE*(DOUT/128)*(HID/32)*BLK_EL];
__device__ __align__(128) unsigned short g_hst[(size_t)NE*(CAP/128)*(HID/32)*BLK_EL]; // h tiled
__device__ __align__(128) unsigned short g_ost[(size_t)NE*(CAP/128)*(HID/32)*BLK_EL]; // o tiled
__device__ float g_b23   [(size_t)NE*HID];                  // b2 + bp fused bias
__device__ float g_hidden[(size_t)B_TOK*GHID];
__device__ float g_logits[(size_t)B_TOK*NE];
__device__ int   g_counts[NE];
__device__ int   g_tokens[(size_t)NE*CAP];
__device__ float g_wts   [(size_t)NE*CAP];
__device__ int   g_dests [(size_t)NE*CAP];                  // token index per (expert,row)

// ---------------- PTX helpers (sm_90 baseline features only) ----------------
__device__ __forceinline__ uint32_t smem_u32(const void* p) {
    uint32_t a;
    asm("{ .reg .u64 t; cvta.to.shared.u64 t, %1; cvt.u32.u64 %0, t; }" : "=r"(a) : "l"(p));
    return a;
}
#define BULK_G2S(dst, src, nbytes, mbar) \
    asm volatile("cp.async.bulk.shared::cluster.global.mbarrier::complete_tx::bytes [%0], [%1], %2, [%3];" \
        :: "r"(dst), "l"(src), "r"(nbytes), "r"(mbar) : "memory")
#define MBAR_INIT(addr, cnt) \
    asm volatile("mbarrier.init.shared.b64 [%0], %1;" :: "r"(addr), "r"(cnt) : "memory")
#define MBAR_EXPECT_TX(addr, tx) \
    asm volatile("mbarrier.arrive.expect_tx.shared.b64 _, [%0], %1;" :: "r"(addr), "r"(tx) : "memory")
__device__ __forceinline__ void mbar_wait(uint32_t addr, uint32_t parity) {
    asm volatile("{\n\t.reg .pred P;\n"
        "LW%=:\n\tmbarrier.try_wait.parity.acquire.cta.shared::cta.b64 P, [%0], %1, 0x989680;\n"
        "\t@!P bra LW%=;\n\t}" :: "r"(addr), "r"(parity) : "memory");
}
#define LDSM4(r, addr) \
    asm volatile("ldmatrix.sync.aligned.m8n8.x4.shared.b16 {%0,%1,%2,%3}, [%4];" \
        : "=r"((r)[0]), "=r"((r)[1]), "=r"((r)[2]), "=r"((r)[3]) : "r"(addr))
#define MMA16816(d, a, b0, b1) \
    asm volatile("mma.sync.aligned.m16n8k16.row.col.f32.f16.f16.f32 " \
        "{%0,%1,%2,%3},{%4,%5,%6,%7},{%8,%9},{%0,%1,%2,%3};" \
        : "+f"((d)[0]), "+f"((d)[1]), "+f"((d)[2]), "+f"((d)[3]) \
        : "r"((a)[0]), "r"((a)[1]), "r"((a)[2]), "r"((a)[3]), "r"(b0), "r"(b1))

// ---------------- HMMA GEMM: tile 128x128x32, bulk tiled operands, segmented K ----------------
// K-space = kcSplit blocks from (Atiled,Btiled) then (KPC-kcSplit) blocks from (At2,Bt2).
// Per k-block: acc += A0*B0 (+ A1*B0 if ATERMS==2) (+ A0*B1 if BTERMS==2).
template<int ATERMS, int BTERMS, int NSTAGES>
__global__ __launch_bounds__(256, 2) void mma_gemm(
    const unsigned short* __restrict__ Atiled, size_t aTermOff,
    const unsigned short* __restrict__ At2, int aMtPerE,
    const unsigned short* __restrict__ Btiled, size_t bTermOff,
    const unsigned short* __restrict__ Bt2,
    const float* __restrict__ bias, int bStrideE,
    float* __restrict__ outF, unsigned short* __restrict__ outS,
    const float* __restrict__ scales, const int* __restrict__ dests,
    const int* __restrict__ counts, int Mfixed,
    int KPC, int kcSplit, int N, int flags)
{
    constexpr uint32_t STAGE_B = (ATERMS + BTERMS) * BLK_B;

    const int e  = blockIdx.z;
    const int M  = counts ? counts[e] : Mfixed;
    const int m0 = blockIdx.y * BM;
    if (m0 >= M) return;
    const int n0 = blockIdx.x * BN;

    const int NT   = N >> 7;
    const int kpc2 = KPC - kcSplit;

    extern __shared__ char smem[];
    const uint32_t sbase = smem_u32(smem);
    const uint32_t mbar0 = sbase + NSTAGES * STAGE_B;

    const int tid  = threadIdx.x;
    const int wid  = tid >> 5;
    const int lane = tid & 31;

    const size_t aTile = (size_t)(e * aMtPerE + blockIdx.y);
    const size_t bTile = (size_t)(e * NT + blockIdx.x);

    if (tid == 0) {
        #pragma unroll
        for (int s = 0; s < NSTAGES; s++) MBAR_INIT(mbar0 + s * 8, 1);
    }
    __syncthreads();

    // ---- fragment smem addresses: warp tile 64x32 ----
    const int wm = wid & 1;
    const int wn = wid >> 1;
    uint32_t aAddr[4][2], bAddr[2][2];
    {
        int arow = wm * 64 + (lane & 15);
        int acol = (lane >> 4) * 8;
        int brbase = wn * 32 + ((lane >> 4) * 8) + (lane & 7);
        int bcol = ((lane >> 3) & 1) * 8;
        #pragma unroll
        for (int ks = 0; ks < 2; ks++) {
            #pragma unroll
            for (int mt = 0; mt < 4; mt++)
                aAddr[mt][ks] = sbase + ((arow + mt * 16) * ROWE + ks * 16 + acol) * 2;
            #pragma unroll
            for (int nt2 = 0; nt2 < 2; nt2++)
                bAddr[nt2][ks] = sbase + ATERMS * BLK_B + ((brbase + nt2 * 16) * ROWE + ks * 16 + bcol) * 2;
        }
    }

    float acc[4][4][4];
    #pragma unroll
    for (int mt = 0; mt < 4; mt++)
        #pragma unroll
        for (int nt = 0; nt < 4; nt++)
            #pragma unroll
            for (int k = 0; k < 4; k++) acc[mt][nt][k] = 0.0f;

    const int NIT = KPC;

    auto load_stage = [&](int s, int it) {
        if (tid == 0) {
            const uint32_t stg = sbase + s * STAGE_B;
            const uint32_t mb = mbar0 + s * 8;
            MBAR_EXPECT_TX(mb, STAGE_B);
            const unsigned short* aSrc;
            const unsigned short* bSrc;
            if (it < kcSplit) {
                aSrc = Atiled + (aTile * kcSplit + it) * BLK_EL;
                bSrc = Btiled + (bTile * kcSplit + it) * BLK_EL;
            } else {
                aSrc = At2 + (aTile * kpc2 + (it - kcSplit)) * BLK_EL;
                bSrc = Bt2 + (bTile * kpc2 + (it - kcSplit)) * BLK_EL;
            }
            BULK_G2S(stg, aSrc, BLK_B, mb);
            if (ATERMS == 2)
                BULK_G2S(stg + BLK_B, Atiled + aTermOff + (aTile * kcSplit + it) * BLK_EL, BLK_B, mb);
            BULK_G2S(stg + ATERMS * BLK_B, bSrc, BLK_B, mb);
            if (BTERMS == 2)
                BULK_G2S(stg + ATERMS * BLK_B + BLK_B, Btiled + bTermOff + (bTile * kcSplit + it) * BLK_EL, BLK_B, mb);
        }
    };

    #pragma unroll
    for (int s = 0; s < NSTAGES - 1; s++)
        if (s < NIT) load_stage(s, s);

    for (int it = 0; it < NIT; it++) {
        mbar_wait(mbar0 + (it % NSTAGES) * 8, (it / NSTAGES) & 1);
        __syncthreads();
        if (it + NSTAGES - 1 < NIT) load_stage((it + NSTAGES - 1) % NSTAGES, it + NSTAGES - 1);

        const uint32_t soff = (it % NSTAGES) * STAGE_B;
        #pragma unroll
        for (int ks = 0; ks < 2; ks++) {
            uint32_t af0[4][4], bf[2][4];
            #pragma unroll
            for (int mt = 0; mt < 4; mt++) LDSM4(af0[mt], aAddr[mt][ks] + soff);
            #pragma unroll
            for (int nt2 = 0; nt2 < 2; nt2++) LDSM4(bf[nt2], bAddr[nt2][ks] + soff);
            #pragma unroll
            for (int mt = 0; mt < 4; mt++)
                #pragma unroll
                for (int nt = 0; nt < 4; nt++)
                    MMA16816(acc[mt][nt], af0[mt], bf[nt >> 1][(nt & 1) * 2], bf[nt >> 1][(nt & 1) * 2 + 1]);
            if (ATERMS == 2) {
                uint32_t af1[4][4];
                #pragma unroll
                for (int mt = 0; mt < 4; mt++) LDSM4(af1[mt], aAddr[mt][ks] + soff + BLK_B);
                #pragma unroll
                for (int mt = 0; mt < 4; mt++)
                    #pragma unroll
                    for (int nt = 0; nt < 4; nt++)
                        MMA16816(acc[mt][nt], af1[mt], bf[nt >> 1][(nt & 1) * 2], bf[nt >> 1][(nt & 1) * 2 + 1]);
            }
            if (BTERMS == 2) {
                uint32_t bfl[2][4];
                #pragma unroll
                for (int nt2 = 0; nt2 < 2; nt2++) LDSM4(bfl[nt2], bAddr[nt2][ks] + soff + BLK_B);
                #pragma unroll
                for (int mt = 0; mt < 4; mt++)
                    #pragma unroll
                    for (int nt = 0; nt < 4; nt++)
                        MMA16816(acc[mt][nt], af0[mt], bfl[nt >> 1][(nt & 1) * 2], bfl[nt >> 1][(nt & 1) * 2 + 1]);
            }
        }
    }

    // ---- epilogue: direct from c-fragments ----
    const float* biasE = bias + (size_t)e * bStrideE;
    const int cq = (lane & 3) * 2;
    const int r0 = lane >> 2;
    float b2v[4][2];
    #pragma unroll
    for (int nt = 0; nt < 4; nt++) {
        int n = n0 + wn * 32 + nt * 8 + cq;
        b2v[nt][0] = biasE[n];
        b2v[nt][1] = biasE[n + 1];
    }

    #pragma unroll
    for (int mt = 0; mt < 4; mt++) {
        #pragma unroll
        for (int h = 0; h < 2; h++) {
            int row = m0 + wm * 64 + mt * 16 + r0 + h * 8;
            if (row >= M) continue;
            size_t erow = (size_t)e * CAP + row;
            float sc = 1.0f;
            int   tok = 0;
            if (flags & FLAG_DEST) {
                sc  = scales[erow];
                tok = dests[erow];
            }
            #pragma unroll
            for (int nt = 0; nt < 4; nt++) {
                int n = n0 + wn * 32 + nt * 8 + cq;
                float v0 = acc[mt][nt][h * 2]     + b2v[nt][0];
                float v1 = acc[mt][nt][h * 2 + 1] + b2v[nt][1];
                if (flags & FLAG_RELU) { v0 = fmaxf(v0, 0.0f); v1 = fmaxf(v1, 0.0f); }
                if (flags & FLAG_SPLIT) {
                    size_t blk = ((erow >> 7) * (size_t)(N >> 5) + (size_t)(n >> 5)) * BLK_EL;
                    *(__half2*)((__half*)outS + blk + (erow & 127) * 40 + (n & 31)) =
                        __halves2half2(__float2half_rn(v0), __float2half_rn(v1));
                } else if (flags & FLAG_DEST) {
                    // out receives exactly 2 commutative fp32 adds per element -> deterministic
                    atomicAdd(outF + (size_t)tok * N + n,     v0 * sc);
                    atomicAdd(outF + (size_t)tok * N + n + 1, v1 * sc);
                } else {
                    float2 o2; o2.x = v0; o2.y = v1;
                    *(float2*)(outF + (size_t)row * N + n) = o2;
                }
            }
        }
    }
}

// ---------------- conversion / gather kernels ----------------
__global__ __launch_bounds__(256) void convert_x(const float* __restrict__ x,
                                                 unsigned short* __restrict__ xt,
                                                 int K, size_t total)
{
    size_t idx = (size_t)blockIdx.x * blockDim.x + threadIdx.x;
    if (idx >= total) return;
    size_t t = idx / K;
    int    k = (int)(idx % K);
    float v = x[idx];
    __half hi = __float2half_rn(v);
    __half lo = __float2half_rn(v - __half2float(hi));
    size_t blk = ((t >> 7) * (size_t)(K >> 5) + (size_t)(k >> 5)) * BLK_EL
               + (t & 127) * 40 + (k & 31);
    ((__half*)xt)[blk]           = hi;
    ((__half*)xt)[XT_TERM + blk] = lo;
}

__global__ __launch_bounds__(256) void convert_w(const float* __restrict__ W,
                                                 unsigned short* __restrict__ Wt,
                                                 int K, int N, size_t termOff)
{
    const int e = blockIdx.z;
    __shared__ float t[32][33];
    const int n0 = blockIdx.x * 32;
    const int k0 = blockIdx.y * 32;
    const float* We = W + (size_t)e * K * N;
    #pragma unroll
    for (int j = 0; j < 4; j++) {
        int k = k0 + threadIdx.y + j * 8;
        t[threadIdx.y + j * 8][threadIdx.x] = We[(size_t)k * N + n0 + threadIdx.x];
    }
    __syncthreads();
    const size_t blkBase = (((size_t)e * (N >> 7) + (size_t)(n0 >> 7)) * (K >> 5) + (size_t)(k0 >> 5)) * BLK_EL;
    #pragma unroll
    for (int j = 0; j < 4; j++) {
        int n = n0 + threadIdx.y + j * 8;
        int k = k0 + threadIdx.x;
        float v = t[threadIdx.x][threadIdx.y + j * 8];
        __half hi = __float2half_rn(v);
        size_t off = blkBase + (n & 127) * 40 + (k & 31);
        ((__half*)Wt)[off] = hi;
        if (termOff) ((__half*)Wt)[termOff + off] = __float2half_rn(v - __half2float(hi));
    }
}

__global__ __launch_bounds__(256) void tile_gather_x(const float* __restrict__ x,
                                                     unsigned short* __restrict__ xg)
{
    const int e  = blockIdx.y;
    const int mt = blockIdx.x;
    const int M  = g_counts[e];
    const int m0 = mt * 128;
    if (m0 >= M) return;
    const int nrows = min(128, M - m0);
    const size_t base = ((size_t)(e * (CAP / 128) + mt) * (DIN / 32)) * BLK_EL;
    for (int idx = threadIdx.x; idx < nrows * DIN; idx += 256) {
        int row = idx >> 10;
        int k   = idx & (DIN - 1);
        int tok = g_tokens[e * CAP + m0 + row];
        float v = x[(size_t)tok * DIN + k];
        ((__half*)xg)[base + (size_t)(k >> 5) * BLK_EL + row * 40 + (k & 31)] = __float2half_rn(v);
    }
}

// b23 = b2 + bp
__global__ __launch_bounds__(256) void bias_fuse(const float* __restrict__ b2,
                                                 const float* __restrict__ bp,
                                                 float* __restrict__ b23)
{
    int i = blockIdx.x * blockDim.x + threadIdx.x;
    if (i < NE * HID) b23[i] = b2[i] + bp[i];
}

// zero the output (poisoned by harness; L4 accumulates atomically)
__global__ __launch_bounds__(256) void zero_out(float4* __restrict__ out, size_t n4)
{
    size_t i = (size_t)blockIdx.x * blockDim.x + threadIdx.x;
    if (i < n4) out[i] = make_float4(0.f, 0.f, 0.f, 0.f);
}

// ---------------- gating logits: one warp per token, N=8 ----------------
__global__ __launch_bounds__(256) void logits_kernel(
    const float* __restrict__ h, const float* __restrict__ gw2,
    const float* __restrict__ gb2, float* __restrict__ logits)
{
    int warp = (blockIdx.x * blockDim.x + threadIdx.x) >> 5;
    int lane = threadIdx.x & 31;
    if (warp >= B_TOK) return;
    const float4* hrow = (const float4*)(h + (size_t)warp * GHID);
    float acc[NE];
    #pragma unroll
    for (int e = 0; e < NE; e++) acc[e] = 0.0f;
    for (int i = lane; i < GHID / 4; i += 32) {
        float4 hv = hrow[i];
        const float* g = gw2 + (size_t)(i * 4) * NE;
        #pragma unroll
        for (int e = 0; e < NE; e++)
            acc[e] += hv.x * g[e] + hv.y * g[NE + e] + hv.z * g[2 * NE + e] + hv.w * g[3 * NE + e];
    }
    #pragma unroll
    for (int e = 0; e < NE; e++)
        #pragma unroll
        for (int off = 16; off > 0; off >>= 1)
            acc[e] += __shfl_xor_sync(0xFFFFFFFFu, acc[e], off);
    if (lane == 0) {
        #pragma unroll
        for (int e = 0; e < NE; e++)
            logits[(size_t)warp * NE + e] = acc[e] + gb2[e];
    }
}

// ---------------- routing ----------------
__global__ void init_kernel() {
    if (threadIdx.x < NE) g_counts[threadIdx.x] = 0;
}

__global__ __launch_bounds__(256) void route_kernel() {
    int t = blockIdx.x * blockDim.x + threadIdx.x;
    if (t >= B_TOK) return;
    float v[NE];
    #pragma unroll
    for (int e = 0; e < NE; e++) v[e] = g_logits[(size_t)t * NE + e];
    int i0 = 0;
    #pragma unroll
    for (int e = 1; e < NE; e++) if (v[e] > v[i0]) i0 = e;
    int i1 = (i0 == 0) ? 1 : 0;
    #pragma unroll
    for (int e = 0; e < NE; e++) if (e != i0 && v[e] > v[i1]) i1 = e;
    float b = __expf(v[i1] - v[i0]);
    float s = 1.0f + b;
    float w0 = 1.0f / s;
    float w1 = b / s;

    int p0 = atomicAdd(&g_counts[i0], 1);
    g_tokens[i0 * CAP + p0] = t;
    g_wts[i0 * CAP + p0]    = w0;
    g_dests[i0 * CAP + p0]  = t;

    int p1 = atomicAdd(&g_counts[i1], 1);
    g_tokens[i1 * CAP + p1] = t;
    g_wts[i1 * CAP + p1]    = w1;
    g_dests[i1 * CAP + p1]  = t;
}

// ---------------- host ----------------
#define NST_E 5
#define DSM_E (NST_E * 2 * BLK_B + 64)      // 102464; x2 CTAs/SM
#define DSM_G (3 * 4 * BLK_B + 64)          // 122944

extern "C" void kernel_launch(void* const* d_in, const int* in_sizes, int n_in,
                              void* d_out, int out_size) {
    const float* x   = (const float*)d_in[0];
    const float* w1  = (const float*)d_in[1];
    const float* b1  = (const float*)d_in[2];
    const float* w2  = (const float*)d_in[3];
    const float* b2  = (const float*)d_in[4];
    const float* w3  = (const float*)d_in[5];
    const float* b3  = (const float*)d_in[6];
    const float* wp  = (const float*)d_in[7];
    const float* bp  = (const float*)d_in[8];
    const float* gw1 = (const float*)d_in[9];
    const float* gb1 = (const float*)d_in[10];
    const float* gw2 = (const float*)d_in[11];
    const float* gb2 = (const float*)d_in[12];
    float* out = (float*)d_out;

    unsigned short *p_xt, *p_gwt, *p_xg, *p_w1t, *p_wpt, *p_w2t, *p_w3t, *p_hst, *p_ost;
    float *p_b23, *p_hidden, *p_logits, *p_wts;
    int *p_counts, *p_tokens, *p_dests;
    cudaGetSymbolAddress((void**)&p_xt,     g_xt);
    cudaGetSymbolAddress((void**)&p_gwt,    g_gwt);
    cudaGetSymbolAddress((void**)&p_xg,     g_xg);
    cudaGetSymbolAddress((void**)&p_w1t,    g_w1t);
    cudaGetSymbolAddress((void**)&p_wpt,    g_wpt);
    cudaGetSymbolAddress((void**)&p_w2t,    g_w2t);
    cudaGetSymbolAddress((void**)&p_w3t,    g_w3t);
    cudaGetSymbolAddress((void**)&p_hst,    g_hst);
    cudaGetSymbolAddress((void**)&p_ost,    g_ost);
    cudaGetSymbolAddress((void**)&p_b23,    g_b23);
    cudaGetSymbolAddress((void**)&p_hidden, g_hidden);
    cudaGetSymbolAddress((void**)&p_logits, g_logits);
    cudaGetSymbolAddress((void**)&p_wts,    g_wts);
    cudaGetSymbolAddress((void**)&p_counts, g_counts);
    cudaGetSymbolAddress((void**)&p_tokens, g_tokens);
    cudaGetSymbolAddress((void**)&p_dests,  g_dests);

    cudaFuncSetAttribute((const void*)mma_gemm<1,1,NST_E>,
                         cudaFuncAttributeMaxDynamicSharedMemorySize, DSM_E);
    cudaFuncSetAttribute((const void*)mma_gemm<2,2,3>,
                         cudaFuncAttributeMaxDynamicSharedMemorySize, DSM_G);

    // zero output (L4 accumulates atomically)
    {
        size_t n4 = (size_t)B_TOK * DOUT / 4;
        zero_out<<<(unsigned)((n4 + 255) / 256), 256>>>((float4*)out, n4);
    }

    // conversions (tiled layouts)
    {
        size_t total = (size_t)B_TOK * DIN;
        convert_x<<<(unsigned)((total + 255) / 256), 256>>>(x, p_xt, DIN, total);
    }
    convert_w<<<dim3(HID / 32, DIN / 32, NE),  dim3(32, 8)>>>(w1,  p_w1t, DIN, HID,  0);
    convert_w<<<dim3(HID / 32, DIN / 32, NE),  dim3(32, 8)>>>(wp,  p_wpt, DIN, HID,  0);
    convert_w<<<dim3(HID / 32, HID / 32, NE),  dim3(32, 8)>>>(w2,  p_w2t, HID, HID,  0);
    convert_w<<<dim3(DOUT / 32, HID / 32, NE), dim3(32, 8)>>>(w3,  p_w3t, HID, DOUT, 0);
    convert_w<<<dim3(GHID / 32, DIN / 32, 1),  dim3(32, 8)>>>(gw1, p_gwt, DIN, GHID, GWT_TERM);
    bias_fuse<<<(NE * HID + 255) / 256, 256>>>(b2, bp, p_b23);

    // G1: gating hidden = relu(x @ gw1 + gb1), 3-term (err ~2^-22, exact routing)
    mma_gemm<2,2,3><<<dim3(GHID / BN, B_TOK / BM, 1), 256, DSM_G>>>(
        p_xt, XT_TERM, nullptr, B_TOK / 128,
        p_gwt, GWT_TERM, nullptr,
        gb1, 0,
        p_hidden, nullptr, nullptr, nullptr, nullptr, B_TOK,
        DIN / 32, DIN / 32, GHID, FLAG_RELU);

    // G2 + routing
    logits_kernel<<<B_TOK / 8, 256>>>(p_hidden, gw2, gb2, p_logits);
    init_kernel<<<1, 32>>>();
    route_kernel<<<B_TOK / 256, 256>>>();

    // gather routed x into tiled layout
    tile_gather_x<<<dim3(CAP / 128, NE), 256>>>(x, p_xg);

    // L1: h = relu(x_g @ w1 + b1) -> tiled fp16
    mma_gemm<1,1,NST_E><<<dim3(HID / BN, CAP / BM, NE), 256, DSM_E>>>(
        p_xg, 0, nullptr, CAP / 128,
        p_w1t, 0, nullptr,
        b1, HID,
        nullptr, p_hst, nullptr, nullptr, p_counts, 0,
        DIN / 32, DIN / 32, HID, FLAG_RELU | FLAG_SPLIT);

    // L3 (L2 fused via K-concat): o = relu([h|x_g] @ [w2;wp] + b2+bp) -> tiled fp16
    mma_gemm<1,1,NST_E><<<dim3(HID / BN, CAP / BM, NE), 256, DSM_E>>>(
        p_hst, 0, p_xg, CAP / 128,
        p_w2t, 0, p_wpt,
        p_b23, HID,
        nullptr, p_ost, nullptr, nullptr, p_counts, 0,
        (HID + DIN) / 32, HID / 32, HID, FLAG_RELU | FLAG_SPLIT);

    // L4: out[tok] += (o @ w3 + b3) * gate_w   (atomic, 2 adds per element)
    mma_gemm<1,1,NST_E><<<dim3(DOUT / BN, CAP / BM, NE), 256, DSM_E>>>(
        p_ost, 0, nullptr, CAP / 128,
        p_w3t, 0, nullptr,
        b3, DOUT,
        out, nullptr, p_wts, p_dests, p_counts, 0,
        HID / 32, HID / 32, DOUT, FLAG_DEST);
}

// round 11
// speedup vs baseline: 3.4098x; 1.0063x over previous
#include <cuda_runtime.h>
#include <cuda_fp16.h>
#include <cstdint>

// ---------------- problem constants ----------------
#define B_TOK 8192
#define DIN   1024
#define HID   2048
#define DOUT  1024
#define NE    8
#define GHID  1024
#define CAP   8192

#define FLAG_RELU  1
#define FLAG_SPLIT 4
#define FLAG_DEST  8

// ---------------- tile geometry (packed 64B rows + XOR swizzle) ----------------
#define BM 128
#define BN 128
#define BK 32
#define BLK_B  8192               // block bytes: 128 rows x 64B (packed)
#define BLK_EL 4096

// element offset of (row r, col c) inside a 128x32 block, swizzled:
// physical 16B-chunk = (c>>3) ^ ((r>>1)&3)
__device__ __forceinline__ uint32_t sw_off(int r, int c) {
    return (uint32_t)(r * 32 + ((((c >> 3) ^ ((r >> 1) & 3)) << 3) | (c & 7)));
}

#define XT_TERM  ((size_t)(B_TOK/128) * (DIN/32) * BLK_EL)
#define GWT_TERM ((size_t)(GHID/128)  * (DIN/32) * BLK_EL)

// ---------------- scratch (static device globals; 128B aligned for bulk) ----------------
__device__ __align__(128) unsigned short g_xt [2*XT_TERM];                      // x tiled [hi|lo] (G1)
__device__ __align__(128) unsigned short g_gwt[2*GWT_TERM];                     // gw1^T tiled [hi|lo]
__device__ __align__(128) unsigned short g_xg [(size_t)NE*(CAP/128)*(DIN/32)*BLK_EL];  // gathered x tiled
__device__ __align__(128) unsigned short g_w1t[(size_t)NE*(HID/128)*(DIN/32)*BLK_EL];
__device__ __align__(128) unsigned short g_wpt[(size_t)NE*(HID/128)*(DIN/32)*BLK_EL];
__device__ __align__(128) unsigned short g_w2t[(size_t)NE*(HID/128)*(HID/32)*BLK_EL];
__device__ __align__(128) unsigned short g_w3t[(size_t)NE*(DOUT/128)*(HID/32)*BLK_EL];
__device__ __align__(128) unsigned short g_hst[(size_t)NE*(CAP/128)*(HID/32)*BLK_EL]; // h tiled
__device__ __align__(128) unsigned short g_ost[(size_t)NE*(CAP/128)*(HID/32)*BLK_EL]; // o tiled
__device__ float g_b23   [(size_t)NE*HID];                  // b2 + bp fused bias
__device__ float g_hidden[(size_t)B_TOK*GHID];
__device__ float g_logits[(size_t)B_TOK*NE];
__device__ int   g_counts[NE];
__device__ int   g_tokens[(size_t)NE*CAP];
__device__ float g_wts   [(size_t)NE*CAP];
__device__ int   g_dests [(size_t)NE*CAP];                  // token index per (expert,row)

// ---------------- PTX helpers (sm_90 baseline features only) ----------------
__device__ __forceinline__ uint32_t smem_u32(const void* p) {
    uint32_t a;
    asm("{ .reg .u64 t; cvta.to.shared.u64 t, %1; cvt.u32.u64 %0, t; }" : "=r"(a) : "l"(p));
    return a;
}
#define BULK_G2S(dst, src, nbytes, mbar) \
    asm volatile("cp.async.bulk.shared::cluster.global.mbarrier::complete_tx::bytes [%0], [%1], %2, [%3];" \
        :: "r"(dst), "l"(src), "r"(nbytes), "r"(mbar) : "memory")
#define MBAR_INIT(addr, cnt) \
    asm volatile("mbarrier.init.shared.b64 [%0], %1;" :: "r"(addr), "r"(cnt) : "memory")
#define MBAR_EXPECT_TX(addr, tx) \
    asm volatile("mbarrier.arrive.expect_tx.shared.b64 _, [%0], %1;" :: "r"(addr), "r"(tx) : "memory")
__device__ __forceinline__ void mbar_wait(uint32_t addr, uint32_t parity) {
    asm volatile("{\n\t.reg .pred P;\n"
        "LW%=:\n\tmbarrier.try_wait.parity.acquire.cta.shared::cta.b64 P, [%0], %1, 0x989680;\n"
        "\t@!P bra LW%=;\n\t}" :: "r"(addr), "r"(parity) : "memory");
}
#define LDSM4(r, addr) \
    asm volatile("ldmatrix.sync.aligned.m8n8.x4.shared.b16 {%0,%1,%2,%3}, [%4];" \
        : "=r"((r)[0]), "=r"((r)[1]), "=r"((r)[2]), "=r"((r)[3]) : "r"(addr))
#define MMA16816(d, a, b0, b1) \
    asm volatile("mma.sync.aligned.m16n8k16.row.col.f32.f16.f16.f32 " \
        "{%0,%1,%2,%3},{%4,%5,%6,%7},{%8,%9},{%0,%1,%2,%3};" \
        : "+f"((d)[0]), "+f"((d)[1]), "+f"((d)[2]), "+f"((d)[3]) \
        : "r"((a)[0]), "r"((a)[1]), "r"((a)[2]), "r"((a)[3]), "r"(b0), "r"(b1))

// ---------------- HMMA GEMM: tile 128x128x32, bulk tiled operands, segmented K ----------------
// K-space = kcSplit blocks from (Atiled,Btiled) then (KPC-kcSplit) blocks from (At2,Bt2).
template<int ATERMS, int BTERMS, int NSTAGES>
__global__ __launch_bounds__(256, 2) void mma_gemm(
    const unsigned short* __restrict__ Atiled, size_t aTermOff,
    const unsigned short* __restrict__ At2, int aMtPerE,
    const unsigned short* __restrict__ Btiled, size_t bTermOff,
    const unsigned short* __restrict__ Bt2,
    const float* __restrict__ bias, int bStrideE,
    float* __restrict__ outF, unsigned short* __restrict__ outS,
    const float* __restrict__ scales, const int* __restrict__ dests,
    const int* __restrict__ counts, int Mfixed,
    int KPC, int kcSplit, int N, int flags)
{
    constexpr uint32_t STAGE_B = (ATERMS + BTERMS) * BLK_B;

    const int e  = blockIdx.z;
    const int M  = counts ? counts[e] : Mfixed;
    const int m0 = blockIdx.y * BM;
    if (m0 >= M) return;
    const int n0 = blockIdx.x * BN;

    const int NT   = N >> 7;
    const int kpc2 = KPC - kcSplit;

    extern __shared__ char smem[];
    const uint32_t sbase = smem_u32(smem);
    const uint32_t mbar0 = sbase + NSTAGES * STAGE_B;

    const int tid  = threadIdx.x;
    const int wid  = tid >> 5;
    const int lane = tid & 31;

    const size_t aTile = (size_t)(e * aMtPerE + blockIdx.y);
    const size_t bTile = (size_t)(e * NT + blockIdx.x);

    if (tid == 0) {
        #pragma unroll
        for (int s = 0; s < NSTAGES; s++) MBAR_INIT(mbar0 + s * 8, 1);
    }
    __syncthreads();

    // ---- fragment smem addresses: warp tile 64x32, swizzled chunks ----
    const int wm = wid & 1;
    const int wn = wid >> 1;
    uint32_t aAddr[4][2], bAddr[2][2];
    {
        int arow0 = wm * 64 + (lane & 15);
        int alc0  = (lane >> 4);             // logical 16B chunk within the ks half
        int brow0 = wn * 32 + ((lane >> 4) * 8) + (lane & 7);
        int blc0  = ((lane >> 3) & 1);
        #pragma unroll
        for (int ks = 0; ks < 2; ks++) {
            #pragma unroll
            for (int mt = 0; mt < 4; mt++) {
                int r  = arow0 + mt * 16;
                int pc = (ks * 2 + alc0) ^ ((r >> 1) & 3);
                aAddr[mt][ks] = sbase + (uint32_t)(r * 64 + pc * 16);
            }
            #pragma unroll
            for (int nt2 = 0; nt2 < 2; nt2++) {
                int r  = brow0 + nt2 * 16;
                int pc = (ks * 2 + blc0) ^ ((r >> 1) & 3);
                bAddr[nt2][ks] = sbase + ATERMS * BLK_B + (uint32_t)(r * 64 + pc * 16);
            }
        }
    }

    float acc[4][4][4];
    #pragma unroll
    for (int mt = 0; mt < 4; mt++)
        #pragma unroll
        for (int nt = 0; nt < 4; nt++)
            #pragma unroll
            for (int k = 0; k < 4; k++) acc[mt][nt][k] = 0.0f;

    const int NIT = KPC;

    auto load_stage = [&](int s, int it) {
        if (tid == 0) {
            const uint32_t stg = sbase + s * STAGE_B;
            const uint32_t mb = mbar0 + s * 8;
            MBAR_EXPECT_TX(mb, STAGE_B);
            const unsigned short* aSrc;
            const unsigned short* bSrc;
            if (it < kcSplit) {
                aSrc = Atiled + (aTile * kcSplit + it) * BLK_EL;
                bSrc = Btiled + (bTile * kcSplit + it) * BLK_EL;
            } else {
                aSrc = At2 + (aTile * kpc2 + (it - kcSplit)) * BLK_EL;
                bSrc = Bt2 + (bTile * kpc2 + (it - kcSplit)) * BLK_EL;
            }
            BULK_G2S(stg, aSrc, BLK_B, mb);
            if (ATERMS == 2)
                BULK_G2S(stg + BLK_B, Atiled + aTermOff + (aTile * kcSplit + it) * BLK_EL, BLK_B, mb);
            BULK_G2S(stg + ATERMS * BLK_B, bSrc, BLK_B, mb);
            if (BTERMS == 2)
                BULK_G2S(stg + ATERMS * BLK_B + BLK_B, Btiled + bTermOff + (bTile * kcSplit + it) * BLK_EL, BLK_B, mb);
        }
    };

    #pragma unroll
    for (int s = 0; s < NSTAGES - 1; s++)
        if (s < NIT) load_stage(s, s);

    for (int it = 0; it < NIT; it++) {
        mbar_wait(mbar0 + (it % NSTAGES) * 8, (it / NSTAGES) & 1);
        __syncthreads();
        if (it + NSTAGES - 1 < NIT) load_stage((it + NSTAGES - 1) % NSTAGES, it + NSTAGES - 1);

        const uint32_t soff = (it % NSTAGES) * STAGE_B;
        #pragma unroll
        for (int ks = 0; ks < 2; ks++) {
            uint32_t af0[4][4], bf[2][4];
            #pragma unroll
            for (int mt = 0; mt < 4; mt++) LDSM4(af0[mt], aAddr[mt][ks] + soff);
            #pragma unroll
            for (int nt2 = 0; nt2 < 2; nt2++) LDSM4(bf[nt2], bAddr[nt2][ks] + soff);
            #pragma unroll
            for (int mt = 0; mt < 4; mt++)
                #pragma unroll
                for (int nt = 0; nt < 4; nt++)
                    MMA16816(acc[mt][nt], af0[mt], bf[nt >> 1][(nt & 1) * 2], bf[nt >> 1][(nt & 1) * 2 + 1]);
            if (ATERMS == 2) {
                uint32_t af1[4][4];
                #pragma unroll
                for (int mt = 0; mt < 4; mt++) LDSM4(af1[mt], aAddr[mt][ks] + soff + BLK_B);
                #pragma unroll
                for (int mt = 0; mt < 4; mt++)
                    #pragma unroll
                    for (int nt = 0; nt < 4; nt++)
                        MMA16816(acc[mt][nt], af1[mt], bf[nt >> 1][(nt & 1) * 2], bf[nt >> 1][(nt & 1) * 2 + 1]);
            }
            if (BTERMS == 2) {
                uint32_t bfl[2][4];
                #pragma unroll
                for (int nt2 = 0; nt2 < 2; nt2++) LDSM4(bfl[nt2], bAddr[nt2][ks] + soff + BLK_B);
                #pragma unroll
                for (int mt = 0; mt < 4; mt++)
                    #pragma unroll
                    for (int nt = 0; nt < 4; nt++)
                        MMA16816(acc[mt][nt], af0[mt], bfl[nt >> 1][(nt & 1) * 2], bfl[nt >> 1][(nt & 1) * 2 + 1]);
            }
        }
    }

    // ---- epilogue: direct from c-fragments ----
    const float* biasE = bias + (size_t)e * bStrideE;
    const int cq = (lane & 3) * 2;
    const int r0 = lane >> 2;
    float b2v[4][2];
    #pragma unroll
    for (int nt = 0; nt < 4; nt++) {
        int n = n0 + wn * 32 + nt * 8 + cq;
        b2v[nt][0] = biasE[n];
        b2v[nt][1] = biasE[n + 1];
    }

    #pragma unroll
    for (int mt = 0; mt < 4; mt++) {
        #pragma unroll
        for (int h = 0; h < 2; h++) {
            int row = m0 + wm * 64 + mt * 16 + r0 + h * 8;
            if (row >= M) continue;
            size_t erow = (size_t)e * CAP + row;
            float sc = 1.0f;
            int   tok = 0;
            if (flags & FLAG_DEST) {
                sc  = scales[erow];
                tok = dests[erow];
            }
            #pragma unroll
            for (int nt = 0; nt < 4; nt++) {
                int n = n0 + wn * 32 + nt * 8 + cq;
                float v0 = acc[mt][nt][h * 2]     + b2v[nt][0];
                float v1 = acc[mt][nt][h * 2 + 1] + b2v[nt][1];
                if (flags & FLAG_RELU) { v0 = fmaxf(v0, 0.0f); v1 = fmaxf(v1, 0.0f); }
                if (flags & FLAG_SPLIT) {
                    size_t blk = ((erow >> 7) * (size_t)(N >> 5) + (size_t)(n >> 5)) * BLK_EL;
                    *(__half2*)((__half*)outS + blk + sw_off((int)(erow & 127), n & 31)) =
                        __halves2half2(__float2half_rn(v0), __float2half_rn(v1));
                } else if (flags & FLAG_DEST) {
                    // out receives exactly 2 commutative fp32 adds per element -> deterministic
                    atomicAdd(outF + (size_t)tok * N + n,     v0 * sc);
                    atomicAdd(outF + (size_t)tok * N + n + 1, v1 * sc);
                } else {
                    float2 o2; o2.x = v0; o2.y = v1;
                    *(float2*)(outF + (size_t)row * N + n) = o2;
                }
            }
        }
    }
}

// ---------------- conversion / gather kernels ----------------
__global__ __launch_bounds__(256) void convert_x(const float* __restrict__ x,
                                                 unsigned short* __restrict__ xt,
                                                 int K, size_t total)
{
    size_t idx = (size_t)blockIdx.x * blockDim.x + threadIdx.x;
    if (idx >= total) return;
    size_t t = idx / K;
    int    k = (int)(idx % K);
    float v = x[idx];
    __half hi = __float2half_rn(v);
    __half lo = __float2half_rn(v - __half2float(hi));
    size_t blk = ((t >> 7) * (size_t)(K >> 5) + (size_t)(k >> 5)) * BLK_EL
               + sw_off((int)(t & 127), k & 31);
    ((__half*)xt)[blk]           = hi;
    ((__half*)xt)[XT_TERM + blk] = lo;
}

__global__ __launch_bounds__(256) void convert_w(const float* __restrict__ W,
                                                 unsigned short* __restrict__ Wt,
                                                 int K, int N, size_t termOff)
{
    const int e = blockIdx.z;
    __shared__ float t[32][33];
    const int n0 = blockIdx.x * 32;
    const int k0 = blockIdx.y * 32;
    const float* We = W + (size_t)e * K * N;
    #pragma unroll
    for (int j = 0; j < 4; j++) {
        int k = k0 + threadIdx.y + j * 8;
        t[threadIdx.y + j * 8][threadIdx.x] = We[(size_t)k * N + n0 + threadIdx.x];
    }
    __syncthreads();
    const size_t blkBase = (((size_t)e * (N >> 7) + (size_t)(n0 >> 7)) * (K >> 5) + (size_t)(k0 >> 5)) * BLK_EL;
    #pragma unroll
    for (int j = 0; j < 4; j++) {
        int n = n0 + threadIdx.y + j * 8;
        int k = k0 + threadIdx.x;
        float v = t[threadIdx.x][threadIdx.y + j * 8];
        __half hi = __float2half_rn(v);
        size_t off = blkBase + sw_off(n & 127, k & 31);
        ((__half*)Wt)[off] = hi;
        if (termOff) ((__half*)Wt)[termOff + off] = __float2half_rn(v - __half2float(hi));
    }
}

__global__ __launch_bounds__(256) void tile_gather_x(const float* __restrict__ x,
                                                     unsigned short* __restrict__ xg)
{
    const int e  = blockIdx.y;
    const int mt = blockIdx.x;
    const int M  = g_counts[e];
    const int m0 = mt * 128;
    if (m0 >= M) return;
    const int nrows = min(128, M - m0);
    const size_t base = ((size_t)(e * (CAP / 128) + mt) * (DIN / 32)) * BLK_EL;
    for (int idx = threadIdx.x; idx < nrows * DIN; idx += 256) {
        int row = idx >> 10;
        int k   = idx & (DIN - 1);
        int tok = g_tokens[e * CAP + m0 + row];
        float v = x[(size_t)tok * DIN + k];
        ((__half*)xg)[base + (size_t)(k >> 5) * BLK_EL + sw_off(row, k & 31)] = __float2half_rn(v);
    }
}

// b23 = b2 + bp
__global__ __launch_bounds__(256) void bias_fuse(const float* __restrict__ b2,
                                                 const float* __restrict__ bp,
                                                 float* __restrict__ b23)
{
    int i = blockIdx.x * blockDim.x + threadIdx.x;
    if (i < NE * HID) b23[i] = b2[i] + bp[i];
}

// zero the output (poisoned by harness; L4 accumulates atomically)
__global__ __launch_bounds__(256) void zero_out(float4* __restrict__ out, size_t n4)
{
    size_t i = (size_t)blockIdx.x * blockDim.x + threadIdx.x;
    if (i < n4) out[i] = make_float4(0.f, 0.f, 0.f, 0.f);
}

// ---------------- gating logits: one warp per token, N=8 ----------------
__global__ __launch_bounds__(256) void logits_kernel(
    const float* __restrict__ h, const float* __restrict__ gw2,
    const float* __restrict__ gb2, float* __restrict__ logits)
{
    int warp = (blockIdx.x * blockDim.x + threadIdx.x) >> 5;
    int lane = threadIdx.x & 31;
    if (warp >= B_TOK) return;
    const float4* hrow = (const float4*)(h + (size_t)warp * GHID);
    float acc[NE];
    #pragma unroll
    for (int e = 0; e < NE; e++) acc[e] = 0.0f;
    for (int i = lane; i < GHID / 4; i += 32) {
        float4 hv = hrow[i];
        const float* g = gw2 + (size_t)(i * 4) * NE;
        #pragma unroll
        for (int e = 0; e < NE; e++)
            acc[e] += hv.x * g[e] + hv.y * g[NE + e] + hv.z * g[2 * NE + e] + hv.w * g[3 * NE + e];
    }
    #pragma unroll
    for (int e = 0; e < NE; e++)
        #pragma unroll
        for (int off = 16; off > 0; off >>= 1)
            acc[e] += __shfl_xor_sync(0xFFFFFFFFu, acc[e], off);
    if (lane == 0) {
        #pragma unroll
        for (int e = 0; e < NE; e++)
            logits[(size_t)warp * NE + e] = acc[e] + gb2[e];
    }
}

// ---------------- routing ----------------
__global__ void init_kernel() {
    if (threadIdx.x < NE) g_counts[threadIdx.x] = 0;
}

__global__ __launch_bounds__(256) void route_kernel() {
    int t = blockIdx.x * blockDim.x + threadIdx.x;
    if (t >= B_TOK) return;
    float v[NE];
    #pragma unroll
    for (int e = 0; e < NE; e++) v[e] = g_logits[(size_t)t * NE + e];
    int i0 = 0;
    #pragma unroll
    for (int e = 1; e < NE; e++) if (v[e] > v[i0]) i0 = e;
    int i1 = (i0 == 0) ? 1 : 0;
    #pragma unroll
    for (int e = 0; e < NE; e++) if (e != i0 && v[e] > v[i1]) i1 = e;
    float b = __expf(v[i1] - v[i0]);
    float s = 1.0f + b;
    float w0 = 1.0f / s;
    float w1 = b / s;

    int p0 = atomicAdd(&g_counts[i0], 1);
    g_tokens[i0 * CAP + p0] = t;
    g_wts[i0 * CAP + p0]    = w0;
    g_dests[i0 * CAP + p0]  = t;

    int p1 = atomicAdd(&g_counts[i1], 1);
    g_tokens[i1 * CAP + p1] = t;
    g_wts[i1 * CAP + p1]    = w1;
    g_dests[i1 * CAP + p1]  = t;
}

// ---------------- host ----------------
#define NST_E 6
#define DSM_E (NST_E * 2 * BLK_B + 64)      // 98368; x2 CTAs/SM
#define DSM_G (3 * 4 * BLK_B + 64)          // 98368; x2 CTAs/SM

extern "C" void kernel_launch(void* const* d_in, const int* in_sizes, int n_in,
                              void* d_out, int out_size) {
    const float* x   = (const float*)d_in[0];
    const float* w1  = (const float*)d_in[1];
    const float* b1  = (const float*)d_in[2];
    const float* w2  = (const float*)d_in[3];
    const float* b2  = (const float*)d_in[4];
    const float* w3  = (const float*)d_in[5];
    const float* b3  = (const float*)d_in[6];
    const float* wp  = (const float*)d_in[7];
    const float* bp  = (const float*)d_in[8];
    const float* gw1 = (const float*)d_in[9];
    const float* gb1 = (const float*)d_in[10];
    const float* gw2 = (const float*)d_in[11];
    const float* gb2 = (const float*)d_in[12];
    float* out = (float*)d_out;

    unsigned short *p_xt, *p_gwt, *p_xg, *p_w1t, *p_wpt, *p_w2t, *p_w3t, *p_hst, *p_ost;
    float *p_b23, *p_hidden, *p_logits, *p_wts;
    int *p_counts, *p_tokens, *p_dests;
    cudaGetSymbolAddress((void**)&p_xt,     g_xt);
    cudaGetSymbolAddress((void**)&p_gwt,    g_gwt);
    cudaGetSymbolAddress((void**)&p_xg,     g_xg);
    cudaGetSymbolAddress((void**)&p_w1t,    g_w1t);
    cudaGetSymbolAddress((void**)&p_wpt,    g_wpt);
    cudaGetSymbolAddress((void**)&p_w2t,    g_w2t);
    cudaGetSymbolAddress((void**)&p_w3t,    g_w3t);
    cudaGetSymbolAddress((void**)&p_hst,    g_hst);
    cudaGetSymbolAddress((void**)&p_ost,    g_ost);
    cudaGetSymbolAddress((void**)&p_b23,    g_b23);
    cudaGetSymbolAddress((void**)&p_hidden, g_hidden);
    cudaGetSymbolAddress((void**)&p_logits, g_logits);
    cudaGetSymbolAddress((void**)&p_wts,    g_wts);
    cudaGetSymbolAddress((void**)&p_counts, g_counts);
    cudaGetSymbolAddress((void**)&p_tokens, g_tokens);
    cudaGetSymbolAddress((void**)&p_dests,  g_dests);

    cudaFuncSetAttribute((const void*)mma_gemm<1,1,NST_E>,
                         cudaFuncAttributeMaxDynamicSharedMemorySize, DSM_E);
    cudaFuncSetAttribute((const void*)mma_gemm<2,2,3>,
                         cudaFuncAttributeMaxDynamicSharedMemorySize, DSM_G);

    // zero output (L4 accumulates atomically)
    {
        size_t n4 = (size_t)B_TOK * DOUT / 4;
        zero_out<<<(unsigned)((n4 + 255) / 256), 256>>>((float4*)out, n4);
    }

    // conversions (tiled swizzled layouts)
    {
        size_t total = (size_t)B_TOK * DIN;
        convert_x<<<(unsigned)((total + 255) / 256), 256>>>(x, p_xt, DIN, total);
    }
    convert_w<<<dim3(HID / 32, DIN / 32, NE),  dim3(32, 8)>>>(w1,  p_w1t, DIN, HID,  0);
    convert_w<<<dim3(HID / 32, DIN / 32, NE),  dim3(32, 8)>>>(wp,  p_wpt, DIN, HID,  0);
    convert_w<<<dim3(HID / 32, HID / 32, NE),  dim3(32, 8)>>>(w2,  p_w2t, HID, HID,  0);
    convert_w<<<dim3(DOUT / 32, HID / 32, NE), dim3(32, 8)>>>(w3,  p_w3t, HID, DOUT, 0);
    convert_w<<<dim3(GHID / 32, DIN / 32, 1),  dim3(32, 8)>>>(gw1, p_gwt, DIN, GHID, GWT_TERM);
    bias_fuse<<<(NE * HID + 255) / 256, 256>>>(b2, bp, p_b23);

    // G1: gating hidden = relu(x @ gw1 + gb1), 3-term (err ~2^-22, exact routing)
    mma_gemm<2,2,3><<<dim3(GHID / BN, B_TOK / BM, 1), 256, DSM_G>>>(
        p_xt, XT_TERM, nullptr, B_TOK / 128,
        p_gwt, GWT_TERM, nullptr,
        gb1, 0,
        p_hidden, nullptr, nullptr, nullptr, nullptr, B_TOK,
        DIN / 32, DIN / 32, GHID, FLAG_RELU);

    // G2 + routing
    logits_kernel<<<B_TOK / 8, 256>>>(p_hidden, gw2, gb2, p_logits);
    init_kernel<<<1, 32>>>();
    route_kernel<<<B_TOK / 256, 256>>>();

    // gather routed x into tiled layout
    tile_gather_x<<<dim3(CAP / 128, NE), 256>>>(x, p_xg);

    // L1: h = relu(x_g @ w1 + b1) -> tiled fp16
    mma_gemm<1,1,NST_E><<<dim3(HID / BN, CAP / BM, NE), 256, DSM_E>>>(
        p_xg, 0, nullptr, CAP / 128,
        p_w1t, 0, nullptr,
        b1, HID,
        nullptr, p_hst, nullptr, nullptr, p_counts, 0,
        DIN / 32, DIN / 32, HID, FLAG_RELU | FLAG_SPLIT);

    // L3 (L2 fused via K-concat): o = relu([h|x_g] @ [w2;wp] + b2+bp) -> tiled fp16
    mma_gemm<1,1,NST_E><<<dim3(HID / BN, CAP / BM, NE), 256, DSM_E>>>(
        p_hst, 0, p_xg, CAP / 128,
        p_w2t, 0, p_wpt,
        p_b23, HID,
        nullptr, p_ost, nullptr, nullptr, p_counts, 0,
        (HID + DIN) / 32, HID / 32, HID, FLAG_RELU | FLAG_SPLIT);

    // L4: out[tok] += (o @ w3 + b3) * gate_w   (atomic, 2 adds per element)
    mma_gemm<1,1,NST_E><<<dim3(DOUT / BN, CAP / BM, NE), 256, DSM_E>>>(
        p_ost, 0, nullptr, CAP / 128,
        p_w3t, 0, nullptr,
        b3, DOUT,
        out, nullptr, p_wts, p_dests, p_counts, 0,
        HID / 32, HID / 32, DOUT, FLAG_DEST);
}

// round 12
// speedup vs baseline: 4.0368x; 1.1839x over previous
#include <cuda_runtime.h>
#include <cuda_fp16.h>
#include <cstdint>

// ---------------- problem constants ----------------
#define B_TOK 8192
#define DIN   1024
#define HID   2048
#define DOUT  1024
#define NE    8
#define GHID  1024
#define CAP   8192

#define FLAG_RELU  1
#define FLAG_SPLIT 4
#define FLAG_DEST  8

// ---------------- tile geometry (packed 64B rows + XOR swizzle) ----------------
#define BM 128
#define BN 128
#define BK 32
#define BLK_B  8192               // block bytes: 128 rows x 64B (packed)
#define BLK_EL 4096

// element offset of (row r, col c) inside a 128x32 block, swizzled:
// physical 16B-chunk = (c>>3) ^ ((r>>1)&3)
__device__ __forceinline__ uint32_t sw_off(int r, int c) {
    return (uint32_t)(r * 32 + ((((c >> 3) ^ ((r >> 1) & 3)) << 3) | (c & 7)));
}

#define XT_TERM  ((size_t)(B_TOK/128) * (DIN/32) * BLK_EL)
#define GWT_TERM ((size_t)(GHID/128)  * (DIN/32) * BLK_EL)

// ---------------- scratch (static device globals; 128B aligned for bulk) ----------------
__device__ __align__(128) unsigned short g_xt [2*XT_TERM];                      // x tiled [hi|lo] (G1)
__device__ __align__(128) unsigned short g_gwt[2*GWT_TERM];                     // gw1^T tiled [hi|lo]
__device__ __align__(128) unsigned short g_xg [(size_t)NE*(CAP/128)*(DIN/32)*BLK_EL];  // gathered x tiled
__device__ __align__(128) unsigned short g_w1t[(size_t)NE*(HID/128)*(DIN/32)*BLK_EL];
__device__ __align__(128) unsigned short g_wpt[(size_t)NE*(HID/128)*(DIN/32)*BLK_EL];
__device__ __align__(128) unsigned short g_w2t[(size_t)NE*(HID/128)*(HID/32)*BLK_EL];
__device__ __align__(128) unsigned short g_w3t[(size_t)NE*(DOUT/128)*(HID/32)*BLK_EL];
__device__ __align__(128) unsigned short g_hst[(size_t)NE*(CAP/128)*(HID/32)*BLK_EL]; // h tiled
__device__ __align__(128) unsigned short g_ost[(size_t)NE*(CAP/128)*(HID/32)*BLK_EL]; // o tiled
__device__ float g_lpart [(size_t)(GHID/128)*B_TOK*NE];     // partial logits per G1 n-tile
__device__ float g_b23   [(size_t)NE*HID];                  // b2 + bp fused bias
__device__ float g_logits[(size_t)B_TOK*NE];
__device__ int   g_counts[NE];
__device__ int   g_tokens[(size_t)NE*CAP];
__device__ float g_wts   [(size_t)NE*CAP];
__device__ int   g_dests [(size_t)NE*CAP];                  // token index per (expert,row)

// ---------------- PTX helpers (sm_90 baseline features only) ----------------
__device__ __forceinline__ uint32_t smem_u32(const void* p) {
    uint32_t a;
    asm("{ .reg .u64 t; cvta.to.shared.u64 t, %1; cvt.u32.u64 %0, t; }" : "=r"(a) : "l"(p));
    return a;
}
#define BULK_G2S(dst, src, nbytes, mbar) \
    asm volatile("cp.async.bulk.shared::cluster.global.mbarrier::complete_tx::bytes [%0], [%1], %2, [%3];" \
        :: "r"(dst), "l"(src), "r"(nbytes), "r"(mbar) : "memory")
#define MBAR_INIT(addr, cnt) \
    asm volatile("mbarrier.init.shared.b64 [%0], %1;" :: "r"(addr), "r"(cnt) : "memory")
#define MBAR_EXPECT_TX(addr, tx) \
    asm volatile("mbarrier.arrive.expect_tx.shared.b64 _, [%0], %1;" :: "r"(addr), "r"(tx) : "memory")
__device__ __forceinline__ void mbar_wait(uint32_t addr, uint32_t parity) {
    asm volatile("{\n\t.reg .pred P;\n"
        "LW%=:\n\tmbarrier.try_wait.parity.acquire.cta.shared::cta.b64 P, [%0], %1, 0x989680;\n"
        "\t@!P bra LW%=;\n\t}" :: "r"(addr), "r"(parity) : "memory");
}
#define LDSM4(r, addr) \
    asm volatile("ldmatrix.sync.aligned.m8n8.x4.shared.b16 {%0,%1,%2,%3}, [%4];" \
        : "=r"((r)[0]), "=r"((r)[1]), "=r"((r)[2]), "=r"((r)[3]) : "r"(addr))
#define MMA16816(d, a, b0, b1) \
    asm volatile("mma.sync.aligned.m16n8k16.row.col.f32.f16.f16.f32 " \
        "{%0,%1,%2,%3},{%4,%5,%6,%7},{%8,%9},{%0,%1,%2,%3};" \
        : "+f"((d)[0]), "+f"((d)[1]), "+f"((d)[2]), "+f"((d)[3]) \
        : "r"((a)[0]), "r"((a)[1]), "r"((a)[2]), "r"((a)[3]), "r"(b0), "r"(b1))

// ---------------- HMMA GEMM: tile 128x128x32, bulk tiled operands ----------------
// KPS k-blocks per pipeline stage (halves sync overhead). Segmented K via kcSplit.
// LG=1: gating epilogue — compute partial logits relu(v)·gw2 instead of storing.
// Stage layout: A term t, kb -> (t*KPS+kb)*BLK_B ; B term t, kb -> ((ATERMS+t)*KPS+kb)*BLK_B.
template<int ATERMS, int BTERMS, int NSTAGES, int KPS, int LG>
__global__ __launch_bounds__(256, 2) void mma_gemm(
    const unsigned short* __restrict__ Atiled, size_t aTermOff,
    const unsigned short* __restrict__ At2, int aMtPerE,
    const unsigned short* __restrict__ Btiled, size_t bTermOff,
    const unsigned short* __restrict__ Bt2,
    const float* __restrict__ bias, int bStrideE,
    float* __restrict__ outF, unsigned short* __restrict__ outS,
    const float* __restrict__ scales, const int* __restrict__ dests,
    const int* __restrict__ counts, int Mfixed,
    int KPC, int kcSplit, int N, int flags)
{
    constexpr uint32_t STAGE_B = (ATERMS + BTERMS) * KPS * BLK_B;

    const int e  = blockIdx.z;
    const int M  = counts ? counts[e] : Mfixed;
    const int m0 = blockIdx.y * BM;
    if (m0 >= M) return;
    const int n0 = blockIdx.x * BN;

    const int NT   = N >> 7;
    const int kpc2 = KPC - kcSplit;

    extern __shared__ char smem[];
    const uint32_t sbase = smem_u32(smem);
    const uint32_t mbar0 = sbase + NSTAGES * STAGE_B;

    const int tid  = threadIdx.x;
    const int wid  = tid >> 5;
    const int lane = tid & 31;

    const size_t aTile = (size_t)(e * aMtPerE + blockIdx.y);
    const size_t bTile = (size_t)(e * NT + blockIdx.x);

    if (tid == 0) {
        #pragma unroll
        for (int s = 0; s < NSTAGES; s++) MBAR_INIT(mbar0 + s * 8, 1);
    }
    __syncthreads();

    // ---- fragment smem addresses (kb=0, term0): warp tile 64x32, swizzled chunks ----
    const int wm = wid & 1;
    const int wn = wid >> 1;
    uint32_t aAddr[4][2], bAddr[2][2];
    {
        int arow0 = wm * 64 + (lane & 15);
        int alc0  = (lane >> 4);
        int brow0 = wn * 32 + ((lane >> 4) * 8) + (lane & 7);
        int blc0  = ((lane >> 3) & 1);
        #pragma unroll
        for (int ks = 0; ks < 2; ks++) {
            #pragma unroll
            for (int mt = 0; mt < 4; mt++) {
                int r  = arow0 + mt * 16;
                int pc = (ks * 2 + alc0) ^ ((r >> 1) & 3);
                aAddr[mt][ks] = sbase + (uint32_t)(r * 64 + pc * 16);
            }
            #pragma unroll
            for (int nt2 = 0; nt2 < 2; nt2++) {
                int r  = brow0 + nt2 * 16;
                int pc = (ks * 2 + blc0) ^ ((r >> 1) & 3);
                bAddr[nt2][ks] = sbase + ATERMS * KPS * BLK_B + (uint32_t)(r * 64 + pc * 16);
            }
        }
    }

    float acc[4][4][4];
    #pragma unroll
    for (int mt = 0; mt < 4; mt++)
        #pragma unroll
        for (int nt = 0; nt < 4; nt++)
            #pragma unroll
            for (int k = 0; k < 4; k++) acc[mt][nt][k] = 0.0f;

    const int NITS = KPC / KPS;

    auto load_stage = [&](int s, int sit) {
        if (tid == 0) {
            const uint32_t stg = sbase + s * STAGE_B;
            const uint32_t mb = mbar0 + s * 8;
            MBAR_EXPECT_TX(mb, STAGE_B);
            #pragma unroll
            for (int kb = 0; kb < KPS; kb++) {
                int gk = sit * KPS + kb;
                const unsigned short* aSrc;
                const unsigned short* bSrc;
                if (gk < kcSplit) {
                    aSrc = Atiled + (aTile * kcSplit + gk) * BLK_EL;
                    bSrc = Btiled + (bTile * kcSplit + gk) * BLK_EL;
                } else {
                    aSrc = At2 + (aTile * kpc2 + (gk - kcSplit)) * BLK_EL;
                    bSrc = Bt2 + (bTile * kpc2 + (gk - kcSplit)) * BLK_EL;
                }
                BULK_G2S(stg + kb * BLK_B, aSrc, BLK_B, mb);
                if (ATERMS == 2)
                    BULK_G2S(stg + (KPS + kb) * BLK_B,
                             Atiled + aTermOff + (aTile * kcSplit + gk) * BLK_EL, BLK_B, mb);
                BULK_G2S(stg + (ATERMS * KPS + kb) * BLK_B, bSrc, BLK_B, mb);
                if (BTERMS == 2)
                    BULK_G2S(stg + ((ATERMS + 1) * KPS + kb) * BLK_B,
                             Btiled + bTermOff + (bTile * kcSplit + gk) * BLK_EL, BLK_B, mb);
            }
        }
    };

    #pragma unroll
    for (int s = 0; s < NSTAGES - 1; s++)
        if (s < NITS) load_stage(s, s);

    for (int sit = 0; sit < NITS; sit++) {
        mbar_wait(mbar0 + (sit % NSTAGES) * 8, (sit / NSTAGES) & 1);
        __syncthreads();
        if (sit + NSTAGES - 1 < NITS) load_stage((sit + NSTAGES - 1) % NSTAGES, sit + NSTAGES - 1);

        const uint32_t soff = (sit % NSTAGES) * STAGE_B;
        #pragma unroll
        for (int kb = 0; kb < KPS; kb++) {
            const uint32_t ko = soff + kb * BLK_B;
            #pragma unroll
            for (int ks = 0; ks < 2; ks++) {
                uint32_t af0[4][4], bf[2][4];
                #pragma unroll
                for (int mt = 0; mt < 4; mt++) LDSM4(af0[mt], aAddr[mt][ks] + ko);
                #pragma unroll
                for (int nt2 = 0; nt2 < 2; nt2++) LDSM4(bf[nt2], bAddr[nt2][ks] + ko);
                #pragma unroll
                for (int mt = 0; mt < 4; mt++)
                    #pragma unroll
                    for (int nt = 0; nt < 4; nt++)
                        MMA16816(acc[mt][nt], af0[mt], bf[nt >> 1][(nt & 1) * 2], bf[nt >> 1][(nt & 1) * 2 + 1]);
                if (ATERMS == 2) {
                    uint32_t af1[4][4];
                    #pragma unroll
                    for (int mt = 0; mt < 4; mt++) LDSM4(af1[mt], aAddr[mt][ks] + ko + KPS * BLK_B);
                    #pragma unroll
                    for (int mt = 0; mt < 4; mt++)
                        #pragma unroll
                        for (int nt = 0; nt < 4; nt++)
                            MMA16816(acc[mt][nt], af1[mt], bf[nt >> 1][(nt & 1) * 2], bf[nt >> 1][(nt & 1) * 2 + 1]);
                }
                if (BTERMS == 2) {
                    uint32_t bfl[2][4];
                    #pragma unroll
                    for (int nt2 = 0; nt2 < 2; nt2++) LDSM4(bfl[nt2], bAddr[nt2][ks] + ko + KPS * BLK_B);
                    #pragma unroll
                    for (int mt = 0; mt < 4; mt++)
                        #pragma unroll
                        for (int nt = 0; nt < 4; nt++)
                            MMA16816(acc[mt][nt], af0[mt], bfl[nt >> 1][(nt & 1) * 2], bfl[nt >> 1][(nt & 1) * 2 + 1]);
                }
            }
        }
    }

    // ---- epilogue ----
    const float* biasE = bias + (size_t)e * bStrideE;
    const int cq = (lane & 3) * 2;
    const int r0 = lane >> 2;
    float b2v[4][2];
    #pragma unroll
    for (int nt = 0; nt < 4; nt++) {
        int n = n0 + wn * 32 + nt * 8 + cq;
        b2v[nt][0] = biasE[n];
        b2v[nt][1] = biasE[n + 1];
    }

    if (LG) {
        // gating epilogue: partial logits = relu(v) . gw2  (scales == gw2 [GHID][NE])
        float* sp = (float*)(smem + NSTAGES * STAGE_B + 64);   // [4 wn][128 rows][NE]
        const float* gw2p = scales;
        #pragma unroll
        for (int mt = 0; mt < 4; mt++) {
            #pragma unroll
            for (int h = 0; h < 2; h++) {
                int row = wm * 64 + mt * 16 + r0 + h * 8;   // local row 0..127
                float p[NE];
                #pragma unroll
                for (int e2 = 0; e2 < NE; e2++) p[e2] = 0.0f;
                #pragma unroll
                for (int nt = 0; nt < 4; nt++) {
                    int n = n0 + wn * 32 + nt * 8 + cq;
                    float v0 = acc[mt][nt][h * 2]     + b2v[nt][0];
                    float v1 = acc[mt][nt][h * 2 + 1] + b2v[nt][1];
                    v0 = fmaxf(v0, 0.0f); v1 = fmaxf(v1, 0.0f);
                    const float* ga = gw2p + (size_t)n * NE;
                    #pragma unroll
                    for (int e2 = 0; e2 < NE; e2++)
                        p[e2] += v0 * ga[e2] + v1 * ga[NE + e2];
                }
                // reduce over the 4 lanes sharing this row (lanes 4*r0 .. 4*r0+3)
                #pragma unroll
                for (int e2 = 0; e2 < NE; e2++) {
                    p[e2] += __shfl_xor_sync(0xFFFFFFFFu, p[e2], 1);
                    p[e2] += __shfl_xor_sync(0xFFFFFFFFu, p[e2], 2);
                }
                if ((lane & 3) == 0) {
                    #pragma unroll
                    for (int e2 = 0; e2 < NE; e2++)
                        sp[((wn * 128) + row) * NE + e2] = p[e2];
                }
            }
        }
        __syncthreads();
        for (int idx = tid; idx < 128 * NE; idx += 256) {
            int row = idx >> 3, e2 = idx & 7;
            float s = sp[row * NE + e2] + sp[(128 + row) * NE + e2]
                    + sp[(256 + row) * NE + e2] + sp[(384 + row) * NE + e2];
            outF[(size_t)blockIdx.x * B_TOK * NE + (size_t)(m0 + row) * NE + e2] = s;
        }
        return;
    }

    #pragma unroll
    for (int mt = 0; mt < 4; mt++) {
        #pragma unroll
        for (int h = 0; h < 2; h++) {
            int row = m0 + wm * 64 + mt * 16 + r0 + h * 8;
            if (row >= M) continue;
            size_t erow = (size_t)e * CAP + row;
            float sc = 1.0f;
            int   tok = 0;
            if (flags & FLAG_DEST) {
                sc  = scales[erow];
                tok = dests[erow];
            }
            #pragma unroll
            for (int nt = 0; nt < 4; nt++) {
                int n = n0 + wn * 32 + nt * 8 + cq;
                float v0 = acc[mt][nt][h * 2]     + b2v[nt][0];
                float v1 = acc[mt][nt][h * 2 + 1] + b2v[nt][1];
                if (flags & FLAG_RELU) { v0 = fmaxf(v0, 0.0f); v1 = fmaxf(v1, 0.0f); }
                if (flags & FLAG_SPLIT) {
                    size_t blk = ((erow >> 7) * (size_t)(N >> 5) + (size_t)(n >> 5)) * BLK_EL;
                    *(__half2*)((__half*)outS + blk + sw_off((int)(erow & 127), n & 31)) =
                        __halves2half2(__float2half_rn(v0), __float2half_rn(v1));
                } else if (flags & FLAG_DEST) {
                    atomicAdd(outF + (size_t)tok * N + n,     v0 * sc);
                    atomicAdd(outF + (size_t)tok * N + n + 1, v1 * sc);
                } else {
                    float2 o2; o2.x = v0; o2.y = v1;
                    *(float2*)(outF + (size_t)row * N + n) = o2;
                }
            }
        }
    }
}

// ---------------- conversion / gather kernels ----------------
__global__ __launch_bounds__(256) void convert_x(const float* __restrict__ x,
                                                 unsigned short* __restrict__ xt,
                                                 int K, size_t total)
{
    size_t idx = (size_t)blockIdx.x * blockDim.x + threadIdx.x;
    if (idx >= total) return;
    size_t t = idx / K;
    int    k = (int)(idx % K);
    float v = x[idx];
    __half hi = __float2half_rn(v);
    __half lo = __float2half_rn(v - __half2float(hi));
    size_t blk = ((t >> 7) * (size_t)(K >> 5) + (size_t)(k >> 5)) * BLK_EL
               + sw_off((int)(t & 127), k & 31);
    ((__half*)xt)[blk]           = hi;
    ((__half*)xt)[XT_TERM + blk] = lo;
}

__global__ __launch_bounds__(256) void convert_w(const float* __restrict__ W,
                                                 unsigned short* __restrict__ Wt,
                                                 int K, int N, size_t termOff)
{
    const int e = blockIdx.z;
    __shared__ float t[32][33];
    const int n0 = blockIdx.x * 32;
    const int k0 = blockIdx.y * 32;
    const float* We = W + (size_t)e * K * N;
    #pragma unroll
    for (int j = 0; j < 4; j++) {
        int k = k0 + threadIdx.y + j * 8;
        t[threadIdx.y + j * 8][threadIdx.x] = We[(size_t)k * N + n0 + threadIdx.x];
    }
    __syncthreads();
    const size_t blkBase = (((size_t)e * (N >> 7) + (size_t)(n0 >> 7)) * (K >> 5) + (size_t)(k0 >> 5)) * BLK_EL;
    #pragma unroll
    for (int j = 0; j < 4; j++) {
        int n = n0 + threadIdx.y + j * 8;
        int k = k0 + threadIdx.x;
        float v = t[threadIdx.x][threadIdx.y + j * 8];
        __half hi = __float2half_rn(v);
        size_t off = blkBase + sw_off(n & 127, k & 31);
        ((__half*)Wt)[off] = hi;
        if (termOff) ((__half*)Wt)[termOff + off] = __float2half_rn(v - __half2float(hi));
    }
}

__global__ __launch_bounds__(256) void tile_gather_x(const float* __restrict__ x,
                                                     unsigned short* __restrict__ xg)
{
    const int e  = blockIdx.y;
    const int mt = blockIdx.x;
    const int M  = g_counts[e];
    const int m0 = mt * 128;
    if (m0 >= M) return;
    const int nrows = min(128, M - m0);
    const size_t base = ((size_t)(e * (CAP / 128) + mt) * (DIN / 32)) * BLK_EL;
    for (int idx = threadIdx.x; idx < nrows * DIN; idx += 256) {
        int row = idx >> 10;
        int k   = idx & (DIN - 1);
        int tok = g_tokens[e * CAP + m0 + row];
        float v = x[(size_t)tok * DIN + k];
        ((__half*)xg)[base + (size_t)(k >> 5) * BLK_EL + sw_off(row, k & 31)] = __float2half_rn(v);
    }
}

// b23 = b2 + bp
__global__ __launch_bounds__(256) void bias_fuse(const float* __restrict__ b2,
                                                 const float* __restrict__ bp,
                                                 float* __restrict__ b23)
{
    int i = blockIdx.x * blockDim.x + threadIdx.x;
    if (i < NE * HID) b23[i] = b2[i] + bp[i];
}

// zero the output (poisoned by harness; L4 accumulates atomically)
__global__ __launch_bounds__(256) void zero_out(float4* __restrict__ out, size_t n4)
{
    size_t i = (size_t)blockIdx.x * blockDim.x + threadIdx.x;
    if (i < n4) out[i] = make_float4(0.f, 0.f, 0.f, 0.f);
}

// logits[t][e] = sum over 8 n-tiles of lpart + gb2[e]
__global__ __launch_bounds__(256) void logits_reduce(const float* __restrict__ lpart,
                                                     const float* __restrict__ gb2,
                                                     float* __restrict__ logits)
{
    int idx = blockIdx.x * blockDim.x + threadIdx.x;
    if (idx >= B_TOK * NE) return;
    float s = gb2[idx & 7];
    #pragma unroll
    for (int bx = 0; bx < GHID / 128; bx++)
        s += lpart[(size_t)bx * B_TOK * NE + idx];
    logits[idx] = s;
}

// ---------------- routing ----------------
__global__ void init_kernel() {
    if (threadIdx.x < NE) g_counts[threadIdx.x] = 0;
}

__global__ __launch_bounds__(256) void route_kernel() {
    int t = blockIdx.x * blockDim.x + threadIdx.x;
    if (t >= B_TOK) return;
    float v[NE];
    #pragma unroll
    for (int e = 0; e < NE; e++) v[e] = g_logits[(size_t)t * NE + e];
    int i0 = 0;
    #pragma unroll
    for (int e = 1; e < NE; e++) if (v[e] > v[i0]) i0 = e;
    int i1 = (i0 == 0) ? 1 : 0;
    #pragma unroll
    for (int e = 0; e < NE; e++) if (e != i0 && v[e] > v[i1]) i1 = e;
    float b = __expf(v[i1] - v[i0]);
    float s = 1.0f + b;
    float w0 = 1.0f / s;
    float w1 = b / s;

    int p0 = atomicAdd(&g_counts[i0], 1);
    g_tokens[i0 * CAP + p0] = t;
    g_wts[i0 * CAP + p0]    = w0;
    g_dests[i0 * CAP + p0]  = t;

    int p1 = atomicAdd(&g_counts[i1], 1);
    g_tokens[i1 * CAP + p1] = t;
    g_wts[i1 * CAP + p1]    = w1;
    g_dests[i1 * CAP + p1]  = t;
}

// ---------------- host ----------------
#define NST_E 3
#define KPS_E 2
#define DSM_E (NST_E * 2 * KPS_E * BLK_B + 64)              // 98368; 2 CTAs/SM
#define DSM_G (2 * 4 * BLK_B + 64 + 4 * 128 * NE * 4)       // 65536+64+16384 = 81984; 2 CTAs/SM

extern "C" void kernel_launch(void* const* d_in, const int* in_sizes, int n_in,
                              void* d_out, int out_size) {
    const float* x   = (const float*)d_in[0];
    const float* w1  = (const float*)d_in[1];
    const float* b1  = (const float*)d_in[2];
    const float* w2  = (const float*)d_in[3];
    const float* b2  = (const float*)d_in[4];
    const float* w3  = (const float*)d_in[5];
    const float* b3  = (const float*)d_in[6];
    const float* wp  = (const float*)d_in[7];
    const float* bp  = (const float*)d_in[8];
    const float* gw1 = (const float*)d_in[9];
    const float* gb1 = (const float*)d_in[10];
    const float* gw2 = (const float*)d_in[11];
    const float* gb2 = (const float*)d_in[12];
    float* out = (float*)d_out;

    unsigned short *p_xt, *p_gwt, *p_xg, *p_w1t, *p_wpt, *p_w2t, *p_w3t, *p_hst, *p_ost;
    float *p_lpart, *p_b23, *p_logits, *p_wts;
    int *p_counts, *p_tokens, *p_dests;
    cudaGetSymbolAddress((void**)&p_xt,     g_xt);
    cudaGetSymbolAddress((void**)&p_gwt,    g_gwt);
    cudaGetSymbolAddress((void**)&p_xg,     g_xg);
    cudaGetSymbolAddress((void**)&p_w1t,    g_w1t);
    cudaGetSymbolAddress((void**)&p_wpt,    g_wpt);
    cudaGetSymbolAddress((void**)&p_w2t,    g_w2t);
    cudaGetSymbolAddress((void**)&p_w3t,    g_w3t);
    cudaGetSymbolAddress((void**)&p_hst,    g_hst);
    cudaGetSymbolAddress((void**)&p_ost,    g_ost);
    cudaGetSymbolAddress((void**)&p_lpart,  g_lpart);
    cudaGetSymbolAddress((void**)&p_b23,    g_b23);
    cudaGetSymbolAddress((void**)&p_logits, g_logits);
    cudaGetSymbolAddress((void**)&p_wts,    g_wts);
    cudaGetSymbolAddress((void**)&p_counts, g_counts);
    cudaGetSymbolAddress((void**)&p_tokens, g_tokens);
    cudaGetSymbolAddress((void**)&p_dests,  g_dests);

    cudaFuncSetAttribute((const void*)mma_gemm<1,1,NST_E,KPS_E,0>,
                         cudaFuncAttributeMaxDynamicSharedMemorySize, DSM_E);
    cudaFuncSetAttribute((const void*)mma_gemm<2,2,2,1,1>,
                         cudaFuncAttributeMaxDynamicSharedMemorySize, DSM_G);

    // zero output (L4 accumulates atomically)
    {
        size_t n4 = (size_t)B_TOK * DOUT / 4;
        zero_out<<<(unsigned)((n4 + 255) / 256), 256>>>((float4*)out, n4);
    }

    // conversions (tiled swizzled layouts)
    {
        size_t total = (size_t)B_TOK * DIN;
        convert_x<<<(unsigned)((total + 255) / 256), 256>>>(x, p_xt, DIN, total);
    }
    convert_w<<<dim3(HID / 32, DIN / 32, NE),  dim3(32, 8)>>>(w1,  p_w1t, DIN, HID,  0);
    convert_w<<<dim3(HID / 32, DIN / 32, NE),  dim3(32, 8)>>>(wp,  p_wpt, DIN, HID,  0);
    convert_w<<<dim3(HID / 32, HID / 32, NE),  dim3(32, 8)>>>(w2,  p_w2t, HID, HID,  0);
    convert_w<<<dim3(DOUT / 32, HID / 32, NE), dim3(32, 8)>>>(w3,  p_w3t, HID, DOUT, 0);
    convert_w<<<dim3(GHID / 32, DIN / 32, 1),  dim3(32, 8)>>>(gw1, p_gwt, DIN, GHID, GWT_TERM);
    bias_fuse<<<(NE * HID + 255) / 256, 256>>>(b2, bp, p_b23);

    // G1: 3-term gating GEMM with fused partial-logit epilogue (relu(x@gw1+gb1)·gw2)
    mma_gemm<2,2,2,1,1><<<dim3(GHID / BN, B_TOK / BM, 1), 256, DSM_G>>>(
        p_xt, XT_TERM, nullptr, B_TOK / 128,
        p_gwt, GWT_TERM, nullptr,
        gb1, 0,
        p_lpart, nullptr, gw2, nullptr, nullptr, B_TOK,
        DIN / 32, DIN / 32, GHID, FLAG_RELU);

    // logits = sum(lpart) + gb2 ; routing
    logits_reduce<<<(B_TOK * NE + 255) / 256, 256>>>(p_lpart, gb2, p_logits);
    init_kernel<<<1, 32>>>();
    route_kernel<<<B_TOK / 256, 256>>>();

    // gather routed x into tiled layout
    tile_gather_x<<<dim3(CAP / 128, NE), 256>>>(x, p_xg);

    // L1: h = relu(x_g @ w1 + b1) -> tiled fp16
    mma_gemm<1,1,NST_E,KPS_E,0><<<dim3(HID / BN, CAP / BM, NE), 256, DSM_E>>>(
        p_xg, 0, nullptr, CAP / 128,
        p_w1t, 0, nullptr,
        b1, HID,
        nullptr, p_hst, nullptr, nullptr, p_counts, 0,
        DIN / 32, DIN / 32, HID, FLAG_RELU | FLAG_SPLIT);

    // L3 (L2 fused via K-concat): o = relu([h|x_g] @ [w2;wp] + b2+bp) -> tiled fp16
    mma_gemm<1,1,NST_E,KPS_E,0><<<dim3(HID / BN, CAP / BM, NE), 256, DSM_E>>>(
        p_hst, 0, p_xg, CAP / 128,
        p_w2t, 0, p_wpt,
        p_b23, HID,
        nullptr, p_ost, nullptr, nullptr, p_counts, 0,
        (HID + DIN) / 32, HID / 32, HID, FLAG_RELU | FLAG_SPLIT);

    // L4: out[tok] += (o @ w3 + b3) * gate_w   (atomic, 2 adds per element)
    mma_gemm<1,1,NST_E,KPS_E,0><<<dim3(DOUT / BN, CAP / BM, NE), 256, DSM_E>>>(
        p_ost, 0, nullptr, CAP / 128,
        p_w3t, 0, nullptr,
        b3, DOUT,
        out, nullptr, p_wts, p_dests, p_counts, 0,
        HID / 32, HID / 32, DOUT, FLAG_DEST);
}

// round 13
// speedup vs baseline: 4.2639x; 1.0563x over previous
#include <cuda_runtime.h>
#include <cuda_fp16.h>
#include <cstdint>

// ---------------- problem constants ----------------
#define B_TOK 8192
#define DIN   1024
#define HID   2048
#define DOUT  1024
#define NE    8
#define GHID  1024
#define CAP   8192

#define FLAG_RELU  1
#define FLAG_SPLIT 4
#define FLAG_DEST  8

// ---------------- tile geometry (packed 64B rows + XOR swizzle) ----------------
#define BM 128
#define BN 128
#define BK 32
#define BLK_B  8192               // block bytes: 128 rows x 64B (packed)
#define BLK_EL 4096

// element offset of (row r, col c) inside a 128x32 block, swizzled:
// physical 16B-chunk = (c>>3) ^ ((r>>1)&3)
__device__ __forceinline__ uint32_t sw_off(int r, int c) {
    return (uint32_t)(r * 32 + ((((c >> 3) ^ ((r >> 1) & 3)) << 3) | (c & 7)));
}

#define XT_TERM  ((size_t)(B_TOK/128) * (DIN/32) * BLK_EL)
#define GWT_TERM ((size_t)(GHID/128)  * (DIN/32) * BLK_EL)

// ---------------- scratch (static device globals; 128B aligned for bulk) ----------------
__device__ __align__(128) unsigned short g_xt [2*XT_TERM];                      // x tiled [hi|lo] (G1)
__device__ __align__(128) unsigned short g_gwt[2*GWT_TERM];                     // gw1^T tiled [hi|lo]
__device__ __align__(128) unsigned short g_xg [(size_t)NE*(CAP/128)*(DIN/32)*BLK_EL];  // gathered x tiled
__device__ __align__(128) unsigned short g_w1t[(size_t)NE*(HID/128)*(DIN/32)*BLK_EL];
__device__ __align__(128) unsigned short g_wpt[(size_t)NE*(HID/128)*(DIN/32)*BLK_EL];
__device__ __align__(128) unsigned short g_w2t[(size_t)NE*(HID/128)*(HID/32)*BLK_EL];
__device__ __align__(128) unsigned short g_w3t[(size_t)NE*(DOUT/128)*(HID/32)*BLK_EL];
__device__ __align__(128) unsigned short g_hst[(size_t)NE*(CAP/128)*(HID/32)*BLK_EL]; // h tiled
__device__ __align__(128) unsigned short g_ost[(size_t)NE*(CAP/128)*(HID/32)*BLK_EL]; // o tiled
__device__ float g_lpart [(size_t)(GHID/128)*B_TOK*NE];     // partial logits per G1 n-tile
__device__ float g_b23   [(size_t)NE*HID];                  // b2 + bp fused bias
__device__ float g_logits[(size_t)B_TOK*NE];
__device__ int   g_counts[NE];
__device__ int   g_tokens[(size_t)NE*CAP];
__device__ float g_wts   [(size_t)NE*CAP];
__device__ int   g_dests [(size_t)NE*CAP];                  // token index per (expert,row)

// ---------------- PTX helpers (sm_90 baseline features only) ----------------
__device__ __forceinline__ uint32_t smem_u32(const void* p) {
    uint32_t a;
    asm("{ .reg .u64 t; cvta.to.shared.u64 t, %1; cvt.u32.u64 %0, t; }" : "=r"(a) : "l"(p));
    return a;
}
#define BULK_G2S(dst, src, nbytes, mbar) \
    asm volatile("cp.async.bulk.shared::cluster.global.mbarrier::complete_tx::bytes [%0], [%1], %2, [%3];" \
        :: "r"(dst), "l"(src), "r"(nbytes), "r"(mbar) : "memory")
#define MBAR_INIT(addr, cnt) \
    asm volatile("mbarrier.init.shared.b64 [%0], %1;" :: "r"(addr), "r"(cnt) : "memory")
#define MBAR_EXPECT_TX(addr, tx) \
    asm volatile("mbarrier.arrive.expect_tx.shared.b64 _, [%0], %1;" :: "r"(addr), "r"(tx) : "memory")
__device__ __forceinline__ void mbar_wait(uint32_t addr, uint32_t parity) {
    asm volatile("{\n\t.reg .pred P;\n"
        "LW%=:\n\tmbarrier.try_wait.parity.acquire.cta.shared::cta.b64 P, [%0], %1, 0x989680;\n"
        "\t@!P bra LW%=;\n\t}" :: "r"(addr), "r"(parity) : "memory");
}
#define LDSM4(r, addr) \
    asm volatile("ldmatrix.sync.aligned.m8n8.x4.shared.b16 {%0,%1,%2,%3}, [%4];" \
        : "=r"((r)[0]), "=r"((r)[1]), "=r"((r)[2]), "=r"((r)[3]) : "r"(addr))
#define MMA16816(d, a, b0, b1) \
    asm volatile("mma.sync.aligned.m16n8k16.row.col.f32.f16.f16.f32 " \
        "{%0,%1,%2,%3},{%4,%5,%6,%7},{%8,%9},{%0,%1,%2,%3};" \
        : "+f"((d)[0]), "+f"((d)[1]), "+f"((d)[2]), "+f"((d)[3]) \
        : "r"((a)[0]), "r"((a)[1]), "r"((a)[2]), "r"((a)[3]), "r"(b0), "r"(b1))

// ---------------- HMMA GEMM: tile 128x128x32, bulk tiled operands ----------------
// KPS k-blocks per pipeline stage. Segmented K via kcSplit.
// LG=1: gating epilogue — compute partial logits relu(v)·gw2 instead of storing.
template<int ATERMS, int BTERMS, int NSTAGES, int KPS, int LG>
__global__ __launch_bounds__(256, 2) void mma_gemm(
    const unsigned short* __restrict__ Atiled, size_t aTermOff,
    const unsigned short* __restrict__ At2, int aMtPerE,
    const unsigned short* __restrict__ Btiled, size_t bTermOff,
    const unsigned short* __restrict__ Bt2,
    const float* __restrict__ bias, int bStrideE,
    float* __restrict__ outF, unsigned short* __restrict__ outS,
    const float* __restrict__ scales, const int* __restrict__ dests,
    const int* __restrict__ counts, int Mfixed,
    int KPC, int kcSplit, int N, int flags)
{
    constexpr uint32_t STAGE_B = (ATERMS + BTERMS) * KPS * BLK_B;

    const int e  = blockIdx.z;
    const int M  = counts ? counts[e] : Mfixed;
    const int m0 = blockIdx.y * BM;
    if (m0 >= M) return;
    const int n0 = blockIdx.x * BN;

    const int NT   = N >> 7;
    const int kpc2 = KPC - kcSplit;

    extern __shared__ char smem[];
    const uint32_t sbase = smem_u32(smem);
    const uint32_t mbar0 = sbase + NSTAGES * STAGE_B;

    const int tid  = threadIdx.x;
    const int wid  = tid >> 5;
    const int lane = tid & 31;

    const size_t aTile = (size_t)(e * aMtPerE + blockIdx.y);
    const size_t bTile = (size_t)(e * NT + blockIdx.x);

    if (tid == 0) {
        #pragma unroll
        for (int s = 0; s < NSTAGES; s++) MBAR_INIT(mbar0 + s * 8, 1);
    }
    __syncthreads();

    // ---- fragment smem addresses (kb=0, term0): warp tile 64x32, swizzled chunks ----
    const int wm = wid & 1;
    const int wn = wid >> 1;
    uint32_t aAddr[4][2], bAddr[2][2];
    {
        int arow0 = wm * 64 + (lane & 15);
        int alc0  = (lane >> 4);
        int brow0 = wn * 32 + ((lane >> 4) * 8) + (lane & 7);
        int blc0  = ((lane >> 3) & 1);
        #pragma unroll
        for (int ks = 0; ks < 2; ks++) {
            #pragma unroll
            for (int mt = 0; mt < 4; mt++) {
                int r  = arow0 + mt * 16;
                int pc = (ks * 2 + alc0) ^ ((r >> 1) & 3);
                aAddr[mt][ks] = sbase + (uint32_t)(r * 64 + pc * 16);
            }
            #pragma unroll
            for (int nt2 = 0; nt2 < 2; nt2++) {
                int r  = brow0 + nt2 * 16;
                int pc = (ks * 2 + blc0) ^ ((r >> 1) & 3);
                bAddr[nt2][ks] = sbase + ATERMS * KPS * BLK_B + (uint32_t)(r * 64 + pc * 16);
            }
        }
    }

    float acc[4][4][4];
    #pragma unroll
    for (int mt = 0; mt < 4; mt++)
        #pragma unroll
        for (int nt = 0; nt < 4; nt++)
            #pragma unroll
            for (int k = 0; k < 4; k++) acc[mt][nt][k] = 0.0f;

    const int NITS = KPC / KPS;

    auto load_stage = [&](int s, int sit) {
        if (tid == 0) {
            const uint32_t stg = sbase + s * STAGE_B;
            const uint32_t mb = mbar0 + s * 8;
            MBAR_EXPECT_TX(mb, STAGE_B);
            #pragma unroll
            for (int kb = 0; kb < KPS; kb++) {
                int gk = sit * KPS + kb;
                const unsigned short* aSrc;
                const unsigned short* bSrc;
                if (gk < kcSplit) {
                    aSrc = Atiled + (aTile * kcSplit + gk) * BLK_EL;
                    bSrc = Btiled + (bTile * kcSplit + gk) * BLK_EL;
                } else {
                    aSrc = At2 + (aTile * kpc2 + (gk - kcSplit)) * BLK_EL;
                    bSrc = Bt2 + (bTile * kpc2 + (gk - kcSplit)) * BLK_EL;
                }
                BULK_G2S(stg + kb * BLK_B, aSrc, BLK_B, mb);
                if (ATERMS == 2)
                    BULK_G2S(stg + (KPS + kb) * BLK_B,
                             Atiled + aTermOff + (aTile * kcSplit + gk) * BLK_EL, BLK_B, mb);
                BULK_G2S(stg + (ATERMS * KPS + kb) * BLK_B, bSrc, BLK_B, mb);
                if (BTERMS == 2)
                    BULK_G2S(stg + ((ATERMS + 1) * KPS + kb) * BLK_B,
                             Btiled + bTermOff + (bTile * kcSplit + gk) * BLK_EL, BLK_B, mb);
            }
        }
    };

    #pragma unroll
    for (int s = 0; s < NSTAGES - 1; s++)
        if (s < NITS) load_stage(s, s);

    for (int sit = 0; sit < NITS; sit++) {
        mbar_wait(mbar0 + (sit % NSTAGES) * 8, (sit / NSTAGES) & 1);
        __syncthreads();
        if (sit + NSTAGES - 1 < NITS) load_stage((sit + NSTAGES - 1) % NSTAGES, sit + NSTAGES - 1);

        const uint32_t soff = (sit % NSTAGES) * STAGE_B;
        #pragma unroll
        for (int kb = 0; kb < KPS; kb++) {
            const uint32_t ko = soff + kb * BLK_B;
            #pragma unroll
            for (int ks = 0; ks < 2; ks++) {
                uint32_t af0[4][4], bf[2][4];
                #pragma unroll
                for (int mt = 0; mt < 4; mt++) LDSM4(af0[mt], aAddr[mt][ks] + ko);
                #pragma unroll
                for (int nt2 = 0; nt2 < 2; nt2++) LDSM4(bf[nt2], bAddr[nt2][ks] + ko);
                #pragma unroll
                for (int mt = 0; mt < 4; mt++)
                    #pragma unroll
                    for (int nt = 0; nt < 4; nt++)
                        MMA16816(acc[mt][nt], af0[mt], bf[nt >> 1][(nt & 1) * 2], bf[nt >> 1][(nt & 1) * 2 + 1]);
                if (ATERMS == 2) {
                    uint32_t af1[4][4];
                    #pragma unroll
                    for (int mt = 0; mt < 4; mt++) LDSM4(af1[mt], aAddr[mt][ks] + ko + KPS * BLK_B);
                    #pragma unroll
                    for (int mt = 0; mt < 4; mt++)
                        #pragma unroll
                        for (int nt = 0; nt < 4; nt++)
                            MMA16816(acc[mt][nt], af1[mt], bf[nt >> 1][(nt & 1) * 2], bf[nt >> 1][(nt & 1) * 2 + 1]);
                }
                if (BTERMS == 2) {
                    uint32_t bfl[2][4];
                    #pragma unroll
                    for (int nt2 = 0; nt2 < 2; nt2++) LDSM4(bfl[nt2], bAddr[nt2][ks] + ko + KPS * BLK_B);
                    #pragma unroll
                    for (int mt = 0; mt < 4; mt++)
                        #pragma unroll
                        for (int nt = 0; nt < 4; nt++)
                            MMA16816(acc[mt][nt], af0[mt], bfl[nt >> 1][(nt & 1) * 2], bfl[nt >> 1][(nt & 1) * 2 + 1]);
                }
            }
        }
    }

    // ---- epilogue ----
    const float* biasE = bias + (size_t)e * bStrideE;
    const int cq = (lane & 3) * 2;
    const int r0 = lane >> 2;
    float b2v[4][2];
    #pragma unroll
    for (int nt = 0; nt < 4; nt++) {
        int n = n0 + wn * 32 + nt * 8 + cq;
        b2v[nt][0] = biasE[n];
        b2v[nt][1] = biasE[n + 1];
    }

    if (LG) {
        // gating epilogue: partial logits = relu(v) . gw2  (scales == gw2 [GHID][NE])
        float* sp = (float*)(smem + NSTAGES * STAGE_B + 64);   // [4 wn][128 rows][NE]
        const float* gw2p = scales;
        #pragma unroll
        for (int mt = 0; mt < 4; mt++) {
            #pragma unroll
            for (int h = 0; h < 2; h++) {
                int row = wm * 64 + mt * 16 + r0 + h * 8;   // local row 0..127
                float p[NE];
                #pragma unroll
                for (int e2 = 0; e2 < NE; e2++) p[e2] = 0.0f;
                #pragma unroll
                for (int nt = 0; nt < 4; nt++) {
                    int n = n0 + wn * 32 + nt * 8 + cq;
                    float v0 = acc[mt][nt][h * 2]     + b2v[nt][0];
                    float v1 = acc[mt][nt][h * 2 + 1] + b2v[nt][1];
                    v0 = fmaxf(v0, 0.0f); v1 = fmaxf(v1, 0.0f);
                    const float* ga = gw2p + (size_t)n * NE;
                    #pragma unroll
                    for (int e2 = 0; e2 < NE; e2++)
                        p[e2] += v0 * ga[e2] + v1 * ga[NE + e2];
                }
                #pragma unroll
                for (int e2 = 0; e2 < NE; e2++) {
                    p[e2] += __shfl_xor_sync(0xFFFFFFFFu, p[e2], 1);
                    p[e2] += __shfl_xor_sync(0xFFFFFFFFu, p[e2], 2);
                }
                if ((lane & 3) == 0) {
                    #pragma unroll
                    for (int e2 = 0; e2 < NE; e2++)
                        sp[((wn * 128) + row) * NE + e2] = p[e2];
                }
            }
        }
        __syncthreads();
        for (int idx = tid; idx < 128 * NE; idx += 256) {
            int row = idx >> 3, e2 = idx & 7;
            float s = sp[row * NE + e2] + sp[(128 + row) * NE + e2]
                    + sp[(256 + row) * NE + e2] + sp[(384 + row) * NE + e2];
            outF[(size_t)blockIdx.x * B_TOK * NE + (size_t)(m0 + row) * NE + e2] = s;
        }
        return;
    }

    #pragma unroll
    for (int mt = 0; mt < 4; mt++) {
        #pragma unroll
        for (int h = 0; h < 2; h++) {
            int row = m0 + wm * 64 + mt * 16 + r0 + h * 8;
            if (row >= M) continue;
            size_t erow = (size_t)e * CAP + row;
            float sc = 1.0f;
            int   tok = 0;
            if (flags & FLAG_DEST) {
                sc  = scales[erow];
                tok = dests[erow];
            }
            #pragma unroll
            for (int nt = 0; nt < 4; nt++) {
                int n = n0 + wn * 32 + nt * 8 + cq;
                float v0 = acc[mt][nt][h * 2]     + b2v[nt][0];
                float v1 = acc[mt][nt][h * 2 + 1] + b2v[nt][1];
                if (flags & FLAG_RELU) { v0 = fmaxf(v0, 0.0f); v1 = fmaxf(v1, 0.0f); }
                if (flags & FLAG_SPLIT) {
                    size_t blk = ((erow >> 7) * (size_t)(N >> 5) + (size_t)(n >> 5)) * BLK_EL;
                    *(__half2*)((__half*)outS + blk + sw_off((int)(erow & 127), n & 31)) =
                        __halves2half2(__float2half_rn(v0), __float2half_rn(v1));
                } else if (flags & FLAG_DEST) {
                    atomicAdd(outF + (size_t)tok * N + n,     v0 * sc);
                    atomicAdd(outF + (size_t)tok * N + n + 1, v1 * sc);
                } else {
                    float2 o2; o2.x = v0; o2.y = v1;
                    *(float2*)(outF + (size_t)row * N + n) = o2;
                }
            }
        }
    }
}

// ---------------- fused prep: all weight conversions in ONE kernel ----------------
// 32x32 transpose tiles, flat grid over 5 jobs: w1, wp, w2, w3, gw1(split).
#define TW1  ((HID/32)*(DIN/32)*NE)     // 16384
#define TWP  TW1                        // 16384
#define TW2  ((HID/32)*(HID/32)*NE)     // 32768
#define TW3  ((DOUT/32)*(HID/32)*NE)    // 16384
#define TGW  ((GHID/32)*(DIN/32))       // 1024
#define TWTOT (TW1+TWP+TW2+TW3+TGW)

__device__ __forceinline__ void conv_tile(const float* W, unsigned short* Wt,
                                          int K, int N, size_t termOff,
                                          int e, int n0, int k0,
                                          float t[32][33])
{
    const float* We = W + (size_t)e * K * N;
    #pragma unroll
    for (int j = 0; j < 4; j++) {
        int k = k0 + threadIdx.y + j * 8;
        t[threadIdx.y + j * 8][threadIdx.x] = We[(size_t)k * N + n0 + threadIdx.x];
    }
    __syncthreads();
    const size_t blkBase = (((size_t)e * (N >> 7) + (size_t)(n0 >> 7)) * (K >> 5) + (size_t)(k0 >> 5)) * BLK_EL;
    #pragma unroll
    for (int j = 0; j < 4; j++) {
        int n = n0 + threadIdx.y + j * 8;
        int k = k0 + threadIdx.x;
        float v = t[threadIdx.x][threadIdx.y + j * 8];
        __half hi = __float2half_rn(v);
        size_t off = blkBase + sw_off(n & 127, k & 31);
        ((__half*)Wt)[off] = hi;
        if (termOff) ((__half*)Wt)[termOff + off] = __float2half_rn(v - __half2float(hi));
    }
}

__global__ void prep_w(const float* __restrict__ w1, const float* __restrict__ wp,
                       const float* __restrict__ w2, const float* __restrict__ w3,
                       const float* __restrict__ gw1,
                       unsigned short* __restrict__ w1t, unsigned short* __restrict__ wpt,
                       unsigned short* __restrict__ w2t, unsigned short* __restrict__ w3t,
                       unsigned short* __restrict__ gwt)
{
    __shared__ float t[32][33];
    int b = blockIdx.x;
    if (b < TW1) {
        int e = b / ((HID/32)*(DIN/32)); int r = b % ((HID/32)*(DIN/32));
        conv_tile(w1, w1t, DIN, HID, 0, e, (r % (HID/32)) * 32, (r / (HID/32)) * 32, t);
    } else if ((b -= TW1) < TWP) {
        int e = b / ((HID/32)*(DIN/32)); int r = b % ((HID/32)*(DIN/32));
        conv_tile(wp, wpt, DIN, HID, 0, e, (r % (HID/32)) * 32, (r / (HID/32)) * 32, t);
    } else if ((b -= TWP) < TW2) {
        int e = b / ((HID/32)*(HID/32)); int r = b % ((HID/32)*(HID/32));
        conv_tile(w2, w2t, HID, HID, 0, e, (r % (HID/32)) * 32, (r / (HID/32)) * 32, t);
    } else if ((b -= TW2) < TW3) {
        int e = b / ((DOUT/32)*(HID/32)); int r = b % ((DOUT/32)*(HID/32));
        conv_tile(w3, w3t, HID, DOUT, 0, e, (r % (DOUT/32)) * 32, (r / (DOUT/32)) * 32, t);
    } else {
        b -= TW3;
        conv_tile(gw1, gwt, DIN, GHID, GWT_TERM, 0, (b % (GHID/32)) * 32, (b / (GHID/32)) * 32, t);
    }
}

// ---------------- fused prep: zero_out + convert_x + bias_fuse ----------------
#define ZN4   ((size_t)B_TOK * DOUT / 4)
#define XTOT  ((size_t)B_TOK * DIN)
__global__ __launch_bounds__(256) void prep_small(float4* __restrict__ out,
                                                  const float* __restrict__ x,
                                                  unsigned short* __restrict__ xt,
                                                  const float* __restrict__ b2,
                                                  const float* __restrict__ bp,
                                                  float* __restrict__ b23)
{
    size_t idx = (size_t)blockIdx.x * blockDim.x + threadIdx.x;
    if (idx < ZN4) {
        out[idx] = make_float4(0.f, 0.f, 0.f, 0.f);
    }
    if (idx < XTOT) {
        size_t t = idx / DIN;
        int    k = (int)(idx % DIN);
        float v = x[idx];
        __half hi = __float2half_rn(v);
        __half lo = __float2half_rn(v - __half2float(hi));
        size_t blk = ((t >> 7) * (size_t)(DIN >> 5) + (size_t)(k >> 5)) * BLK_EL
                   + sw_off((int)(t & 127), k & 31);
        ((__half*)xt)[blk]           = hi;
        ((__half*)xt)[XT_TERM + blk] = lo;
    }
    if (idx < NE * HID) b23[idx] = b2[idx] + bp[idx];
}

// ---------------- gather routed x: vectorized, one 16B chunk per thread ----------------
__global__ __launch_bounds__(256) void tile_gather_x(const float* __restrict__ x,
                                                     unsigned short* __restrict__ xg)
{
    const int e  = blockIdx.y;
    const int mt = blockIdx.x;
    const int M  = g_counts[e];
    const int m0 = mt * 128;
    if (m0 >= M) return;
    const int nrows = min(128, M - m0);
    const size_t base = ((size_t)(e * (CAP / 128) + mt) * (DIN / 32)) * BLK_EL;
    const int nchunks = nrows * (DIN / 8);      // 16B chunks
    for (int idx = threadIdx.x; idx < nchunks; idx += 256) {
        int row = idx >> 7;                     // DIN/8 = 128 chunks per row
        int c8  = idx & 127;
        int k   = c8 * 8;
        int tok = g_tokens[e * CAP + m0 + row];
        const float4* xp = (const float4*)(x + (size_t)tok * DIN + k);
        float4 a = xp[0], b = xp[1];
        __half h[8];
        h[0] = __float2half_rn(a.x); h[1] = __float2half_rn(a.y);
        h[2] = __float2half_rn(a.z); h[3] = __float2half_rn(a.w);
        h[4] = __float2half_rn(b.x); h[5] = __float2half_rn(b.y);
        h[6] = __float2half_rn(b.z); h[7] = __float2half_rn(b.w);
        // destination chunk: swizzled, 16B aligned
        size_t off = base + (size_t)(k >> 5) * BLK_EL + sw_off(row, k & 31);
        *(uint4*)((__half*)xg + off) = *(uint4*)h;
    }
}

// logits[t][e] = sum over 8 n-tiles of lpart + gb2[e]
__global__ __launch_bounds__(256) void logits_reduce(const float* __restrict__ lpart,
                                                     const float* __restrict__ gb2,
                                                     float* __restrict__ logits)
{
    int idx = blockIdx.x * blockDim.x + threadIdx.x;
    if (idx >= B_TOK * NE) return;
    float s = gb2[idx & 7];
    #pragma unroll
    for (int bx = 0; bx < GHID / 128; bx++)
        s += lpart[(size_t)bx * B_TOK * NE + idx];
    logits[idx] = s;
}

// ---------------- routing ----------------
__global__ void init_kernel() {
    if (threadIdx.x < NE) g_counts[threadIdx.x] = 0;
}

__global__ __launch_bounds__(256) void route_kernel() {
    int t = blockIdx.x * blockDim.x + threadIdx.x;
    if (t >= B_TOK) return;
    float v[NE];
    #pragma unroll
    for (int e = 0; e < NE; e++) v[e] = g_logits[(size_t)t * NE + e];
    int i0 = 0;
    #pragma unroll
    for (int e = 1; e < NE; e++) if (v[e] > v[i0]) i0 = e;
    int i1 = (i0 == 0) ? 1 : 0;
    #pragma unroll
    for (int e = 0; e < NE; e++) if (e != i0 && v[e] > v[i1]) i1 = e;
    float b = __expf(v[i1] - v[i0]);
    float s = 1.0f + b;
    float w0 = 1.0f / s;
    float w1 = b / s;

    int p0 = atomicAdd(&g_counts[i0], 1);
    g_tokens[i0 * CAP + p0] = t;
    g_wts[i0 * CAP + p0]    = w0;
    g_dests[i0 * CAP + p0]  = t;

    int p1 = atomicAdd(&g_counts[i1], 1);
    g_tokens[i1 * CAP + p1] = t;
    g_wts[i1 * CAP + p1]    = w1;
    g_dests[i1 * CAP + p1]  = t;
}

// ---------------- host ----------------
#define NST_E 3
#define KPS_E 2
#define DSM_E (NST_E * 2 * KPS_E * BLK_B + 64)              // 98368; 2 CTAs/SM
#define DSM_G (2 * 4 * BLK_B + 64 + 4 * 128 * NE * 4)       // 81984; 2 CTAs/SM

extern "C" void kernel_launch(void* const* d_in, const int* in_sizes, int n_in,
                              void* d_out, int out_size) {
    const float* x   = (const float*)d_in[0];
    const float* w1  = (const float*)d_in[1];
    const float* b1  = (const float*)d_in[2];
    const float* w2  = (const float*)d_in[3];
    const float* b2  = (const float*)d_in[4];
    const float* w3  = (const float*)d_in[5];
    const float* b3  = (const float*)d_in[6];
    const float* wp  = (const float*)d_in[7];
    const float* bp  = (const float*)d_in[8];
    const float* gw1 = (const float*)d_in[9];
    const float* gb1 = (const float*)d_in[10];
    const float* gw2 = (const float*)d_in[11];
    const float* gb2 = (const float*)d_in[12];
    float* out = (float*)d_out;

    unsigned short *p_xt, *p_gwt, *p_xg, *p_w1t, *p_wpt, *p_w2t, *p_w3t, *p_hst, *p_ost;
    float *p_lpart, *p_b23, *p_logits, *p_wts;
    int *p_counts, *p_tokens, *p_dests;
    cudaGetSymbolAddress((void**)&p_xt,     g_xt);
    cudaGetSymbolAddress((void**)&p_gwt,    g_gwt);
    cudaGetSymbolAddress((void**)&p_xg,     g_xg);
    cudaGetSymbolAddress((void**)&p_w1t,    g_w1t);
    cudaGetSymbolAddress((void**)&p_wpt,    g_wpt);
    cudaGetSymbolAddress((void**)&p_w2t,    g_w2t);
    cudaGetSymbolAddress((void**)&p_w3t,    g_w3t);
    cudaGetSymbolAddress((void**)&p_hst,    g_hst);
    cudaGetSymbolAddress((void**)&p_ost,    g_ost);
    cudaGetSymbolAddress((void**)&p_lpart,  g_lpart);
    cudaGetSymbolAddress((void**)&p_b23,    g_b23);
    cudaGetSymbolAddress((void**)&p_logits, g_logits);
    cudaGetSymbolAddress((void**)&p_wts,    g_wts);
    cudaGetSymbolAddress((void**)&p_counts, g_counts);
    cudaGetSymbolAddress((void**)&p_tokens, g_tokens);
    cudaGetSymbolAddress((void**)&p_dests,  g_dests);

    cudaFuncSetAttribute((const void*)mma_gemm<1,1,NST_E,KPS_E,0>,
                         cudaFuncAttributeMaxDynamicSharedMemorySize, DSM_E);
    cudaFuncSetAttribute((const void*)mma_gemm<2,2,2,1,1>,
                         cudaFuncAttributeMaxDynamicSharedMemorySize, DSM_G);

    // prep: zero out + x split/tile + bias fuse (1 launch), all weight conversions (1 launch)
    {
        size_t n = XTOT;   // dominant range
        prep_small<<<(unsigned)((n + 255) / 256), 256>>>((float4*)out, x, p_xt, b2, bp, p_b23);
    }
    prep_w<<<TWTOT, dim3(32, 8)>>>(w1, wp, w2, w3, gw1, p_w1t, p_wpt, p_w2t, p_w3t, p_gwt);

    // G1: 3-term gating GEMM with fused partial-logit epilogue (relu(x@gw1+gb1)·gw2)
    mma_gemm<2,2,2,1,1><<<dim3(GHID / BN, B_TOK / BM, 1), 256, DSM_G>>>(
        p_xt, XT_TERM, nullptr, B_TOK / 128,
        p_gwt, GWT_TERM, nullptr,
        gb1, 0,
        p_lpart, nullptr, gw2, nullptr, nullptr, B_TOK,
        DIN / 32, DIN / 32, GHID, FLAG_RELU);

    // logits = sum(lpart) + gb2 ; routing
    logits_reduce<<<(B_TOK * NE + 255) / 256, 256>>>(p_lpart, gb2, p_logits);
    init_kernel<<<1, 32>>>();
    route_kernel<<<B_TOK / 256, 256>>>();

    // gather routed x into tiled layout (vectorized 16B chunks)
    tile_gather_x<<<dim3(CAP / 128, NE), 256>>>(x, p_xg);

    // L1: h = relu(x_g @ w1 + b1) -> tiled fp16
    mma_gemm<1,1,NST_E,KPS_E,0><<<dim3(HID / BN, CAP / BM, NE), 256, DSM_E>>>(
        p_xg, 0, nullptr, CAP / 128,
        p_w1t, 0, nullptr,
        b1, HID,
        nullptr, p_hst, nullptr, nullptr, p_counts, 0,
        DIN / 32, DIN / 32, HID, FLAG_RELU | FLAG_SPLIT);

    // L3 (L2 fused via K-concat): o = relu([h|x_g] @ [w2;wp] + b2+bp) -> tiled fp16
    mma_gemm<1,1,NST_E,KPS_E,0><<<dim3(HID / BN, CAP / BM, NE), 256, DSM_E>>>(
        p_hst, 0, p_xg, CAP / 128,
        p_w2t, 0, p_wpt,
        p_b23, HID,
        nullptr, p_ost, nullptr, nullptr, p_counts, 0,
        (HID + DIN) / 32, HID / 32, HID, FLAG_RELU | FLAG_SPLIT);

    // L4: out[tok] += (o @ w3 + b3) * gate_w   (atomic, 2 adds per element)
    mma_gemm<1,1,NST_E,KPS_E,0><<<dim3(DOUT / BN, CAP / BM, NE), 256, DSM_E>>>(
        p_ost, 0, nullptr, CAP / 128,
        p_w3t, 0, nullptr,
        b3, DOUT,
        out, nullptr, p_wts, p_dests, p_counts, 0,
        HID / 32, HID / 32, DOUT, FLAG_DEST);
}